// round 9
// baseline (speedup 1.0000x reference)
#include <cuda_runtime.h>
#include <cuda_bf16.h>
#include <math.h>
#include <stdint.h>

// ---------------- problem constants ----------------
#define T_TOK   2048
#define HID     2048
#define NH      16
#define D_NOPE  128
#define D_ROPE  64
#define D_QK    192
#define D_V     128
#define Q_LORA  1536
#define KV_LORA 512
#define QKV_A_N 2112
#define QKVP    2176      // QKV_A_N padded to multiple of 128
#define SCALING 0.07216878364870322f   // 192^-0.5

// ---------------- scratch ----------------
__device__ __align__(128) float g_qkv_a [T_TOK * QKVP];
__device__ __align__(128) float g_qbuf  [T_TOK * NH * D_QK];
__device__ __align__(128) float g_kvbuf [T_TOK * NH * 256];
__device__ __align__(128) float g_kpe   [T_TOK * D_ROPE];
// bf16 hi/lo planes
__device__ __align__(128) __nv_bfloat16 g_hid_hi [T_TOK * HID];
__device__ __align__(128) __nv_bfloat16 g_hid_lo [T_TOK * HID];
__device__ __align__(128) __nv_bfloat16 g_qn_hi  [T_TOK * Q_LORA];
__device__ __align__(128) __nv_bfloat16 g_qn_lo  [T_TOK * Q_LORA];
__device__ __align__(128) __nv_bfloat16 g_kvn_hi [T_TOK * KV_LORA];
__device__ __align__(128) __nv_bfloat16 g_kvn_lo [T_TOK * KV_LORA];
__device__ __align__(128) __nv_bfloat16 g_attn_hi[T_TOK * NH * D_V];
__device__ __align__(128) __nv_bfloat16 g_attn_lo[T_TOK * NH * D_V];
__device__ __align__(128) __nv_bfloat16 g_wa_hi  [QKVP * HID];    // padded, rows>=2112 zero
__device__ __align__(128) __nv_bfloat16 g_wa_lo  [QKVP * HID];
__device__ __align__(128) __nv_bfloat16 g_wqb_hi [NH * D_QK * Q_LORA];
__device__ __align__(128) __nv_bfloat16 g_wqb_lo [NH * D_QK * Q_LORA];
__device__ __align__(128) __nv_bfloat16 g_wkvb_hi[NH * 256 * KV_LORA];
__device__ __align__(128) __nv_bfloat16 g_wkvb_lo[NH * 256 * KV_LORA];
__device__ __align__(128) __nv_bfloat16 g_wo_hi  [HID * NH * D_V];
__device__ __align__(128) __nv_bfloat16 g_wo_lo  [HID * NH * D_V];
// attention operand planes
__device__ __align__(128) __nv_bfloat16 g_q_hi  [T_TOK * NH * D_QK];
__device__ __align__(128) __nv_bfloat16 g_q_lo  [T_TOK * NH * D_QK];
__device__ __align__(128) __nv_bfloat16 g_k_hi  [T_TOK * NH * D_QK];
__device__ __align__(128) __nv_bfloat16 g_k_lo  [T_TOK * NH * D_QK];
__device__ __align__(128) __nv_bfloat16 g_vt_hi [NH * D_V * T_TOK];
__device__ __align__(128) __nv_bfloat16 g_vt_lo [NH * D_V * T_TOK];

// ---------------- helpers ----------------
__device__ __forceinline__ void cp16(void* s, const void* g) {
    unsigned int sa = (unsigned int)__cvta_generic_to_shared(s);
    asm volatile("cp.async.cg.shared.global [%0], [%1], 16;" :: "r"(sa), "l"(g));
}
#define CP_COMMIT() asm volatile("cp.async.commit_group;")
#define CP_WAIT1()  asm volatile("cp.async.wait_group 1;")
#define CP_WAIT0()  asm volatile("cp.async.wait_group 0;")

__device__ __forceinline__ uint32_t smem_u32(const void* p) {
    return (uint32_t)__cvta_generic_to_shared(p);
}
#define LDSM4(r0, r1, r2, r3, a) \
    asm volatile("ldmatrix.sync.aligned.m8n8.x4.shared.b16 {%0,%1,%2,%3}, [%4];" \
        : "=r"(r0), "=r"(r1), "=r"(r2), "=r"(r3) : "r"(a))

__device__ __forceinline__ void mma_bf16(float* c,
    uint32_t a0, uint32_t a1, uint32_t a2, uint32_t a3, uint32_t b0, uint32_t b1)
{
    asm volatile(
        "mma.sync.aligned.m16n8k16.row.col.f32.bf16.bf16.f32 "
        "{%0,%1,%2,%3},{%4,%5,%6,%7},{%8,%9},{%0,%1,%2,%3};"
        : "+f"(c[0]), "+f"(c[1]), "+f"(c[2]), "+f"(c[3])
        : "r"(a0), "r"(a1), "r"(a2), "r"(a3), "r"(b0), "r"(b1));
}

__device__ __forceinline__ void split_hl(float v, __nv_bfloat16& h, __nv_bfloat16& l) {
    h = __float2bfloat16(v);
    l = __float2bfloat16(v - __bfloat162float(h));
}
__device__ __forceinline__ uint32_t pack2(__nv_bfloat16 a, __nv_bfloat16 b) {
    return (uint32_t)__bfloat16_as_ushort(a) | ((uint32_t)__bfloat16_as_ushort(b) << 16);
}

// ---------------- converters ----------------
__global__ __launch_bounds__(256) void convert_hl_kernel(
    const float2* __restrict__ src, uint32_t* __restrict__ hi,
    uint32_t* __restrict__ lo, int n2)
{
    int i = blockIdx.x * 256 + threadIdx.x;
    const int stride = gridDim.x * 256;
    for (; i < n2; i += stride) {
        const float2 v = src[i];
        __nv_bfloat16 h0, l0, h1, l1;
        split_hl(v.x, h0, l0);
        split_hl(v.y, h1, l1);
        hi[i] = pack2(h0, h1);
        lo[i] = pack2(l0, l1);
    }
}

// in fp32 [R][C] -> out hi/lo bf16 [Cpad][R]; cols >= C read as 0
__global__ __launch_bounds__(256) void transpose_cvt_kernel(
    const float* __restrict__ in, __nv_bfloat16* __restrict__ hi,
    __nv_bfloat16* __restrict__ lo, int R, int C)
{
    __shared__ float t[32][33];
    const int c0 = blockIdx.x * 32, r0 = blockIdx.y * 32;
    const int x = threadIdx.x, y = threadIdx.y;
#pragma unroll
    for (int j = 0; j < 32; j += 8)
        t[y + j][x] = (c0 + x < C) ? in[(size_t)(r0 + y + j) * C + c0 + x] : 0.f;
    __syncthreads();
#pragma unroll
    for (int j = 0; j < 32; j += 8) {
        const float v = t[x][y + j];
        __nv_bfloat16 h, l;
        split_hl(v, h, l);
        const size_t o = (size_t)(c0 + y + j) * R + r0 + x;
        hi[o] = h;
        lo[o] = l;
    }
}

// build K planes: k[t][h*192+d] = d<128 ? kv[t][h*256+d] : kpe[t][d-128]
__global__ __launch_bounds__(256) void build_k_kernel(
    const float* __restrict__ kvbuf, const float* __restrict__ kpe,
    __nv_bfloat16* __restrict__ kh, __nv_bfloat16* __restrict__ kl)
{
    const int t = blockIdx.x;
    for (int i = threadIdx.x; i < NH * D_QK; i += 256) {
        const int h = i / D_QK, d = i - h * D_QK;
        const float v = (d < 128)
            ? kvbuf[(size_t)t * (NH * 256) + h * 256 + d]
            : kpe[(size_t)t * D_ROPE + (d - 128)];
        __nv_bfloat16 hh, ll;
        split_hl(v, hh, ll);
        kh[(size_t)t * (NH * D_QK) + i] = hh;
        kl[(size_t)t * (NH * D_QK) + i] = ll;
    }
}

// build VT planes: vt[h][d][t] = kvbuf[t][h*256+128+d]
__global__ __launch_bounds__(256) void build_vt_kernel(
    const float* __restrict__ kvbuf,
    __nv_bfloat16* __restrict__ vth, __nv_bfloat16* __restrict__ vtl)
{
    __shared__ float tile[32][33];
    const int h = blockIdx.z;
    const int d0 = blockIdx.y * 32;
    const int t0 = blockIdx.x * 32;
    const int x = threadIdx.x, y = threadIdx.y;
#pragma unroll
    for (int j = 0; j < 32; j += 8)
        tile[y + j][x] = kvbuf[(size_t)(t0 + y + j) * (NH * 256) + h * 256 + 128 + d0 + x];
    __syncthreads();
#pragma unroll
    for (int j = 0; j < 32; j += 8) {
        const float v = tile[x][y + j];
        __nv_bfloat16 hh, ll;
        split_hl(v, hh, ll);
        const size_t o = ((size_t)h * D_V + d0 + y + j) * T_TOK + t0 + x;
        vth[o] = hh;
        vtl[o] = ll;
    }
}

// ---------------- bf16 hi/lo split GEMM (wide tile: 256x128, warp 64x64) ----------------
#define PITCH_B 80
#define AHI_OFF 0
#define ALO_OFF 20480
#define BHI_OFF 40960
#define BLO_OFF 51200
#define W_STAGE 61440
#define W_SMEM  (2 * W_STAGE)

__global__ __launch_bounds__(256, 1) void gemm_hl(
    const __nv_bfloat16* __restrict__ Ah, const __nv_bfloat16* __restrict__ Al,
    const __nv_bfloat16* __restrict__ Bh, const __nv_bfloat16* __restrict__ Bl,
    float* __restrict__ C, int M, int N, int K)
{
    extern __shared__ __align__(128) char smx[];
    const uint32_t sbase = smem_u32(smx);
    const int tid  = threadIdx.x;
    const int warp = tid >> 5;
    const int lane = tid & 31;
    const int wm   = warp >> 1;          // 0..3 -> rows wm*64
    const int wn   = warp & 1;           // 0..1 -> cols wn*64
    const int row0 = blockIdx.y * 256;
    const int col0 = blockIdx.x * 128;

    float c[32][4];
#pragma unroll
    for (int i = 0; i < 32; i++)
#pragma unroll
        for (int j = 0; j < 4; j++) c[i][j] = 0.f;

    // fill: A 1024 cp16/plane, B 512 cp16/plane => 12 per thread
    auto fill = [&](int stage, int k0) {
        char* st = smx + stage * W_STAGE;
#pragma unroll
        for (int rep = 0; rep < 4; rep++) {
            const int cch = tid + rep * 256;       // 0..1023
            const int r = cch >> 2, q = cch & 3;
            const size_t src = (size_t)(row0 + r) * K + k0 + q * 8;
            cp16(st + AHI_OFF + r * PITCH_B + q * 16, Ah + src);
            cp16(st + ALO_OFF + r * PITCH_B + q * 16, Al + src);
        }
#pragma unroll
        for (int rep = 0; rep < 2; rep++) {
            const int cch = tid + rep * 256;       // 0..511
            const int r = cch >> 2, q = cch & 3;   // r 0..127
            const size_t src = (size_t)(col0 + r) * K + k0 + q * 8;
            cp16(st + BHI_OFF + r * PITCH_B + q * 16, Bh + src);
            cp16(st + BLO_OFF + r * PITCH_B + q * 16, Bl + src);
        }
    };

    fill(0, 0);
    CP_COMMIT();

    const int nch = K >> 5;
    const int rowL = (lane & 7) + (lane & 8);
    const int kbL  = (lane >> 4) * 16;

    for (int ch = 0; ch < nch; ch++) {
        const int buf = ch & 1;
        if (ch + 1 < nch) {
            fill(buf ^ 1, (ch + 1) * 32);
            CP_COMMIT();
            CP_WAIT1();
        } else {
            CP_WAIT0();
        }
        __syncthreads();

        const uint32_t sAh = sbase + buf * W_STAGE + AHI_OFF;
        const uint32_t sAl = sbase + buf * W_STAGE + ALO_OFF;
        const uint32_t sBh = sbase + buf * W_STAGE + BHI_OFF;
        const uint32_t sBl = sbase + buf * W_STAGE + BLO_OFF;

#pragma unroll
        for (int kk = 0; kk < 2; kk++) {
            const int kb = kk * 32 + kbL;
            uint32_t bh[4][4], bl[4][4];
#pragma unroll
            for (int j = 0; j < 4; j++) {
                const int rB = (wn * 64 + j * 16 + rowL) * PITCH_B + kb;
                LDSM4(bh[j][0], bh[j][1], bh[j][2], bh[j][3], sBh + rB);
                LDSM4(bl[j][0], bl[j][1], bl[j][2], bl[j][3], sBl + rB);
            }
#pragma unroll
            for (int i = 0; i < 4; i++) {
                const int rA = (wm * 64 + i * 16 + rowL) * PITCH_B + kb;
                uint32_t ah0, ah1, ah2, ah3, al0, al1, al2, al3;
                LDSM4(ah0, ah1, ah2, ah3, sAh + rA);
                LDSM4(al0, al1, al2, al3, sAl + rA);
#pragma unroll
                for (int f = 0; f < 8; f++) {
                    const int j = f >> 1, h = f & 1;
                    float* acc = c[i * 8 + f];
                    mma_bf16(acc, ah0, ah1, ah2, ah3, bh[j][h], bh[j][h + 2]);
                    mma_bf16(acc, ah0, ah1, ah2, ah3, bl[j][h], bl[j][h + 2]);
                    mma_bf16(acc, al0, al1, al2, al3, bh[j][h], bh[j][h + 2]);
                }
            }
        }
        __syncthreads();
    }

    const int qr = lane >> 2, qc = 2 * (lane & 3);
#pragma unroll
    for (int i = 0; i < 4; i++) {
#pragma unroll
        for (int f = 0; f < 8; f++) {
            const int r   = row0 + wm * 64 + i * 16 + qr;
            const int col = col0 + wn * 64 + f * 8 + qc;
            *(float2*)(C + (size_t)r * N + col)       = make_float2(c[i * 8 + f][0], c[i * 8 + f][1]);
            *(float2*)(C + (size_t)(r + 8) * N + col) = make_float2(c[i * 8 + f][2], c[i * 8 + f][3]);
        }
    }
}

// ---------------- RMSNorm -> bf16 hi/lo ----------------
__global__ __launch_bounds__(256) void rmsnorm_kernel(
    const float* __restrict__ in, int ld, int off, int width,
    const float* __restrict__ gamma,
    __nv_bfloat16* __restrict__ ohi, __nv_bfloat16* __restrict__ olo)
{
    const int row = blockIdx.x;
    const float* x = in + (size_t)row * ld + off;
    float ss = 0.f;
    for (int i = threadIdx.x; i < width; i += 256) {
        float v = x[i];
        ss += v * v;
    }
#pragma unroll
    for (int o = 16; o; o >>= 1) ss += __shfl_xor_sync(0xffffffffu, ss, o);
    __shared__ float warp_s[8];
    __shared__ float s_inv;
    if ((threadIdx.x & 31) == 0) warp_s[threadIdx.x >> 5] = ss;
    __syncthreads();
    if (threadIdx.x == 0) {
        float t = 0.f;
#pragma unroll
        for (int i = 0; i < 8; i++) t += warp_s[i];
        s_inv = rsqrtf(t / (float)width + 1e-6f);
    }
    __syncthreads();
    const float inv = s_inv;
    for (int i = threadIdx.x; i < width; i += 256) {
        const float v = x[i] * inv * gamma[i];
        __nv_bfloat16 h, l;
        split_hl(v, h, l);
        ohi[(size_t)row * width + i] = h;
        olo[(size_t)row * width + i] = l;
    }
}

// ---------------- RoPE (fp32) ----------------
__global__ __launch_bounds__(256) void rope_kernel(
    float* __restrict__ q, const float* __restrict__ qkv_a,
    float* __restrict__ kpe, const int* __restrict__ positions)
{
    const int t = blockIdx.x;
    const float pos = (float)positions[t];
    for (int i = threadIdx.x; i < NH * 32 + 32; i += 256) {
        if (i < NH * 32) {
            const int h = i >> 5, p = i & 31;
            const float inv = powf(10000.0f, -(float)p / 32.0f);
            float s, c;
            sincosf(pos * inv, &s, &c);
            float* base = q + (size_t)t * (NH * D_QK) + h * D_QK + D_NOPE;
            const float x1 = base[2 * p], x2 = base[2 * p + 1];
            base[2 * p]     = x1 * c - x2 * s;
            base[2 * p + 1] = x1 * s + x2 * c;
        } else {
            const int p = i - NH * 32;
            const float inv = powf(10000.0f, -(float)p / 32.0f);
            float s, c;
            sincosf(pos * inv, &s, &c);
            const float* src = qkv_a + (size_t)t * QKVP + (Q_LORA + KV_LORA);
            const float x1 = src[2 * p], x2 = src[2 * p + 1];
            kpe[(size_t)t * D_ROPE + 2 * p]     = x1 * c - x2 * s;
            kpe[(size_t)t * D_ROPE + 2 * p + 1] = x1 * s + x2 * c;
        }
    }
}

// ---------------- bf16 hi/lo causal flash attention ----------------
#define SQH 0
#define SQL 25600
#define SKH 51200
#define SKL 76800
#define SVH 102400
#define SVL 120832
#define SPH 139264
#define SPL 148480
#define SSTAT 157696
#define ATT_SMEM (SSTAT + 1792)

__global__ __launch_bounds__(256, 1) void attn_hl_kernel(
    const __nv_bfloat16* __restrict__ qh, const __nv_bfloat16* __restrict__ ql,
    const __nv_bfloat16* __restrict__ kh, const __nv_bfloat16* __restrict__ kl,
    const __nv_bfloat16* __restrict__ vth, const __nv_bfloat16* __restrict__ vtl,
    uint32_t* __restrict__ ohi, uint32_t* __restrict__ olo)
{
    extern __shared__ __align__(128) char sma[];
    const uint32_t sb = smem_u32(sma);
    float* sWmax  = (float*)(sma + SSTAT);
    float* sWsum  = sWmax + 128;
    float* sM     = sWsum + 128;
    float* sL     = sM + 64;
    float* sScale = sL + 64;

    const int h    = blockIdx.y;
    const int qt   = (int)gridDim.x - 1 - (int)blockIdx.x;   // longest-first
    const int t0   = qt * 64;
    const int tid  = threadIdx.x;
    const int w    = tid >> 5;
    const int lane = tid & 31;
    const int g    = lane >> 2;
    const int t    = lane & 3;
    const int mrow = (w & 3) * 16;
    const int nhalf = w >> 2;
    const int r0 = mrow + g, r1 = r0 + 8;

    for (int i = tid; i < 1536; i += 256) {
        const int r = i / 24, c = i - r * 24;
        const size_t src = (size_t)(t0 + r) * (NH * D_QK) + h * D_QK + c * 8;
        cp16(sma + SQH + r * 400 + c * 16, qh + src);
        cp16(sma + SQL + r * 400 + c * 16, ql + src);
    }
    CP_COMMIT();
    if (tid < 64) { sM[tid] = -1e30f; sL[tid] = 0.f; }

    float o[8][4];
#pragma unroll
    for (int i = 0; i < 8; i++)
#pragma unroll
        for (int j = 0; j < 4; j++) o[i][j] = 0.f;

    const int rowL = (lane & 7) + (lane & 8);
    const int kbL  = (lane >> 4) * 16;

    for (int kt = 0; kt <= qt; kt++) {
        const int k0 = kt * 64;
        __syncthreads();
        for (int i = tid; i < 1536; i += 256) {
            const int r = i / 24, c = i - r * 24;
            const size_t src = (size_t)(k0 + r) * (NH * D_QK) + h * D_QK + c * 8;
            cp16(sma + SKH + r * 400 + c * 16, kh + src);
            cp16(sma + SKL + r * 400 + c * 16, kl + src);
        }
        for (int i = tid; i < 1024; i += 256) {
            const int r = i >> 3, c = i & 7;
            const size_t src = ((size_t)h * D_V + r) * T_TOK + k0 + c * 8;
            cp16(sma + SVH + r * 144 + c * 16, vth + src);
            cp16(sma + SVL + r * 144 + c * 16, vtl + src);
        }
        CP_COMMIT();
        CP_WAIT0();
        __syncthreads();

        float s[4][4];
#pragma unroll
        for (int nt = 0; nt < 4; nt++)
#pragma unroll
            for (int j = 0; j < 4; j++) s[nt][j] = 0.f;

#pragma unroll 3
        for (int ks = 0; ks < 12; ks++) {
            const int kb = ks * 32 + kbL;
            uint32_t ah0, ah1, ah2, ah3, al0, al1, al2, al3;
            const int rA = (mrow + rowL) * 400 + kb;
            LDSM4(ah0, ah1, ah2, ah3, sb + SQH + rA);
            LDSM4(al0, al1, al2, al3, sb + SQL + rA);
            uint32_t bh[2][4], bl[2][4];
#pragma unroll
            for (int j = 0; j < 2; j++) {
                const int rB = (nhalf * 32 + j * 16 + rowL) * 400 + kb;
                LDSM4(bh[j][0], bh[j][1], bh[j][2], bh[j][3], sb + SKH + rB);
                LDSM4(bl[j][0], bl[j][1], bl[j][2], bl[j][3], sb + SKL + rB);
            }
#pragma unroll
            for (int nt = 0; nt < 4; nt++) {
                const int j = nt >> 1, hh = nt & 1;
                mma_bf16(s[nt], ah0, ah1, ah2, ah3, bh[j][hh], bh[j][hh + 2]);
                mma_bf16(s[nt], ah0, ah1, ah2, ah3, bl[j][hh], bl[j][hh + 2]);
                mma_bf16(s[nt], al0, al1, al2, al3, bh[j][hh], bh[j][hh + 2]);
            }
        }

        const int rg0 = t0 + r0, rg1 = t0 + r1;
#pragma unroll
        for (int nt = 0; nt < 4; nt++) {
            const int cg = k0 + nhalf * 32 + nt * 8 + 2 * t;
            s[nt][0] = (rg0 >= cg)     ? s[nt][0] * SCALING : -1e30f;
            s[nt][1] = (rg0 >= cg + 1) ? s[nt][1] * SCALING : -1e30f;
            s[nt][2] = (rg1 >= cg)     ? s[nt][2] * SCALING : -1e30f;
            s[nt][3] = (rg1 >= cg + 1) ? s[nt][3] * SCALING : -1e30f;
        }

        float mx0 = -1e30f, mx1 = -1e30f;
#pragma unroll
        for (int nt = 0; nt < 4; nt++) {
            mx0 = fmaxf(mx0, fmaxf(s[nt][0], s[nt][1]));
            mx1 = fmaxf(mx1, fmaxf(s[nt][2], s[nt][3]));
        }
        mx0 = fmaxf(mx0, __shfl_xor_sync(0xffffffffu, mx0, 1));
        mx0 = fmaxf(mx0, __shfl_xor_sync(0xffffffffu, mx0, 2));
        mx1 = fmaxf(mx1, __shfl_xor_sync(0xffffffffu, mx1, 1));
        mx1 = fmaxf(mx1, __shfl_xor_sync(0xffffffffu, mx1, 2));
        if (t == 0) { sWmax[nhalf * 64 + r0] = mx0; sWmax[nhalf * 64 + r1] = mx1; }
        __syncthreads();

        const float mn0 = fmaxf(sM[r0], fmaxf(sWmax[r0], sWmax[64 + r0]));
        const float mn1 = fmaxf(sM[r1], fmaxf(sWmax[r1], sWmax[64 + r1]));

        float sum0 = 0.f, sum1 = 0.f;
#pragma unroll
        for (int nt = 0; nt < 4; nt++) {
            s[nt][0] = __expf(s[nt][0] - mn0);
            s[nt][1] = __expf(s[nt][1] - mn0);
            s[nt][2] = __expf(s[nt][2] - mn1);
            s[nt][3] = __expf(s[nt][3] - mn1);
            sum0 += s[nt][0] + s[nt][1];
            sum1 += s[nt][2] + s[nt][3];
            const int coll = nhalf * 32 + nt * 8 + 2 * t;
            __nv_bfloat16 h0, l0, h1, l1;
            split_hl(s[nt][0], h0, l0); split_hl(s[nt][1], h1, l1);
            *(uint32_t*)(sma + SPH + r0 * 144 + coll * 2) = pack2(h0, h1);
            *(uint32_t*)(sma + SPL + r0 * 144 + coll * 2) = pack2(l0, l1);
            split_hl(s[nt][2], h0, l0); split_hl(s[nt][3], h1, l1);
            *(uint32_t*)(sma + SPH + r1 * 144 + coll * 2) = pack2(h0, h1);
            *(uint32_t*)(sma + SPL + r1 * 144 + coll * 2) = pack2(l0, l1);
        }
        sum0 += __shfl_xor_sync(0xffffffffu, sum0, 1);
        sum0 += __shfl_xor_sync(0xffffffffu, sum0, 2);
        sum1 += __shfl_xor_sync(0xffffffffu, sum1, 1);
        sum1 += __shfl_xor_sync(0xffffffffu, sum1, 2);
        if (t == 0) { sWsum[nhalf * 64 + r0] = sum0; sWsum[nhalf * 64 + r1] = sum1; }
        __syncthreads();

        if (tid < 64) {
            const float mo = sM[tid];
            const float mn = fmaxf(mo, fmaxf(sWmax[tid], sWmax[64 + tid]));
            const float sc = __expf(mo - mn);
            sM[tid] = mn;
            sL[tid] = sL[tid] * sc + sWsum[tid] + sWsum[64 + tid];
            sScale[tid] = sc;
        }
        __syncthreads();

        const float sc0 = sScale[r0], sc1 = sScale[r1];
#pragma unroll
        for (int nt = 0; nt < 8; nt++) {
            o[nt][0] *= sc0; o[nt][1] *= sc0;
            o[nt][2] *= sc1; o[nt][3] *= sc1;
        }

#pragma unroll
        for (int ks = 0; ks < 4; ks++) {
            const int kb = ks * 32 + kbL;
            uint32_t ph0, ph1, ph2, ph3, pl0, pl1, pl2, pl3;
            const int rP = (mrow + rowL) * 144 + kb;
            LDSM4(ph0, ph1, ph2, ph3, sb + SPH + rP);
            LDSM4(pl0, pl1, pl2, pl3, sb + SPL + rP);
#pragma unroll
            for (int j2 = 0; j2 < 4; j2++) {
                const int rV = (nhalf * 64 + j2 * 16 + rowL) * 144 + kb;
                uint32_t vh[4], vl[4];
                LDSM4(vh[0], vh[1], vh[2], vh[3], sb + SVH + rV);
                LDSM4(vl[0], vl[1], vl[2], vl[3], sb + SVL + rV);
#pragma unroll
                for (int hh = 0; hh < 2; hh++) {
                    float* acc = o[j2 * 2 + hh];
                    mma_bf16(acc, ph0, ph1, ph2, ph3, vh[hh], vh[hh + 2]);
                    mma_bf16(acc, ph0, ph1, ph2, ph3, vl[hh], vl[hh + 2]);
                    mma_bf16(acc, pl0, pl1, pl2, pl3, vh[hh], vh[hh + 2]);
                }
            }
        }
    }

    const float il0 = 1.f / sL[r0];
    const float il1 = 1.f / sL[r1];
#pragma unroll
    for (int nt = 0; nt < 8; nt++) {
        const int col = h * D_V + nhalf * 64 + nt * 8 + 2 * t;
        const float v00 = o[nt][0] * il0, v01 = o[nt][1] * il0;
        const float v10 = o[nt][2] * il1, v11 = o[nt][3] * il1;
        __nv_bfloat16 h0, l0, h1, l1;
        split_hl(v00, h0, l0); split_hl(v01, h1, l1);
        ohi[((size_t)(t0 + r0) * (NH * D_V) + col) >> 1] = pack2(h0, h1);
        olo[((size_t)(t0 + r0) * (NH * D_V) + col) >> 1] = pack2(l0, l1);
        split_hl(v10, h0, l0); split_hl(v11, h1, l1);
        ohi[((size_t)(t0 + r1) * (NH * D_V) + col) >> 1] = pack2(h0, h1);
        olo[((size_t)(t0 + r1) * (NH * D_V) + col) >> 1] = pack2(l0, l1);
    }
}

// ---------------- launch ----------------
extern "C" void kernel_launch(void* const* d_in, const int* in_sizes, int n_in,
                              void* d_out, int out_size)
{
    const float* hidden    = (const float*)d_in[0];
    const int*   positions = (const int*)  d_in[1];
    const float* w_qkv_a   = (const float*)d_in[2];
    const float* gamma_q   = (const float*)d_in[3];
    const float* w_q_b     = (const float*)d_in[4];
    const float* gamma_kv  = (const float*)d_in[5];
    const float* w_kv_b    = (const float*)d_in[6];
    const float* w_o       = (const float*)d_in[7];
    float* out = (float*)d_out;

    float *qkv_a, *qbuf, *kvbuf, *kpe;
    __nv_bfloat16 *hid_h, *hid_l, *qn_h, *qn_l, *kvn_h, *kvn_l, *at_h, *at_l;
    __nv_bfloat16 *wa_h, *wa_l, *wqb_h, *wqb_l, *wkvb_h, *wkvb_l, *wo_h, *wo_l;
    __nv_bfloat16 *q_h, *q_l, *k_h, *k_l, *vt_h, *vt_l;
    cudaGetSymbolAddress((void**)&qkv_a, g_qkv_a);
    cudaGetSymbolAddress((void**)&qbuf,  g_qbuf);
    cudaGetSymbolAddress((void**)&kvbuf, g_kvbuf);
    cudaGetSymbolAddress((void**)&kpe,   g_kpe);
    cudaGetSymbolAddress((void**)&hid_h, g_hid_hi);  cudaGetSymbolAddress((void**)&hid_l, g_hid_lo);
    cudaGetSymbolAddress((void**)&qn_h,  g_qn_hi);   cudaGetSymbolAddress((void**)&qn_l,  g_qn_lo);
    cudaGetSymbolAddress((void**)&kvn_h, g_kvn_hi);  cudaGetSymbolAddress((void**)&kvn_l, g_kvn_lo);
    cudaGetSymbolAddress((void**)&at_h,  g_attn_hi); cudaGetSymbolAddress((void**)&at_l,  g_attn_lo);
    cudaGetSymbolAddress((void**)&wa_h,  g_wa_hi);   cudaGetSymbolAddress((void**)&wa_l,  g_wa_lo);
    cudaGetSymbolAddress((void**)&wqb_h, g_wqb_hi);  cudaGetSymbolAddress((void**)&wqb_l, g_wqb_lo);
    cudaGetSymbolAddress((void**)&wkvb_h,g_wkvb_hi); cudaGetSymbolAddress((void**)&wkvb_l,g_wkvb_lo);
    cudaGetSymbolAddress((void**)&wo_h,  g_wo_hi);   cudaGetSymbolAddress((void**)&wo_l,  g_wo_lo);
    cudaGetSymbolAddress((void**)&q_h,   g_q_hi);    cudaGetSymbolAddress((void**)&q_l,   g_q_lo);
    cudaGetSymbolAddress((void**)&k_h,   g_k_hi);    cudaGetSymbolAddress((void**)&k_l,   g_k_lo);
    cudaGetSymbolAddress((void**)&vt_h,  g_vt_hi);   cudaGetSymbolAddress((void**)&vt_l,  g_vt_lo);

    cudaFuncSetAttribute(gemm_hl, cudaFuncAttributeMaxDynamicSharedMemorySize, W_SMEM);
    cudaFuncSetAttribute(attn_hl_kernel, cudaFuncAttributeMaxDynamicSharedMemorySize, ATT_SMEM);

    // 0) one-time conversions (wa padded to 2176 rows, pad rows zero)
    convert_hl_kernel<<<1184, 256>>>((const float2*)hidden,
        (uint32_t*)hid_h, (uint32_t*)hid_l, T_TOK * HID / 2);
    transpose_cvt_kernel<<<dim3(QKVP / 32, HID / 32),         dim3(32, 8)>>>(w_qkv_a, wa_h,   wa_l,   HID,      QKV_A_N);
    transpose_cvt_kernel<<<dim3((NH*D_QK) / 32, Q_LORA / 32), dim3(32, 8)>>>(w_q_b,   wqb_h,  wqb_l,  Q_LORA,   NH * D_QK);
    transpose_cvt_kernel<<<dim3((NH*256) / 32, KV_LORA / 32), dim3(32, 8)>>>(w_kv_b,  wkvb_h, wkvb_l, KV_LORA,  NH * 256);
    transpose_cvt_kernel<<<dim3(HID / 32, (NH*D_V) / 32),     dim3(32, 8)>>>(w_o,     wo_h,   wo_l,   NH * D_V, HID);

    // 1) qkv_a = hidden @ w_qkv_a   (N padded to 2176)
    gemm_hl<<<dim3(QKVP / 128, T_TOK / 256), 256, W_SMEM>>>(
        hid_h, hid_l, wa_h, wa_l, qkv_a, T_TOK, QKVP, HID);

    // 2) RMSNorm -> hi/lo
    rmsnorm_kernel<<<T_TOK, 256>>>(qkv_a, QKVP, 0,      Q_LORA,  gamma_q,  qn_h,  qn_l);
    rmsnorm_kernel<<<T_TOK, 256>>>(qkv_a, QKVP, Q_LORA, KV_LORA, gamma_kv, kvn_h, kvn_l);

    // 3) q = qn @ w_q_b
    gemm_hl<<<dim3((NH * D_QK) / 128, T_TOK / 256), 256, W_SMEM>>>(
        qn_h, qn_l, wqb_h, wqb_l, qbuf, T_TOK, NH * D_QK, Q_LORA);

    // 4) kv = kvn @ w_kv_b
    gemm_hl<<<dim3((NH * 256) / 128, T_TOK / 256), 256, W_SMEM>>>(
        kvn_h, kvn_l, wkvb_h, wkvb_l, kvbuf, T_TOK, NH * 256, KV_LORA);

    // 5) RoPE
    rope_kernel<<<T_TOK, 256>>>(qbuf, qkv_a, kpe, positions);

    // 6) attention operand planes
    convert_hl_kernel<<<1184, 256>>>((const float2*)qbuf,
        (uint32_t*)q_h, (uint32_t*)q_l, T_TOK * NH * D_QK / 2);
    build_k_kernel<<<T_TOK, 256>>>(kvbuf, kpe, k_h, k_l);
    build_vt_kernel<<<dim3(T_TOK / 32, D_V / 32, NH), dim3(32, 8)>>>(kvbuf, vt_h, vt_l);

    // 7) attention -> hi/lo planes
    attn_hl_kernel<<<dim3(T_TOK / 64, NH), 256, ATT_SMEM>>>(
        q_h, q_l, k_h, k_l, vt_h, vt_l, (uint32_t*)at_h, (uint32_t*)at_l);

    // 8) out = attn @ w_o
    gemm_hl<<<dim3(HID / 128, T_TOK / 256), 256, W_SMEM>>>(
        at_h, at_l, wo_h, wo_l, out, T_TOK, HID, NH * D_V);
}

// round 10
// speedup vs baseline: 1.1970x; 1.1970x over previous
#include <cuda_runtime.h>
#include <cuda_bf16.h>
#include <cuda_fp16.h>
#include <math.h>
#include <stdint.h>

// ---------------- problem constants ----------------
#define T_TOK   2048
#define HID     2048
#define NH      16
#define D_NOPE  128
#define D_ROPE  64
#define D_QK    192
#define D_V     128
#define Q_LORA  1536
#define KV_LORA 512
#define QKV_A_N 2112
#define SCALING 0.07216878364870322f   // 192^-0.5

// ---------------- scratch ----------------
__device__ __align__(128) float g_qkv_a [T_TOK * QKV_A_N];
__device__ __align__(128) float g_qbuf  [T_TOK * NH * D_QK];
__device__ __align__(128) float g_kvbuf [T_TOK * NH * 256];
__device__ __align__(128) float g_kpe   [T_TOK * D_ROPE];
// fp16 planes for GEMMs (A split hi/lo, B single-rounded)
__device__ __align__(128) __half g_hid_hi [T_TOK * HID];
__device__ __align__(128) __half g_hid_lo [T_TOK * HID];
__device__ __align__(128) __half g_qn_hi  [T_TOK * Q_LORA];
__device__ __align__(128) __half g_qn_lo  [T_TOK * Q_LORA];
__device__ __align__(128) __half g_kvn_hi [T_TOK * KV_LORA];
__device__ __align__(128) __half g_kvn_lo [T_TOK * KV_LORA];
__device__ __align__(128) __half g_attn_hi[T_TOK * NH * D_V];
__device__ __align__(128) __half g_attn_lo[T_TOK * NH * D_V];
__device__ __align__(128) __half g_wa_f16  [QKV_A_N * HID];
__device__ __align__(128) __half g_wqb_f16 [NH * D_QK * Q_LORA];
__device__ __align__(128) __half g_wkvb_f16[NH * 256 * KV_LORA];
__device__ __align__(128) __half g_wo_f16  [HID * NH * D_V];
// bf16 attention operand planes (3-product, proven accurate)
__device__ __align__(128) __nv_bfloat16 g_q_hi  [T_TOK * NH * D_QK];
__device__ __align__(128) __nv_bfloat16 g_q_lo  [T_TOK * NH * D_QK];
__device__ __align__(128) __nv_bfloat16 g_k_hi  [T_TOK * NH * D_QK];
__device__ __align__(128) __nv_bfloat16 g_k_lo  [T_TOK * NH * D_QK];
__device__ __align__(128) __nv_bfloat16 g_vt_hi [NH * D_V * T_TOK];
__device__ __align__(128) __nv_bfloat16 g_vt_lo [NH * D_V * T_TOK];

// ---------------- helpers ----------------
__device__ __forceinline__ void cp16(void* s, const void* g) {
    unsigned int sa = (unsigned int)__cvta_generic_to_shared(s);
    asm volatile("cp.async.cg.shared.global [%0], [%1], 16;" :: "r"(sa), "l"(g));
}
#define CP_COMMIT() asm volatile("cp.async.commit_group;")
#define CP_WAIT1()  asm volatile("cp.async.wait_group 1;")
#define CP_WAIT0()  asm volatile("cp.async.wait_group 0;")

__device__ __forceinline__ uint32_t smem_u32(const void* p) {
    return (uint32_t)__cvta_generic_to_shared(p);
}
#define LDSM4(r0, r1, r2, r3, a) \
    asm volatile("ldmatrix.sync.aligned.m8n8.x4.shared.b16 {%0,%1,%2,%3}, [%4];" \
        : "=r"(r0), "=r"(r1), "=r"(r2), "=r"(r3) : "r"(a))

__device__ __forceinline__ void mma_bf16(float* c,
    uint32_t a0, uint32_t a1, uint32_t a2, uint32_t a3, uint32_t b0, uint32_t b1)
{
    asm volatile(
        "mma.sync.aligned.m16n8k16.row.col.f32.bf16.bf16.f32 "
        "{%0,%1,%2,%3},{%4,%5,%6,%7},{%8,%9},{%0,%1,%2,%3};"
        : "+f"(c[0]), "+f"(c[1]), "+f"(c[2]), "+f"(c[3])
        : "r"(a0), "r"(a1), "r"(a2), "r"(a3), "r"(b0), "r"(b1));
}
__device__ __forceinline__ void mma_f16(float* c,
    uint32_t a0, uint32_t a1, uint32_t a2, uint32_t a3, uint32_t b0, uint32_t b1)
{
    asm volatile(
        "mma.sync.aligned.m16n8k16.row.col.f32.f16.f16.f32 "
        "{%0,%1,%2,%3},{%4,%5,%6,%7},{%8,%9},{%0,%1,%2,%3};"
        : "+f"(c[0]), "+f"(c[1]), "+f"(c[2]), "+f"(c[3])
        : "r"(a0), "r"(a1), "r"(a2), "r"(a3), "r"(b0), "r"(b1));
}

__device__ __forceinline__ void split_bf(float v, __nv_bfloat16& h, __nv_bfloat16& l) {
    h = __float2bfloat16(v);
    l = __float2bfloat16(v - __bfloat162float(h));
}
__device__ __forceinline__ void split_f16(float v, __half& h, __half& l) {
    h = __float2half_rn(v);
    l = __float2half_rn(v - __half2float(h));
}
__device__ __forceinline__ uint32_t pack2bf(__nv_bfloat16 a, __nv_bfloat16 b) {
    return (uint32_t)__bfloat16_as_ushort(a) | ((uint32_t)__bfloat16_as_ushort(b) << 16);
}
__device__ __forceinline__ uint32_t pack2h(__half a, __half b) {
    return (uint32_t)__half_as_ushort(a) | ((uint32_t)__half_as_ushort(b) << 16);
}

// ---------------- converters ----------------
// fp32 -> fp16 hi/lo (activations for GEMM A operand)
__global__ __launch_bounds__(256) void convert_hl_f16_kernel(
    const float2* __restrict__ src, uint32_t* __restrict__ hi,
    uint32_t* __restrict__ lo, int n2)
{
    int i = blockIdx.x * 256 + threadIdx.x;
    const int stride = gridDim.x * 256;
    for (; i < n2; i += stride) {
        const float2 v = src[i];
        __half h0, l0, h1, l1;
        split_f16(v.x, h0, l0);
        split_f16(v.y, h1, l1);
        hi[i] = pack2h(h0, h1);
        lo[i] = pack2h(l0, l1);
    }
}

// fp32 -> bf16 hi/lo (attention Q operand)
__global__ __launch_bounds__(256) void convert_hl_bf_kernel(
    const float2* __restrict__ src, uint32_t* __restrict__ hi,
    uint32_t* __restrict__ lo, int n2)
{
    int i = blockIdx.x * 256 + threadIdx.x;
    const int stride = gridDim.x * 256;
    for (; i < n2; i += stride) {
        const float2 v = src[i];
        __nv_bfloat16 h0, l0, h1, l1;
        split_bf(v.x, h0, l0);
        split_bf(v.y, h1, l1);
        hi[i] = pack2bf(h0, h1);
        lo[i] = pack2bf(l0, l1);
    }
}

// in fp32 [R][C] -> out single fp16 [C][R] (weights)
__global__ __launch_bounds__(256) void transpose_cvt_f16_kernel(
    const float* __restrict__ in, __half* __restrict__ outp, int R, int C)
{
    __shared__ float t[32][33];
    const int c0 = blockIdx.x * 32, r0 = blockIdx.y * 32;
    const int x = threadIdx.x, y = threadIdx.y;
#pragma unroll
    for (int j = 0; j < 32; j += 8)
        t[y + j][x] = in[(size_t)(r0 + y + j) * C + c0 + x];
    __syncthreads();
#pragma unroll
    for (int j = 0; j < 32; j += 8)
        outp[(size_t)(c0 + y + j) * R + r0 + x] = __float2half_rn(t[x][y + j]);
}

// build K planes (bf16 hi/lo): k[t][h*192+d]
__global__ __launch_bounds__(256) void build_k_kernel(
    const float* __restrict__ kvbuf, const float* __restrict__ kpe,
    __nv_bfloat16* __restrict__ kh, __nv_bfloat16* __restrict__ kl)
{
    const int t = blockIdx.x;
    for (int i = threadIdx.x; i < NH * D_QK; i += 256) {
        const int h = i / D_QK, d = i - h * D_QK;
        const float v = (d < 128)
            ? kvbuf[(size_t)t * (NH * 256) + h * 256 + d]
            : kpe[(size_t)t * D_ROPE + (d - 128)];
        __nv_bfloat16 hh, ll;
        split_bf(v, hh, ll);
        kh[(size_t)t * (NH * D_QK) + i] = hh;
        kl[(size_t)t * (NH * D_QK) + i] = ll;
    }
}

// build VT planes (bf16 hi/lo): vt[h][d][t]
__global__ __launch_bounds__(256) void build_vt_kernel(
    const float* __restrict__ kvbuf,
    __nv_bfloat16* __restrict__ vth, __nv_bfloat16* __restrict__ vtl)
{
    __shared__ float tile[32][33];
    const int h = blockIdx.z;
    const int d0 = blockIdx.y * 32;
    const int t0 = blockIdx.x * 32;
    const int x = threadIdx.x, y = threadIdx.y;
#pragma unroll
    for (int j = 0; j < 32; j += 8)
        tile[y + j][x] = kvbuf[(size_t)(t0 + y + j) * (NH * 256) + h * 256 + 128 + d0 + x];
    __syncthreads();
#pragma unroll
    for (int j = 0; j < 32; j += 8) {
        const float v = tile[x][y + j];
        __nv_bfloat16 hh, ll;
        split_bf(v, hh, ll);
        const size_t o = ((size_t)h * D_V + d0 + y + j) * T_TOK + t0 + x;
        vth[o] = hh;
        vtl[o] = ll;
    }
}

// ---------------- fp16 2-product GEMM: C = (Ah+Al) @ Bh^T ----------------
// BM=256, BN=64, BK=32; 8 warps (4m x 2n), warp tile 64x32, occ 2.
#define PITCH_B 80
#define F_AHI 0
#define F_ALO 20480
#define F_BHI 40960
#define F_STAGE 46080
#define F_SMEM  (2 * F_STAGE)

__global__ __launch_bounds__(256, 2) void gemm_f16(
    const __half* __restrict__ Ah, const __half* __restrict__ Al,
    const __half* __restrict__ Bh,
    float* __restrict__ C, int M, int N, int K)
{
    extern __shared__ __align__(128) char smx[];
    const uint32_t sbase = smem_u32(smx);
    const int tid  = threadIdx.x;
    const int warp = tid >> 5;
    const int lane = tid & 31;
    const int wm   = warp >> 1;
    const int wn   = warp & 1;
    const int row0 = blockIdx.y * 256;
    const int col0 = blockIdx.x * 64;

    float c[16][4];
#pragma unroll
    for (int i = 0; i < 16; i++)
#pragma unroll
        for (int j = 0; j < 4; j++) c[i][j] = 0.f;

    auto fill = [&](int stage, int k0) {
        char* st = smx + stage * F_STAGE;
#pragma unroll
        for (int rep = 0; rep < 4; rep++) {
            const int cch = tid + rep * 256;
            const int r = cch >> 2, q = cch & 3;
            const size_t src = (size_t)(row0 + r) * K + k0 + q * 8;
            cp16(st + F_AHI + r * PITCH_B + q * 16, Ah + src);
            cp16(st + F_ALO + r * PITCH_B + q * 16, Al + src);
        }
        {
            const int r = tid >> 2, q = tid & 3;   // 64 rows x 4 chunks
            const size_t src = (size_t)(col0 + r) * K + k0 + q * 8;
            cp16(st + F_BHI + r * PITCH_B + q * 16, Bh + src);
        }
    };

    fill(0, 0);
    CP_COMMIT();

    const int nch = K >> 5;
    const int rowL = (lane & 7) + (lane & 8);
    const int kbL  = (lane >> 4) * 16;

    for (int ch = 0; ch < nch; ch++) {
        const int buf = ch & 1;
        if (ch + 1 < nch) {
            fill(buf ^ 1, (ch + 1) * 32);
            CP_COMMIT();
            CP_WAIT1();
        } else {
            CP_WAIT0();
        }
        __syncthreads();

        const uint32_t sAh = sbase + buf * F_STAGE + F_AHI;
        const uint32_t sAl = sbase + buf * F_STAGE + F_ALO;
        const uint32_t sBh = sbase + buf * F_STAGE + F_BHI;

#pragma unroll
        for (int kk = 0; kk < 2; kk++) {
            const int kb = kk * 32 + kbL;
            uint32_t bh[2][4];
#pragma unroll
            for (int j = 0; j < 2; j++) {
                const int rB = (wn * 32 + j * 16 + rowL) * PITCH_B + kb;
                LDSM4(bh[j][0], bh[j][1], bh[j][2], bh[j][3], sBh + rB);
            }
#pragma unroll
            for (int i = 0; i < 4; i++) {
                const int rA = (wm * 64 + i * 16 + rowL) * PITCH_B + kb;
                uint32_t ah0, ah1, ah2, ah3, al0, al1, al2, al3;
                LDSM4(ah0, ah1, ah2, ah3, sAh + rA);
                LDSM4(al0, al1, al2, al3, sAl + rA);
#pragma unroll
                for (int f = 0; f < 4; f++) {
                    const int j = f >> 1, h = f & 1;
                    float* acc = c[i * 4 + f];
                    mma_f16(acc, ah0, ah1, ah2, ah3, bh[j][h], bh[j][h + 2]);
                    mma_f16(acc, al0, al1, al2, al3, bh[j][h], bh[j][h + 2]);
                }
            }
        }
        __syncthreads();
    }

    const int qr = lane >> 2, qc = 2 * (lane & 3);
#pragma unroll
    for (int i = 0; i < 4; i++) {
#pragma unroll
        for (int f = 0; f < 4; f++) {
            const int r   = row0 + wm * 64 + i * 16 + qr;
            const int col = col0 + wn * 32 + f * 8 + qc;
            *(float2*)(C + (size_t)r * N + col)       = make_float2(c[i * 4 + f][0], c[i * 4 + f][1]);
            *(float2*)(C + (size_t)(r + 8) * N + col) = make_float2(c[i * 4 + f][2], c[i * 4 + f][3]);
        }
    }
}

// ---------------- RMSNorm -> fp16 hi/lo ----------------
__global__ __launch_bounds__(256) void rmsnorm_kernel(
    const float* __restrict__ in, int ld, int off, int width,
    const float* __restrict__ gamma,
    __half* __restrict__ ohi, __half* __restrict__ olo)
{
    const int row = blockIdx.x;
    const float* x = in + (size_t)row * ld + off;
    float ss = 0.f;
    for (int i = threadIdx.x; i < width; i += 256) {
        float v = x[i];
        ss += v * v;
    }
#pragma unroll
    for (int o = 16; o; o >>= 1) ss += __shfl_xor_sync(0xffffffffu, ss, o);
    __shared__ float warp_s[8];
    __shared__ float s_inv;
    if ((threadIdx.x & 31) == 0) warp_s[threadIdx.x >> 5] = ss;
    __syncthreads();
    if (threadIdx.x == 0) {
        float t = 0.f;
#pragma unroll
        for (int i = 0; i < 8; i++) t += warp_s[i];
        s_inv = rsqrtf(t / (float)width + 1e-6f);
    }
    __syncthreads();
    const float inv = s_inv;
    for (int i = threadIdx.x; i < width; i += 256) {
        const float v = x[i] * inv * gamma[i];
        __half h, l;
        split_f16(v, h, l);
        ohi[(size_t)row * width + i] = h;
        olo[(size_t)row * width + i] = l;
    }
}

// ---------------- RoPE (fp32) ----------------
__global__ __launch_bounds__(256) void rope_kernel(
    float* __restrict__ q, const float* __restrict__ qkv_a,
    float* __restrict__ kpe, const int* __restrict__ positions)
{
    const int t = blockIdx.x;
    const float pos = (float)positions[t];
    for (int i = threadIdx.x; i < NH * 32 + 32; i += 256) {
        if (i < NH * 32) {
            const int h = i >> 5, p = i & 31;
            const float inv = powf(10000.0f, -(float)p / 32.0f);
            float s, c;
            sincosf(pos * inv, &s, &c);
            float* base = q + (size_t)t * (NH * D_QK) + h * D_QK + D_NOPE;
            const float x1 = base[2 * p], x2 = base[2 * p + 1];
            base[2 * p]     = x1 * c - x2 * s;
            base[2 * p + 1] = x1 * s + x2 * c;
        } else {
            const int p = i - NH * 32;
            const float inv = powf(10000.0f, -(float)p / 32.0f);
            float s, c;
            sincosf(pos * inv, &s, &c);
            const float* src = qkv_a + (size_t)t * QKV_A_N + (Q_LORA + KV_LORA);
            const float x1 = src[2 * p], x2 = src[2 * p + 1];
            kpe[(size_t)t * D_ROPE + 2 * p]     = x1 * c - x2 * s;
            kpe[(size_t)t * D_ROPE + 2 * p + 1] = x1 * s + x2 * c;
        }
    }
}

// ---------------- bf16 hi/lo causal flash attention (R8, epilogue -> fp16) ----------------
#define SQH 0
#define SQL 25600
#define SKH 51200
#define SKL 76800
#define SVH 102400
#define SVL 120832
#define SPH 139264
#define SPL 148480
#define SSTAT 157696
#define ATT_SMEM (SSTAT + 1792)

__global__ __launch_bounds__(256, 1) void attn_hl_kernel(
    const __nv_bfloat16* __restrict__ qh, const __nv_bfloat16* __restrict__ ql,
    const __nv_bfloat16* __restrict__ kh, const __nv_bfloat16* __restrict__ kl,
    const __nv_bfloat16* __restrict__ vth, const __nv_bfloat16* __restrict__ vtl,
    uint32_t* __restrict__ ohi, uint32_t* __restrict__ olo)
{
    extern __shared__ __align__(128) char sma[];
    const uint32_t sb = smem_u32(sma);
    float* sWmax  = (float*)(sma + SSTAT);
    float* sWsum  = sWmax + 128;
    float* sM     = sWsum + 128;
    float* sL     = sM + 64;
    float* sScale = sL + 64;

    const int h    = blockIdx.y;
    const int qt   = (int)gridDim.x - 1 - (int)blockIdx.x;   // longest-first
    const int t0   = qt * 64;
    const int tid  = threadIdx.x;
    const int w    = tid >> 5;
    const int lane = tid & 31;
    const int g    = lane >> 2;
    const int t    = lane & 3;
    const int mrow = (w & 3) * 16;
    const int nhalf = w >> 2;
    const int r0 = mrow + g, r1 = r0 + 8;

    for (int i = tid; i < 1536; i += 256) {
        const int r = i / 24, c = i - r * 24;
        const size_t src = (size_t)(t0 + r) * (NH * D_QK) + h * D_QK + c * 8;
        cp16(sma + SQH + r * 400 + c * 16, qh + src);
        cp16(sma + SQL + r * 400 + c * 16, ql + src);
    }
    CP_COMMIT();
    if (tid < 64) { sM[tid] = -1e30f; sL[tid] = 0.f; }

    float o[8][4];
#pragma unroll
    for (int i = 0; i < 8; i++)
#pragma unroll
        for (int j = 0; j < 4; j++) o[i][j] = 0.f;

    const int rowL = (lane & 7) + (lane & 8);
    const int kbL  = (lane >> 4) * 16;

    for (int kt = 0; kt <= qt; kt++) {
        const int k0 = kt * 64;
        __syncthreads();
        for (int i = tid; i < 1536; i += 256) {
            const int r = i / 24, c = i - r * 24;
            const size_t src = (size_t)(k0 + r) * (NH * D_QK) + h * D_QK + c * 8;
            cp16(sma + SKH + r * 400 + c * 16, kh + src);
            cp16(sma + SKL + r * 400 + c * 16, kl + src);
        }
        for (int i = tid; i < 1024; i += 256) {
            const int r = i >> 3, c = i & 7;
            const size_t src = ((size_t)h * D_V + r) * T_TOK + k0 + c * 8;
            cp16(sma + SVH + r * 144 + c * 16, vth + src);
            cp16(sma + SVL + r * 144 + c * 16, vtl + src);
        }
        CP_COMMIT();
        CP_WAIT0();
        __syncthreads();

        float s[4][4];
#pragma unroll
        for (int nt = 0; nt < 4; nt++)
#pragma unroll
            for (int j = 0; j < 4; j++) s[nt][j] = 0.f;

#pragma unroll 3
        for (int ks = 0; ks < 12; ks++) {
            const int kb = ks * 32 + kbL;
            uint32_t ah0, ah1, ah2, ah3, al0, al1, al2, al3;
            const int rA = (mrow + rowL) * 400 + kb;
            LDSM4(ah0, ah1, ah2, ah3, sb + SQH + rA);
            LDSM4(al0, al1, al2, al3, sb + SQL + rA);
            uint32_t bh[2][4], bl[2][4];
#pragma unroll
            for (int j = 0; j < 2; j++) {
                const int rB = (nhalf * 32 + j * 16 + rowL) * 400 + kb;
                LDSM4(bh[j][0], bh[j][1], bh[j][2], bh[j][3], sb + SKH + rB);
                LDSM4(bl[j][0], bl[j][1], bl[j][2], bl[j][3], sb + SKL + rB);
            }
#pragma unroll
            for (int nt = 0; nt < 4; nt++) {
                const int j = nt >> 1, hh = nt & 1;
                mma_bf16(s[nt], ah0, ah1, ah2, ah3, bh[j][hh], bh[j][hh + 2]);
                mma_bf16(s[nt], ah0, ah1, ah2, ah3, bl[j][hh], bl[j][hh + 2]);
                mma_bf16(s[nt], al0, al1, al2, al3, bh[j][hh], bh[j][hh + 2]);
            }
        }

        const int rg0 = t0 + r0, rg1 = t0 + r1;
#pragma unroll
        for (int nt = 0; nt < 4; nt++) {
            const int cg = k0 + nhalf * 32 + nt * 8 + 2 * t;
            s[nt][0] = (rg0 >= cg)     ? s[nt][0] * SCALING : -1e30f;
            s[nt][1] = (rg0 >= cg + 1) ? s[nt][1] * SCALING : -1e30f;
            s[nt][2] = (rg1 >= cg)     ? s[nt][2] * SCALING : -1e30f;
            s[nt][3] = (rg1 >= cg + 1) ? s[nt][3] * SCALING : -1e30f;
        }

        float mx0 = -1e30f, mx1 = -1e30f;
#pragma unroll
        for (int nt = 0; nt < 4; nt++) {
            mx0 = fmaxf(mx0, fmaxf(s[nt][0], s[nt][1]));
            mx1 = fmaxf(mx1, fmaxf(s[nt][2], s[nt][3]));
        }
        mx0 = fmaxf(mx0, __shfl_xor_sync(0xffffffffu, mx0, 1));
        mx0 = fmaxf(mx0, __shfl_xor_sync(0xffffffffu, mx0, 2));
        mx1 = fmaxf(mx1, __shfl_xor_sync(0xffffffffu, mx1, 1));
        mx1 = fmaxf(mx1, __shfl_xor_sync(0xffffffffu, mx1, 2));
        if (t == 0) { sWmax[nhalf * 64 + r0] = mx0; sWmax[nhalf * 64 + r1] = mx1; }
        __syncthreads();

        const float mn0 = fmaxf(sM[r0], fmaxf(sWmax[r0], sWmax[64 + r0]));
        const float mn1 = fmaxf(sM[r1], fmaxf(sWmax[r1], sWmax[64 + r1]));

        float sum0 = 0.f, sum1 = 0.f;
#pragma unroll
        for (int nt = 0; nt < 4; nt++) {
            s[nt][0] = __expf(s[nt][0] - mn0);
            s[nt][1] = __expf(s[nt][1] - mn0);
            s[nt][2] = __expf(s[nt][2] - mn1);
            s[nt][3] = __expf(s[nt][3] - mn1);
            sum0 += s[nt][0] + s[nt][1];
            sum1 += s[nt][2] + s[nt][3];
            const int coll = nhalf * 32 + nt * 8 + 2 * t;
            __nv_bfloat16 h0, l0, h1, l1;
            split_bf(s[nt][0], h0, l0); split_bf(s[nt][1], h1, l1);
            *(uint32_t*)(sma + SPH + r0 * 144 + coll * 2) = pack2bf(h0, h1);
            *(uint32_t*)(sma + SPL + r0 * 144 + coll * 2) = pack2bf(l0, l1);
            split_bf(s[nt][2], h0, l0); split_bf(s[nt][3], h1, l1);
            *(uint32_t*)(sma + SPH + r1 * 144 + coll * 2) = pack2bf(h0, h1);
            *(uint32_t*)(sma + SPL + r1 * 144 + coll * 2) = pack2bf(l0, l1);
        }
        sum0 += __shfl_xor_sync(0xffffffffu, sum0, 1);
        sum0 += __shfl_xor_sync(0xffffffffu, sum0, 2);
        sum1 += __shfl_xor_sync(0xffffffffu, sum1, 1);
        sum1 += __shfl_xor_sync(0xffffffffu, sum1, 2);
        if (t == 0) { sWsum[nhalf * 64 + r0] = sum0; sWsum[nhalf * 64 + r1] = sum1; }
        __syncthreads();

        if (tid < 64) {
            const float mo = sM[tid];
            const float mn = fmaxf(mo, fmaxf(sWmax[tid], sWmax[64 + tid]));
            const float sc = __expf(mo - mn);
            sM[tid] = mn;
            sL[tid] = sL[tid] * sc + sWsum[tid] + sWsum[64 + tid];
            sScale[tid] = sc;
        }
        __syncthreads();

        const float sc0 = sScale[r0], sc1 = sScale[r1];
#pragma unroll
        for (int nt = 0; nt < 8; nt++) {
            o[nt][0] *= sc0; o[nt][1] *= sc0;
            o[nt][2] *= sc1; o[nt][3] *= sc1;
        }

#pragma unroll
        for (int ks = 0; ks < 4; ks++) {
            const int kb = ks * 32 + kbL;
            uint32_t ph0, ph1, ph2, ph3, pl0, pl1, pl2, pl3;
            const int rP = (mrow + rowL) * 144 + kb;
            LDSM4(ph0, ph1, ph2, ph3, sb + SPH + rP);
            LDSM4(pl0, pl1, pl2, pl3, sb + SPL + rP);
#pragma unroll
            for (int j2 = 0; j2 < 4; j2++) {
                const int rV = (nhalf * 64 + j2 * 16 + rowL) * 144 + kb;
                uint32_t vh[4], vl[4];
                LDSM4(vh[0], vh[1], vh[2], vh[3], sb + SVH + rV);
                LDSM4(vl[0], vl[1], vl[2], vl[3], sb + SVL + rV);
#pragma unroll
                for (int hh = 0; hh < 2; hh++) {
                    float* acc = o[j2 * 2 + hh];
                    mma_bf16(acc, ph0, ph1, ph2, ph3, vh[hh], vh[hh + 2]);
                    mma_bf16(acc, ph0, ph1, ph2, ph3, vl[hh], vl[hh + 2]);
                    mma_bf16(acc, pl0, pl1, pl2, pl3, vh[hh], vh[hh + 2]);
                }
            }
        }
    }

    // epilogue -> fp16 hi/lo planes (A operand of the w_o GEMM)
    const float il0 = 1.f / sL[r0];
    const float il1 = 1.f / sL[r1];
#pragma unroll
    for (int nt = 0; nt < 8; nt++) {
        const int col = h * D_V + nhalf * 64 + nt * 8 + 2 * t;
        const float v00 = o[nt][0] * il0, v01 = o[nt][1] * il0;
        const float v10 = o[nt][2] * il1, v11 = o[nt][3] * il1;
        __half h0, l0, h1, l1;
        split_f16(v00, h0, l0); split_f16(v01, h1, l1);
        ohi[((size_t)(t0 + r0) * (NH * D_V) + col) >> 1] = pack2h(h0, h1);
        olo[((size_t)(t0 + r0) * (NH * D_V) + col) >> 1] = pack2h(l0, l1);
        split_f16(v10, h0, l0); split_f16(v11, h1, l1);
        ohi[((size_t)(t0 + r1) * (NH * D_V) + col) >> 1] = pack2h(h0, h1);
        olo[((size_t)(t0 + r1) * (NH * D_V) + col) >> 1] = pack2h(l0, l1);
    }
}

// ---------------- launch ----------------
extern "C" void kernel_launch(void* const* d_in, const int* in_sizes, int n_in,
                              void* d_out, int out_size)
{
    const float* hidden    = (const float*)d_in[0];
    const int*   positions = (const int*)  d_in[1];
    const float* w_qkv_a   = (const float*)d_in[2];
    const float* gamma_q   = (const float*)d_in[3];
    const float* w_q_b     = (const float*)d_in[4];
    const float* gamma_kv  = (const float*)d_in[5];
    const float* w_kv_b    = (const float*)d_in[6];
    const float* w_o       = (const float*)d_in[7];
    float* out = (float*)d_out;

    float *qkv_a, *qbuf, *kvbuf, *kpe;
    __half *hid_h, *hid_l, *qn_h, *qn_l, *kvn_h, *kvn_l, *at_h, *at_l;
    __half *wa, *wqb, *wkvb, *wo;
    __nv_bfloat16 *q_h, *q_l, *k_h, *k_l, *vt_h, *vt_l;
    cudaGetSymbolAddress((void**)&qkv_a, g_qkv_a);
    cudaGetSymbolAddress((void**)&qbuf,  g_qbuf);
    cudaGetSymbolAddress((void**)&kvbuf, g_kvbuf);
    cudaGetSymbolAddress((void**)&kpe,   g_kpe);
    cudaGetSymbolAddress((void**)&hid_h, g_hid_hi);  cudaGetSymbolAddress((void**)&hid_l, g_hid_lo);
    cudaGetSymbolAddress((void**)&qn_h,  g_qn_hi);   cudaGetSymbolAddress((void**)&qn_l,  g_qn_lo);
    cudaGetSymbolAddress((void**)&kvn_h, g_kvn_hi);  cudaGetSymbolAddress((void**)&kvn_l, g_kvn_lo);
    cudaGetSymbolAddress((void**)&at_h,  g_attn_hi); cudaGetSymbolAddress((void**)&at_l,  g_attn_lo);
    cudaGetSymbolAddress((void**)&wa,    g_wa_f16);
    cudaGetSymbolAddress((void**)&wqb,   g_wqb_f16);
    cudaGetSymbolAddress((void**)&wkvb,  g_wkvb_f16);
    cudaGetSymbolAddress((void**)&wo,    g_wo_f16);
    cudaGetSymbolAddress((void**)&q_h,   g_q_hi);    cudaGetSymbolAddress((void**)&q_l,   g_q_lo);
    cudaGetSymbolAddress((void**)&k_h,   g_k_hi);    cudaGetSymbolAddress((void**)&k_l,   g_k_lo);
    cudaGetSymbolAddress((void**)&vt_h,  g_vt_hi);   cudaGetSymbolAddress((void**)&vt_l,  g_vt_lo);

    cudaFuncSetAttribute(gemm_f16, cudaFuncAttributeMaxDynamicSharedMemorySize, F_SMEM);
    cudaFuncSetAttribute(attn_hl_kernel, cudaFuncAttributeMaxDynamicSharedMemorySize, ATT_SMEM);

    // 0) one-time conversions
    convert_hl_f16_kernel<<<1184, 256>>>((const float2*)hidden,
        (uint32_t*)hid_h, (uint32_t*)hid_l, T_TOK * HID / 2);
    transpose_cvt_f16_kernel<<<dim3(QKV_A_N / 32, HID / 32),      dim3(32, 8)>>>(w_qkv_a, wa,   HID,      QKV_A_N);
    transpose_cvt_f16_kernel<<<dim3((NH*D_QK) / 32, Q_LORA / 32), dim3(32, 8)>>>(w_q_b,   wqb,  Q_LORA,   NH * D_QK);
    transpose_cvt_f16_kernel<<<dim3((NH*256) / 32, KV_LORA / 32), dim3(32, 8)>>>(w_kv_b,  wkvb, KV_LORA,  NH * 256);
    transpose_cvt_f16_kernel<<<dim3(HID / 32, (NH*D_V) / 32),     dim3(32, 8)>>>(w_o,     wo,   NH * D_V, HID);

    // 1) qkv_a = hidden @ w_qkv_a
    gemm_f16<<<dim3(QKV_A_N / 64, T_TOK / 256), 256, F_SMEM>>>(
        hid_h, hid_l, wa, qkv_a, T_TOK, QKV_A_N, HID);

    // 2) RMSNorm -> fp16 hi/lo
    rmsnorm_kernel<<<T_TOK, 256>>>(qkv_a, QKV_A_N, 0,      Q_LORA,  gamma_q,  qn_h,  qn_l);
    rmsnorm_kernel<<<T_TOK, 256>>>(qkv_a, QKV_A_N, Q_LORA, KV_LORA, gamma_kv, kvn_h, kvn_l);

    // 3) q = qn @ w_q_b
    gemm_f16<<<dim3((NH * D_QK) / 64, T_TOK / 256), 256, F_SMEM>>>(
        qn_h, qn_l, wqb, qbuf, T_TOK, NH * D_QK, Q_LORA);

    // 4) kv = kvn @ w_kv_b
    gemm_f16<<<dim3((NH * 256) / 64, T_TOK / 256), 256, F_SMEM>>>(
        kvn_h, kvn_l, wkvb, kvbuf, T_TOK, NH * 256, KV_LORA);

    // 5) RoPE
    rope_kernel<<<T_TOK, 256>>>(qbuf, qkv_a, kpe, positions);

    // 6) attention operand planes (bf16 hi/lo)
    convert_hl_bf_kernel<<<1184, 256>>>((const float2*)qbuf,
        (uint32_t*)q_h, (uint32_t*)q_l, T_TOK * NH * D_QK / 2);
    build_k_kernel<<<T_TOK, 256>>>(kvbuf, kpe, k_h, k_l);
    build_vt_kernel<<<dim3(T_TOK / 32, D_V / 32, NH), dim3(32, 8)>>>(kvbuf, vt_h, vt_l);

    // 7) attention -> fp16 hi/lo planes
    attn_hl_kernel<<<dim3(T_TOK / 64, NH), 256, ATT_SMEM>>>(
        q_h, q_l, k_h, k_l, vt_h, vt_l, (uint32_t*)at_h, (uint32_t*)at_l);

    // 8) out = attn @ w_o
    gemm_f16<<<dim3(HID / 64, T_TOK / 256), 256, F_SMEM>>>(
        at_h, at_l, wo, out, T_TOK, HID, NH * D_V);
}

// round 11
// speedup vs baseline: 1.3826x; 1.1550x over previous
#include <cuda_runtime.h>
#include <cuda_fp16.h>
#include <math.h>
#include <stdint.h>

// ---------------- problem constants ----------------
#define T_TOK   2048
#define HID     2048
#define NH      16
#define D_NOPE  128
#define D_ROPE  64
#define D_QK    192
#define D_V     128
#define Q_LORA  1536
#define KV_LORA 512
#define QKV_A_N 2112
#define SCALING 0.07216878364870322f   // 192^-0.5

// ---------------- scratch ----------------
__device__ __align__(128) float g_qkv_a [T_TOK * QKV_A_N];
__device__ __align__(128) float g_qbuf  [T_TOK * NH * D_QK];
__device__ __align__(128) float g_kvbuf [T_TOK * NH * 256];
__device__ __align__(128) float g_kpe   [T_TOK * D_ROPE];
// fp16 planes for GEMMs (A split hi/lo, B single-rounded)
__device__ __align__(128) __half g_hid_hi [T_TOK * HID];
__device__ __align__(128) __half g_hid_lo [T_TOK * HID];
__device__ __align__(128) __half g_qn_hi  [T_TOK * Q_LORA];
__device__ __align__(128) __half g_qn_lo  [T_TOK * Q_LORA];
__device__ __align__(128) __half g_kvn_hi [T_TOK * KV_LORA];
__device__ __align__(128) __half g_kvn_lo [T_TOK * KV_LORA];
__device__ __align__(128) __half g_attn_hi[T_TOK * NH * D_V];
__device__ __align__(128) __half g_attn_lo[T_TOK * NH * D_V];
__device__ __align__(128) __half g_wa_f16  [QKV_A_N * HID];
__device__ __align__(128) __half g_wqb_f16 [NH * D_QK * Q_LORA];
__device__ __align__(128) __half g_wkvb_f16[NH * 256 * KV_LORA];
__device__ __align__(128) __half g_wo_f16  [HID * NH * D_V];
// fp16 attention operand planes (Q hi/lo; K, V single-rounded)
__device__ __align__(128) __half g_q_hi  [T_TOK * NH * D_QK];
__device__ __align__(128) __half g_q_lo  [T_TOK * NH * D_QK];
__device__ __align__(128) __half g_k_f16 [T_TOK * NH * D_QK];
__device__ __align__(128) __half g_vt_f16[NH * D_V * T_TOK];

// ---------------- helpers ----------------
__device__ __forceinline__ void cp16(void* s, const void* g) {
    unsigned int sa = (unsigned int)__cvta_generic_to_shared(s);
    asm volatile("cp.async.cg.shared.global [%0], [%1], 16;" :: "r"(sa), "l"(g));
}
#define CP_COMMIT() asm volatile("cp.async.commit_group;")
#define CP_WAIT1()  asm volatile("cp.async.wait_group 1;")
#define CP_WAIT0()  asm volatile("cp.async.wait_group 0;")

__device__ __forceinline__ uint32_t smem_u32(const void* p) {
    return (uint32_t)__cvta_generic_to_shared(p);
}
#define LDSM4(r0, r1, r2, r3, a) \
    asm volatile("ldmatrix.sync.aligned.m8n8.x4.shared.b16 {%0,%1,%2,%3}, [%4];" \
        : "=r"(r0), "=r"(r1), "=r"(r2), "=r"(r3) : "r"(a))

__device__ __forceinline__ void mma_f16(float* c,
    uint32_t a0, uint32_t a1, uint32_t a2, uint32_t a3, uint32_t b0, uint32_t b1)
{
    asm volatile(
        "mma.sync.aligned.m16n8k16.row.col.f32.f16.f16.f32 "
        "{%0,%1,%2,%3},{%4,%5,%6,%7},{%8,%9},{%0,%1,%2,%3};"
        : "+f"(c[0]), "+f"(c[1]), "+f"(c[2]), "+f"(c[3])
        : "r"(a0), "r"(a1), "r"(a2), "r"(a3), "r"(b0), "r"(b1));
}

__device__ __forceinline__ void split_f16(float v, __half& h, __half& l) {
    h = __float2half_rn(v);
    l = __float2half_rn(v - __half2float(h));
}
__device__ __forceinline__ uint32_t pack2h(__half a, __half b) {
    return (uint32_t)__half_as_ushort(a) | ((uint32_t)__half_as_ushort(b) << 16);
}

// ---------------- converters ----------------
__global__ __launch_bounds__(256) void convert_hl_f16_kernel(
    const float2* __restrict__ src, uint32_t* __restrict__ hi,
    uint32_t* __restrict__ lo, int n2)
{
    int i = blockIdx.x * 256 + threadIdx.x;
    const int stride = gridDim.x * 256;
    for (; i < n2; i += stride) {
        const float2 v = src[i];
        __half h0, l0, h1, l1;
        split_f16(v.x, h0, l0);
        split_f16(v.y, h1, l1);
        hi[i] = pack2h(h0, h1);
        lo[i] = pack2h(l0, l1);
    }
}

// in fp32 [R][C] -> out single fp16 [C][R] (weights)
__global__ __launch_bounds__(256) void transpose_cvt_f16_kernel(
    const float* __restrict__ in, __half* __restrict__ outp, int R, int C)
{
    __shared__ float t[32][33];
    const int c0 = blockIdx.x * 32, r0 = blockIdx.y * 32;
    const int x = threadIdx.x, y = threadIdx.y;
#pragma unroll
    for (int j = 0; j < 32; j += 8)
        t[y + j][x] = in[(size_t)(r0 + y + j) * C + c0 + x];
    __syncthreads();
#pragma unroll
    for (int j = 0; j < 32; j += 8)
        outp[(size_t)(c0 + y + j) * R + r0 + x] = __float2half_rn(t[x][y + j]);
}

// build K plane (single fp16): k[t][h*192+d]
__global__ __launch_bounds__(256) void build_k_kernel(
    const float* __restrict__ kvbuf, const float* __restrict__ kpe,
    __half* __restrict__ k16)
{
    const int t = blockIdx.x;
    for (int i = threadIdx.x; i < NH * D_QK; i += 256) {
        const int h = i / D_QK, d = i - h * D_QK;
        const float v = (d < 128)
            ? kvbuf[(size_t)t * (NH * 256) + h * 256 + d]
            : kpe[(size_t)t * D_ROPE + (d - 128)];
        k16[(size_t)t * (NH * D_QK) + i] = __float2half_rn(v);
    }
}

// build VT plane (single fp16): vt[h][d][t]
__global__ __launch_bounds__(256) void build_vt_kernel(
    const float* __restrict__ kvbuf, __half* __restrict__ vt16)
{
    __shared__ float tile[32][33];
    const int h = blockIdx.z;
    const int d0 = blockIdx.y * 32;
    const int t0 = blockIdx.x * 32;
    const int x = threadIdx.x, y = threadIdx.y;
#pragma unroll
    for (int j = 0; j < 32; j += 8)
        tile[y + j][x] = kvbuf[(size_t)(t0 + y + j) * (NH * 256) + h * 256 + 128 + d0 + x];
    __syncthreads();
#pragma unroll
    for (int j = 0; j < 32; j += 8)
        vt16[((size_t)h * D_V + d0 + y + j) * T_TOK + t0 + x] = __float2half_rn(tile[x][y + j]);
}

// ---------------- fp16 2-product GEMM: C = (Ah+Al) @ Bh^T (R10, proven) ----------------
#define PITCH_B 80
#define F_AHI 0
#define F_ALO 20480
#define F_BHI 40960
#define F_STAGE 46080
#define F_SMEM  (2 * F_STAGE)

__global__ __launch_bounds__(256, 2) void gemm_f16(
    const __half* __restrict__ Ah, const __half* __restrict__ Al,
    const __half* __restrict__ Bh,
    float* __restrict__ C, int M, int N, int K)
{
    extern __shared__ __align__(128) char smx[];
    const uint32_t sbase = smem_u32(smx);
    const int tid  = threadIdx.x;
    const int warp = tid >> 5;
    const int lane = tid & 31;
    const int wm   = warp >> 1;
    const int wn   = warp & 1;
    const int row0 = blockIdx.y * 256;
    const int col0 = blockIdx.x * 64;

    float c[16][4];
#pragma unroll
    for (int i = 0; i < 16; i++)
#pragma unroll
        for (int j = 0; j < 4; j++) c[i][j] = 0.f;

    auto fill = [&](int stage, int k0) {
        char* st = smx + stage * F_STAGE;
#pragma unroll
        for (int rep = 0; rep < 4; rep++) {
            const int cch = tid + rep * 256;
            const int r = cch >> 2, q = cch & 3;
            const size_t src = (size_t)(row0 + r) * K + k0 + q * 8;
            cp16(st + F_AHI + r * PITCH_B + q * 16, Ah + src);
            cp16(st + F_ALO + r * PITCH_B + q * 16, Al + src);
        }
        {
            const int r = tid >> 2, q = tid & 3;
            const size_t src = (size_t)(col0 + r) * K + k0 + q * 8;
            cp16(st + F_BHI + r * PITCH_B + q * 16, Bh + src);
        }
    };

    fill(0, 0);
    CP_COMMIT();

    const int nch = K >> 5;
    const int rowL = (lane & 7) + (lane & 8);
    const int kbL  = (lane >> 4) * 16;

    for (int ch = 0; ch < nch; ch++) {
        const int buf = ch & 1;
        if (ch + 1 < nch) {
            fill(buf ^ 1, (ch + 1) * 32);
            CP_COMMIT();
            CP_WAIT1();
        } else {
            CP_WAIT0();
        }
        __syncthreads();

        const uint32_t sAh = sbase + buf * F_STAGE + F_AHI;
        const uint32_t sAl = sbase + buf * F_STAGE + F_ALO;
        const uint32_t sBh = sbase + buf * F_STAGE + F_BHI;

#pragma unroll
        for (int kk = 0; kk < 2; kk++) {
            const int kb = kk * 32 + kbL;
            uint32_t bh[2][4];
#pragma unroll
            for (int j = 0; j < 2; j++) {
                const int rB = (wn * 32 + j * 16 + rowL) * PITCH_B + kb;
                LDSM4(bh[j][0], bh[j][1], bh[j][2], bh[j][3], sBh + rB);
            }
#pragma unroll
            for (int i = 0; i < 4; i++) {
                const int rA = (wm * 64 + i * 16 + rowL) * PITCH_B + kb;
                uint32_t ah0, ah1, ah2, ah3, al0, al1, al2, al3;
                LDSM4(ah0, ah1, ah2, ah3, sAh + rA);
                LDSM4(al0, al1, al2, al3, sAl + rA);
#pragma unroll
                for (int f = 0; f < 4; f++) {
                    const int j = f >> 1, h = f & 1;
                    float* acc = c[i * 4 + f];
                    mma_f16(acc, ah0, ah1, ah2, ah3, bh[j][h], bh[j][h + 2]);
                    mma_f16(acc, al0, al1, al2, al3, bh[j][h], bh[j][h + 2]);
                }
            }
        }
        __syncthreads();
    }

    const int qr = lane >> 2, qc = 2 * (lane & 3);
#pragma unroll
    for (int i = 0; i < 4; i++) {
#pragma unroll
        for (int f = 0; f < 4; f++) {
            const int r   = row0 + wm * 64 + i * 16 + qr;
            const int col = col0 + wn * 32 + f * 8 + qc;
            *(float2*)(C + (size_t)r * N + col)       = make_float2(c[i * 4 + f][0], c[i * 4 + f][1]);
            *(float2*)(C + (size_t)(r + 8) * N + col) = make_float2(c[i * 4 + f][2], c[i * 4 + f][3]);
        }
    }
}

// ---------------- RMSNorm -> fp16 hi/lo ----------------
__global__ __launch_bounds__(256) void rmsnorm_kernel(
    const float* __restrict__ in, int ld, int off, int width,
    const float* __restrict__ gamma,
    __half* __restrict__ ohi, __half* __restrict__ olo)
{
    const int row = blockIdx.x;
    const float* x = in + (size_t)row * ld + off;
    float ss = 0.f;
    for (int i = threadIdx.x; i < width; i += 256) {
        float v = x[i];
        ss += v * v;
    }
#pragma unroll
    for (int o = 16; o; o >>= 1) ss += __shfl_xor_sync(0xffffffffu, ss, o);
    __shared__ float warp_s[8];
    __shared__ float s_inv;
    if ((threadIdx.x & 31) == 0) warp_s[threadIdx.x >> 5] = ss;
    __syncthreads();
    if (threadIdx.x == 0) {
        float t = 0.f;
#pragma unroll
        for (int i = 0; i < 8; i++) t += warp_s[i];
        s_inv = rsqrtf(t / (float)width + 1e-6f);
    }
    __syncthreads();
    const float inv = s_inv;
    for (int i = threadIdx.x; i < width; i += 256) {
        const float v = x[i] * inv * gamma[i];
        __half h, l;
        split_f16(v, h, l);
        ohi[(size_t)row * width + i] = h;
        olo[(size_t)row * width + i] = l;
    }
}

// ---------------- RoPE (fp32) ----------------
__global__ __launch_bounds__(256) void rope_kernel(
    float* __restrict__ q, const float* __restrict__ qkv_a,
    float* __restrict__ kpe, const int* __restrict__ positions)
{
    const int t = blockIdx.x;
    const float pos = (float)positions[t];
    for (int i = threadIdx.x; i < NH * 32 + 32; i += 256) {
        if (i < NH * 32) {
            const int h = i >> 5, p = i & 31;
            const float inv = powf(10000.0f, -(float)p / 32.0f);
            float s, c;
            sincosf(pos * inv, &s, &c);
            float* base = q + (size_t)t * (NH * D_QK) + h * D_QK + D_NOPE;
            const float x1 = base[2 * p], x2 = base[2 * p + 1];
            base[2 * p]     = x1 * c - x2 * s;
            base[2 * p + 1] = x1 * s + x2 * c;
        } else {
            const int p = i - NH * 32;
            const float inv = powf(10000.0f, -(float)p / 32.0f);
            float s, c;
            sincosf(pos * inv, &s, &c);
            const float* src = qkv_a + (size_t)t * QKV_A_N + (Q_LORA + KV_LORA);
            const float x1 = src[2 * p], x2 = src[2 * p + 1];
            kpe[(size_t)t * D_ROPE + 2 * p]     = x1 * c - x2 * s;
            kpe[(size_t)t * D_ROPE + 2 * p + 1] = x1 * s + x2 * c;
        }
    }
}

// ---------------- fp16 2-product causal flash attention ----------------
// Q hi/lo (near-exact), K single fp16, V single fp16, P hi/lo.
#define SQH 0
#define SQL 25600
#define SK  51200
#define SV  76800
#define SPH 95232
#define SPL 104448
#define SSTAT 113664
#define ATT_SMEM (SSTAT + 1792)

__global__ __launch_bounds__(256, 1) void attn_f16_kernel(
    const __half* __restrict__ qh, const __half* __restrict__ ql,
    const __half* __restrict__ k16, const __half* __restrict__ vt16,
    uint32_t* __restrict__ ohi, uint32_t* __restrict__ olo)
{
    extern __shared__ __align__(128) char sma[];
    const uint32_t sb = smem_u32(sma);
    float* sWmax  = (float*)(sma + SSTAT);
    float* sWsum  = sWmax + 128;
    float* sM     = sWsum + 128;
    float* sL     = sM + 64;
    float* sScale = sL + 64;

    const int h    = blockIdx.y;
    const int qt   = (int)gridDim.x - 1 - (int)blockIdx.x;   // longest-first
    const int t0   = qt * 64;
    const int tid  = threadIdx.x;
    const int w    = tid >> 5;
    const int lane = tid & 31;
    const int g    = lane >> 2;
    const int t    = lane & 3;
    const int mrow = (w & 3) * 16;
    const int nhalf = w >> 2;
    const int r0 = mrow + g, r1 = r0 + 8;

    // Q tile (once)
    for (int i = tid; i < 1536; i += 256) {
        const int r = i / 24, c = i - r * 24;
        const size_t src = (size_t)(t0 + r) * (NH * D_QK) + h * D_QK + c * 8;
        cp16(sma + SQH + r * 400 + c * 16, qh + src);
        cp16(sma + SQL + r * 400 + c * 16, ql + src);
    }
    CP_COMMIT();
    if (tid < 64) { sM[tid] = -1e30f; sL[tid] = 0.f; }

    float o[8][4];
#pragma unroll
    for (int i = 0; i < 8; i++)
#pragma unroll
        for (int j = 0; j < 4; j++) o[i][j] = 0.f;

    const int rowL = (lane & 7) + (lane & 8);
    const int kbL  = (lane >> 4) * 16;

    for (int kt = 0; kt <= qt; kt++) {
        const int k0 = kt * 64;
        __syncthreads();
        for (int i = tid; i < 1536; i += 256) {
            const int r = i / 24, c = i - r * 24;
            const size_t src = (size_t)(k0 + r) * (NH * D_QK) + h * D_QK + c * 8;
            cp16(sma + SK + r * 400 + c * 16, k16 + src);
        }
        for (int i = tid; i < 1024; i += 256) {
            const int r = i >> 3, c = i & 7;
            const size_t src = ((size_t)h * D_V + r) * T_TOK + k0 + c * 8;
            cp16(sma + SV + r * 144 + c * 16, vt16 + src);
        }
        CP_COMMIT();
        CP_WAIT0();
        __syncthreads();

        // ---- S = (Qh+Ql) @ K^T ----
        float s[4][4];
#pragma unroll
        for (int nt = 0; nt < 4; nt++)
#pragma unroll
            for (int j = 0; j < 4; j++) s[nt][j] = 0.f;

#pragma unroll 3
        for (int ks = 0; ks < 12; ks++) {
            const int kb = ks * 32 + kbL;
            uint32_t ah0, ah1, ah2, ah3, al0, al1, al2, al3;
            const int rA = (mrow + rowL) * 400 + kb;
            LDSM4(ah0, ah1, ah2, ah3, sb + SQH + rA);
            LDSM4(al0, al1, al2, al3, sb + SQL + rA);
            uint32_t bh[2][4];
#pragma unroll
            for (int j = 0; j < 2; j++) {
                const int rB = (nhalf * 32 + j * 16 + rowL) * 400 + kb;
                LDSM4(bh[j][0], bh[j][1], bh[j][2], bh[j][3], sb + SK + rB);
            }
#pragma unroll
            for (int nt = 0; nt < 4; nt++) {
                const int j = nt >> 1, hh = nt & 1;
                mma_f16(s[nt], ah0, ah1, ah2, ah3, bh[j][hh], bh[j][hh + 2]);
                mma_f16(s[nt], al0, al1, al2, al3, bh[j][hh], bh[j][hh + 2]);
            }
        }

        const int rg0 = t0 + r0, rg1 = t0 + r1;
#pragma unroll
        for (int nt = 0; nt < 4; nt++) {
            const int cg = k0 + nhalf * 32 + nt * 8 + 2 * t;
            s[nt][0] = (rg0 >= cg)     ? s[nt][0] * SCALING : -1e30f;
            s[nt][1] = (rg0 >= cg + 1) ? s[nt][1] * SCALING : -1e30f;
            s[nt][2] = (rg1 >= cg)     ? s[nt][2] * SCALING : -1e30f;
            s[nt][3] = (rg1 >= cg + 1) ? s[nt][3] * SCALING : -1e30f;
        }

        float mx0 = -1e30f, mx1 = -1e30f;
#pragma unroll
        for (int nt = 0; nt < 4; nt++) {
            mx0 = fmaxf(mx0, fmaxf(s[nt][0], s[nt][1]));
            mx1 = fmaxf(mx1, fmaxf(s[nt][2], s[nt][3]));
        }
        mx0 = fmaxf(mx0, __shfl_xor_sync(0xffffffffu, mx0, 1));
        mx0 = fmaxf(mx0, __shfl_xor_sync(0xffffffffu, mx0, 2));
        mx1 = fmaxf(mx1, __shfl_xor_sync(0xffffffffu, mx1, 1));
        mx1 = fmaxf(mx1, __shfl_xor_sync(0xffffffffu, mx1, 2));
        if (t == 0) { sWmax[nhalf * 64 + r0] = mx0; sWmax[nhalf * 64 + r1] = mx1; }
        __syncthreads();

        const float mn0 = fmaxf(sM[r0], fmaxf(sWmax[r0], sWmax[64 + r0]));
        const float mn1 = fmaxf(sM[r1], fmaxf(sWmax[r1], sWmax[64 + r1]));

        float sum0 = 0.f, sum1 = 0.f;
#pragma unroll
        for (int nt = 0; nt < 4; nt++) {
            s[nt][0] = __expf(s[nt][0] - mn0);
            s[nt][1] = __expf(s[nt][1] - mn0);
            s[nt][2] = __expf(s[nt][2] - mn1);
            s[nt][3] = __expf(s[nt][3] - mn1);
            sum0 += s[nt][0] + s[nt][1];
            sum1 += s[nt][2] + s[nt][3];
            const int coll = nhalf * 32 + nt * 8 + 2 * t;
            __half h0, l0, h1, l1;
            split_f16(s[nt][0], h0, l0); split_f16(s[nt][1], h1, l1);
            *(uint32_t*)(sma + SPH + r0 * 144 + coll * 2) = pack2h(h0, h1);
            *(uint32_t*)(sma + SPL + r0 * 144 + coll * 2) = pack2h(l0, l1);
            split_f16(s[nt][2], h0, l0); split_f16(s[nt][3], h1, l1);
            *(uint32_t*)(sma + SPH + r1 * 144 + coll * 2) = pack2h(h0, h1);
            *(uint32_t*)(sma + SPL + r1 * 144 + coll * 2) = pack2h(l0, l1);
        }
        sum0 += __shfl_xor_sync(0xffffffffu, sum0, 1);
        sum0 += __shfl_xor_sync(0xffffffffu, sum0, 2);
        sum1 += __shfl_xor_sync(0xffffffffu, sum1, 1);
        sum1 += __shfl_xor_sync(0xffffffffu, sum1, 2);
        if (t == 0) { sWsum[nhalf * 64 + r0] = sum0; sWsum[nhalf * 64 + r1] = sum1; }
        __syncthreads();

        if (tid < 64) {
            const float mo = sM[tid];
            const float mn = fmaxf(mo, fmaxf(sWmax[tid], sWmax[64 + tid]));
            const float sc = __expf(mo - mn);
            sM[tid] = mn;
            sL[tid] = sL[tid] * sc + sWsum[tid] + sWsum[64 + tid];
            sScale[tid] = sc;
        }
        __syncthreads();

        const float sc0 = sScale[r0], sc1 = sScale[r1];
#pragma unroll
        for (int nt = 0; nt < 8; nt++) {
            o[nt][0] *= sc0; o[nt][1] *= sc0;
            o[nt][2] *= sc1; o[nt][3] *= sc1;
        }

        // ---- O += (Ph+Pl) @ V ----
#pragma unroll
        for (int ks = 0; ks < 4; ks++) {
            const int kb = ks * 32 + kbL;
            uint32_t ph0, ph1, ph2, ph3, pl0, pl1, pl2, pl3;
            const int rP = (mrow + rowL) * 144 + kb;
            LDSM4(ph0, ph1, ph2, ph3, sb + SPH + rP);
            LDSM4(pl0, pl1, pl2, pl3, sb + SPL + rP);
#pragma unroll
            for (int j2 = 0; j2 < 4; j2++) {
                const int rV = (nhalf * 64 + j2 * 16 + rowL) * 144 + kb;
                uint32_t vh[4];
                LDSM4(vh[0], vh[1], vh[2], vh[3], sb + SV + rV);
#pragma unroll
                for (int hh = 0; hh < 2; hh++) {
                    float* acc = o[j2 * 2 + hh];
                    mma_f16(acc, ph0, ph1, ph2, ph3, vh[hh], vh[hh + 2]);
                    mma_f16(acc, pl0, pl1, pl2, pl3, vh[hh], vh[hh + 2]);
                }
            }
        }
    }

    // epilogue -> fp16 hi/lo planes (A operand of the w_o GEMM)
    const float il0 = 1.f / sL[r0];
    const float il1 = 1.f / sL[r1];
#pragma unroll
    for (int nt = 0; nt < 8; nt++) {
        const int col = h * D_V + nhalf * 64 + nt * 8 + 2 * t;
        const float v00 = o[nt][0] * il0, v01 = o[nt][1] * il0;
        const float v10 = o[nt][2] * il1, v11 = o[nt][3] * il1;
        __half h0, l0, h1, l1;
        split_f16(v00, h0, l0); split_f16(v01, h1, l1);
        ohi[((size_t)(t0 + r0) * (NH * D_V) + col) >> 1] = pack2h(h0, h1);
        olo[((size_t)(t0 + r0) * (NH * D_V) + col) >> 1] = pack2h(l0, l1);
        split_f16(v10, h0, l0); split_f16(v11, h1, l1);
        ohi[((size_t)(t0 + r1) * (NH * D_V) + col) >> 1] = pack2h(h0, h1);
        olo[((size_t)(t0 + r1) * (NH * D_V) + col) >> 1] = pack2h(l0, l1);
    }
}

// ---------------- launch ----------------
extern "C" void kernel_launch(void* const* d_in, const int* in_sizes, int n_in,
                              void* d_out, int out_size)
{
    const float* hidden    = (const float*)d_in[0];
    const int*   positions = (const int*)  d_in[1];
    const float* w_qkv_a   = (const float*)d_in[2];
    const float* gamma_q   = (const float*)d_in[3];
    const float* w_q_b     = (const float*)d_in[4];
    const float* gamma_kv  = (const float*)d_in[5];
    const float* w_kv_b    = (const float*)d_in[6];
    const float* w_o       = (const float*)d_in[7];
    float* out = (float*)d_out;

    float *qkv_a, *qbuf, *kvbuf, *kpe;
    __half *hid_h, *hid_l, *qn_h, *qn_l, *kvn_h, *kvn_l, *at_h, *at_l;
    __half *wa, *wqb, *wkvb, *wo;
    __half *q_h, *q_l, *k16, *vt16;
    cudaGetSymbolAddress((void**)&qkv_a, g_qkv_a);
    cudaGetSymbolAddress((void**)&qbuf,  g_qbuf);
    cudaGetSymbolAddress((void**)&kvbuf, g_kvbuf);
    cudaGetSymbolAddress((void**)&kpe,   g_kpe);
    cudaGetSymbolAddress((void**)&hid_h, g_hid_hi);  cudaGetSymbolAddress((void**)&hid_l, g_hid_lo);
    cudaGetSymbolAddress((void**)&qn_h,  g_qn_hi);   cudaGetSymbolAddress((void**)&qn_l,  g_qn_lo);
    cudaGetSymbolAddress((void**)&kvn_h, g_kvn_hi);  cudaGetSymbolAddress((void**)&kvn_l, g_kvn_lo);
    cudaGetSymbolAddress((void**)&at_h,  g_attn_hi); cudaGetSymbolAddress((void**)&at_l,  g_attn_lo);
    cudaGetSymbolAddress((void**)&wa,    g_wa_f16);
    cudaGetSymbolAddress((void**)&wqb,   g_wqb_f16);
    cudaGetSymbolAddress((void**)&wkvb,  g_wkvb_f16);
    cudaGetSymbolAddress((void**)&wo,    g_wo_f16);
    cudaGetSymbolAddress((void**)&q_h,   g_q_hi);    cudaGetSymbolAddress((void**)&q_l,   g_q_lo);
    cudaGetSymbolAddress((void**)&k16,   g_k_f16);
    cudaGetSymbolAddress((void**)&vt16,  g_vt_f16);

    cudaFuncSetAttribute(gemm_f16, cudaFuncAttributeMaxDynamicSharedMemorySize, F_SMEM);
    cudaFuncSetAttribute(attn_f16_kernel, cudaFuncAttributeMaxDynamicSharedMemorySize, ATT_SMEM);

    // 0) one-time conversions
    convert_hl_f16_kernel<<<1184, 256>>>((const float2*)hidden,
        (uint32_t*)hid_h, (uint32_t*)hid_l, T_TOK * HID / 2);
    transpose_cvt_f16_kernel<<<dim3(QKV_A_N / 32, HID / 32),      dim3(32, 8)>>>(w_qkv_a, wa,   HID,      QKV_A_N);
    transpose_cvt_f16_kernel<<<dim3((NH*D_QK) / 32, Q_LORA / 32), dim3(32, 8)>>>(w_q_b,   wqb,  Q_LORA,   NH * D_QK);
    transpose_cvt_f16_kernel<<<dim3((NH*256) / 32, KV_LORA / 32), dim3(32, 8)>>>(w_kv_b,  wkvb, KV_LORA,  NH * 256);
    transpose_cvt_f16_kernel<<<dim3(HID / 32, (NH*D_V) / 32),     dim3(32, 8)>>>(w_o,     wo,   NH * D_V, HID);

    // 1) qkv_a = hidden @ w_qkv_a
    gemm_f16<<<dim3(QKV_A_N / 64, T_TOK / 256), 256, F_SMEM>>>(
        hid_h, hid_l, wa, qkv_a, T_TOK, QKV_A_N, HID);

    // 2) RMSNorm -> fp16 hi/lo
    rmsnorm_kernel<<<T_TOK, 256>>>(qkv_a, QKV_A_N, 0,      Q_LORA,  gamma_q,  qn_h,  qn_l);
    rmsnorm_kernel<<<T_TOK, 256>>>(qkv_a, QKV_A_N, Q_LORA, KV_LORA, gamma_kv, kvn_h, kvn_l);

    // 3) q = qn @ w_q_b
    gemm_f16<<<dim3((NH * D_QK) / 64, T_TOK / 256), 256, F_SMEM>>>(
        qn_h, qn_l, wqb, qbuf, T_TOK, NH * D_QK, Q_LORA);

    // 4) kv = kvn @ w_kv_b
    gemm_f16<<<dim3((NH * 256) / 64, T_TOK / 256), 256, F_SMEM>>>(
        kvn_h, kvn_l, wkvb, kvbuf, T_TOK, NH * 256, KV_LORA);

    // 5) RoPE
    rope_kernel<<<T_TOK, 256>>>(qbuf, qkv_a, kpe, positions);

    // 6) attention operand planes (fp16)
    convert_hl_f16_kernel<<<1184, 256>>>((const float2*)qbuf,
        (uint32_t*)q_h, (uint32_t*)q_l, T_TOK * NH * D_QK / 2);
    build_k_kernel<<<T_TOK, 256>>>(kvbuf, kpe, k16);
    build_vt_kernel<<<dim3(T_TOK / 32, D_V / 32, NH), dim3(32, 8)>>>(kvbuf, vt16);

    // 7) attention -> fp16 hi/lo planes
    attn_f16_kernel<<<dim3(T_TOK / 64, NH), 256, ATT_SMEM>>>(
        q_h, q_l, k16, vt16, (uint32_t*)at_h, (uint32_t*)at_l);

    // 8) out = attn @ w_o
    gemm_f16<<<dim3(HID / 64, T_TOK / 256), 256, F_SMEM>>>(
        at_h, at_l, wo, out, T_TOK, HID, NH * D_V);
}

// round 12
// speedup vs baseline: 1.4358x; 1.0385x over previous
#include <cuda_runtime.h>
#include <cuda_fp16.h>
#include <math.h>
#include <stdint.h>

// ---------------- problem constants ----------------
#define T_TOK   2048
#define HID     2048
#define NH      16
#define D_NOPE  128
#define D_ROPE  64
#define D_QK    192
#define D_V     128
#define Q_LORA  1536
#define KV_LORA 512
#define QKV_A_N 2112
#define SCALING 0.07216878364870322f   // 192^-0.5

// ---------------- scratch ----------------
__device__ __align__(128) float g_qkv_a [T_TOK * QKV_A_N];
__device__ __align__(128) float g_kvbuf [T_TOK * NH * 256];
__device__ __align__(128) float g_kpe   [T_TOK * D_ROPE];
// fp16 planes
__device__ __align__(128) __half g_hid_hi [T_TOK * HID];
__device__ __align__(128) __half g_hid_lo [T_TOK * HID];
__device__ __align__(128) __half g_qn_hi  [T_TOK * Q_LORA];
__device__ __align__(128) __half g_qn_lo  [T_TOK * Q_LORA];
__device__ __align__(128) __half g_kvn_hi [T_TOK * KV_LORA];
__device__ __align__(128) __half g_kvn_lo [T_TOK * KV_LORA];
__device__ __align__(128) __half g_attn_hi[T_TOK * NH * D_V];
__device__ __align__(128) __half g_attn_lo[T_TOK * NH * D_V];
__device__ __align__(128) __half g_wa_f16  [QKV_A_N * HID];
__device__ __align__(128) __half g_wqb_f16 [NH * D_QK * Q_LORA];
__device__ __align__(128) __half g_wkvb_f16[NH * 256 * KV_LORA];
__device__ __align__(128) __half g_wo_f16  [HID * NH * D_V];
// attention operand planes (Q hi/lo; K, V single-rounded)
__device__ __align__(128) __half g_q_hi  [T_TOK * NH * D_QK];
__device__ __align__(128) __half g_q_lo  [T_TOK * NH * D_QK];
__device__ __align__(128) __half g_k_f16 [T_TOK * NH * D_QK];
__device__ __align__(128) __half g_vt_f16[NH * D_V * T_TOK];

// ---------------- helpers ----------------
__device__ __forceinline__ void cp16(void* s, const void* g) {
    unsigned int sa = (unsigned int)__cvta_generic_to_shared(s);
    asm volatile("cp.async.cg.shared.global [%0], [%1], 16;" :: "r"(sa), "l"(g));
}
#define CP_COMMIT() asm volatile("cp.async.commit_group;")
#define CP_WAIT1()  asm volatile("cp.async.wait_group 1;")
#define CP_WAIT0()  asm volatile("cp.async.wait_group 0;")

__device__ __forceinline__ uint32_t smem_u32(const void* p) {
    return (uint32_t)__cvta_generic_to_shared(p);
}
#define LDSM4(r0, r1, r2, r3, a) \
    asm volatile("ldmatrix.sync.aligned.m8n8.x4.shared.b16 {%0,%1,%2,%3}, [%4];" \
        : "=r"(r0), "=r"(r1), "=r"(r2), "=r"(r3) : "r"(a))

__device__ __forceinline__ void mma_f16(float* c,
    uint32_t a0, uint32_t a1, uint32_t a2, uint32_t a3, uint32_t b0, uint32_t b1)
{
    asm volatile(
        "mma.sync.aligned.m16n8k16.row.col.f32.f16.f16.f32 "
        "{%0,%1,%2,%3},{%4,%5,%6,%7},{%8,%9},{%0,%1,%2,%3};"
        : "+f"(c[0]), "+f"(c[1]), "+f"(c[2]), "+f"(c[3])
        : "r"(a0), "r"(a1), "r"(a2), "r"(a3), "r"(b0), "r"(b1));
}

__device__ __forceinline__ void split_f16(float v, __half& h, __half& l) {
    h = __float2half_rn(v);
    l = __float2half_rn(v - __half2float(h));
}
__device__ __forceinline__ uint32_t pack2h(__half a, __half b) {
    return (uint32_t)__half_as_ushort(a) | ((uint32_t)__half_as_ushort(b) << 16);
}

// ---------------- converters ----------------
__global__ __launch_bounds__(256) void convert_hl_f16_kernel(
    const float2* __restrict__ src, uint32_t* __restrict__ hi,
    uint32_t* __restrict__ lo, int n2)
{
    int i = blockIdx.x * 256 + threadIdx.x;
    const int stride = gridDim.x * 256;
    for (; i < n2; i += stride) {
        const float2 v = src[i];
        __half h0, l0, h1, l1;
        split_f16(v.x, h0, l0);
        split_f16(v.y, h1, l1);
        hi[i] = pack2h(h0, h1);
        lo[i] = pack2h(l0, l1);
    }
}

// in fp32 [R][C] -> out single fp16 [C][R] (weights)
__global__ __launch_bounds__(256) void transpose_cvt_f16_kernel(
    const float* __restrict__ in, __half* __restrict__ outp, int R, int C)
{
    __shared__ float t[32][33];
    const int c0 = blockIdx.x * 32, r0 = blockIdx.y * 32;
    const int x = threadIdx.x, y = threadIdx.y;
#pragma unroll
    for (int j = 0; j < 32; j += 8)
        t[y + j][x] = in[(size_t)(r0 + y + j) * C + c0 + x];
    __syncthreads();
#pragma unroll
    for (int j = 0; j < 32; j += 8)
        outp[(size_t)(c0 + y + j) * R + r0 + x] = __float2half_rn(t[x][y + j]);
}

// build K plane (single fp16)
__global__ __launch_bounds__(256) void build_k_kernel(
    const float* __restrict__ kvbuf, const float* __restrict__ kpe,
    __half* __restrict__ k16)
{
    const int t = blockIdx.x;
    for (int i = threadIdx.x; i < NH * D_QK; i += 256) {
        const int h = i / D_QK, d = i - h * D_QK;
        const float v = (d < 128)
            ? kvbuf[(size_t)t * (NH * 256) + h * 256 + d]
            : kpe[(size_t)t * D_ROPE + (d - 128)];
        k16[(size_t)t * (NH * D_QK) + i] = __float2half_rn(v);
    }
}

// build VT plane (single fp16): vt[h][d][t]
__global__ __launch_bounds__(256) void build_vt_kernel(
    const float* __restrict__ kvbuf, __half* __restrict__ vt16)
{
    __shared__ float tile[32][33];
    const int h = blockIdx.z;
    const int d0 = blockIdx.y * 32;
    const int t0 = blockIdx.x * 32;
    const int x = threadIdx.x, y = threadIdx.y;
#pragma unroll
    for (int j = 0; j < 32; j += 8)
        tile[y + j][x] = kvbuf[(size_t)(t0 + y + j) * (NH * 256) + h * 256 + 128 + d0 + x];
    __syncthreads();
#pragma unroll
    for (int j = 0; j < 32; j += 8)
        vt16[((size_t)h * D_V + d0 + y + j) * T_TOK + t0 + x] = __float2half_rn(tile[x][y + j]);
}

// ---------------- fp16 2-product GEMM ----------------
// out_hl == 0: write fp32 C. out_hl == 1: write fp16 hi/lo planes (Chi/Clo).
#define PITCH_B 80
#define F_AHI 0
#define F_ALO 20480
#define F_BHI 40960
#define F_STAGE 46080
#define F_SMEM  (2 * F_STAGE)

__global__ __launch_bounds__(256, 2) void gemm_f16(
    const __half* __restrict__ Ah, const __half* __restrict__ Al,
    const __half* __restrict__ Bh,
    float* __restrict__ C, uint32_t* __restrict__ Chi, uint32_t* __restrict__ Clo,
    int out_hl, int M, int N, int K)
{
    extern __shared__ __align__(128) char smx[];
    const uint32_t sbase = smem_u32(smx);
    const int tid  = threadIdx.x;
    const int warp = tid >> 5;
    const int lane = tid & 31;
    const int wm   = warp >> 1;
    const int wn   = warp & 1;
    const int row0 = blockIdx.y * 256;
    const int col0 = blockIdx.x * 64;

    float c[16][4];
#pragma unroll
    for (int i = 0; i < 16; i++)
#pragma unroll
        for (int j = 0; j < 4; j++) c[i][j] = 0.f;

    auto fill = [&](int stage, int k0) {
        char* st = smx + stage * F_STAGE;
#pragma unroll
        for (int rep = 0; rep < 4; rep++) {
            const int cch = tid + rep * 256;
            const int r = cch >> 2, q = cch & 3;
            const size_t src = (size_t)(row0 + r) * K + k0 + q * 8;
            cp16(st + F_AHI + r * PITCH_B + q * 16, Ah + src);
            cp16(st + F_ALO + r * PITCH_B + q * 16, Al + src);
        }
        {
            const int r = tid >> 2, q = tid & 3;
            const size_t src = (size_t)(col0 + r) * K + k0 + q * 8;
            cp16(st + F_BHI + r * PITCH_B + q * 16, Bh + src);
        }
    };

    fill(0, 0);
    CP_COMMIT();

    const int nch = K >> 5;
    const int rowL = (lane & 7) + (lane & 8);
    const int kbL  = (lane >> 4) * 16;

    for (int ch = 0; ch < nch; ch++) {
        const int buf = ch & 1;
        if (ch + 1 < nch) {
            fill(buf ^ 1, (ch + 1) * 32);
            CP_COMMIT();
            CP_WAIT1();
        } else {
            CP_WAIT0();
        }
        __syncthreads();

        const uint32_t sAh = sbase + buf * F_STAGE + F_AHI;
        const uint32_t sAl = sbase + buf * F_STAGE + F_ALO;
        const uint32_t sBh = sbase + buf * F_STAGE + F_BHI;

#pragma unroll
        for (int kk = 0; kk < 2; kk++) {
            const int kb = kk * 32 + kbL;
            uint32_t bh[2][4];
#pragma unroll
            for (int j = 0; j < 2; j++) {
                const int rB = (wn * 32 + j * 16 + rowL) * PITCH_B + kb;
                LDSM4(bh[j][0], bh[j][1], bh[j][2], bh[j][3], sBh + rB);
            }
#pragma unroll
            for (int i = 0; i < 4; i++) {
                const int rA = (wm * 64 + i * 16 + rowL) * PITCH_B + kb;
                uint32_t ah0, ah1, ah2, ah3, al0, al1, al2, al3;
                LDSM4(ah0, ah1, ah2, ah3, sAh + rA);
                LDSM4(al0, al1, al2, al3, sAl + rA);
#pragma unroll
                for (int f = 0; f < 4; f++) {
                    const int j = f >> 1, h = f & 1;
                    float* acc = c[i * 4 + f];
                    mma_f16(acc, ah0, ah1, ah2, ah3, bh[j][h], bh[j][h + 2]);
                    mma_f16(acc, al0, al1, al2, al3, bh[j][h], bh[j][h + 2]);
                }
            }
        }
        __syncthreads();
    }

    const int qr = lane >> 2, qc = 2 * (lane & 3);
    if (out_hl) {
#pragma unroll
        for (int i = 0; i < 4; i++) {
#pragma unroll
            for (int f = 0; f < 4; f++) {
                const int r   = row0 + wm * 64 + i * 16 + qr;
                const int col = col0 + wn * 32 + f * 8 + qc;
                __half h0, l0, h1, l1;
                split_f16(c[i * 4 + f][0], h0, l0);
                split_f16(c[i * 4 + f][1], h1, l1);
                Chi[((size_t)r * N + col) >> 1] = pack2h(h0, h1);
                Clo[((size_t)r * N + col) >> 1] = pack2h(l0, l1);
                split_f16(c[i * 4 + f][2], h0, l0);
                split_f16(c[i * 4 + f][3], h1, l1);
                Chi[((size_t)(r + 8) * N + col) >> 1] = pack2h(h0, h1);
                Clo[((size_t)(r + 8) * N + col) >> 1] = pack2h(l0, l1);
            }
        }
    } else {
#pragma unroll
        for (int i = 0; i < 4; i++) {
#pragma unroll
            for (int f = 0; f < 4; f++) {
                const int r   = row0 + wm * 64 + i * 16 + qr;
                const int col = col0 + wn * 32 + f * 8 + qc;
                *(float2*)(C + (size_t)r * N + col)       = make_float2(c[i * 4 + f][0], c[i * 4 + f][1]);
                *(float2*)(C + (size_t)(r + 8) * N + col) = make_float2(c[i * 4 + f][2], c[i * 4 + f][3]);
            }
        }
    }
}

// ---------------- RMSNorm -> fp16 hi/lo ----------------
__global__ __launch_bounds__(256) void rmsnorm_kernel(
    const float* __restrict__ in, int ld, int off, int width,
    const float* __restrict__ gamma,
    __half* __restrict__ ohi, __half* __restrict__ olo)
{
    const int row = blockIdx.x;
    const float* x = in + (size_t)row * ld + off;
    float ss = 0.f;
    for (int i = threadIdx.x; i < width; i += 256) {
        float v = x[i];
        ss += v * v;
    }
#pragma unroll
    for (int o = 16; o; o >>= 1) ss += __shfl_xor_sync(0xffffffffu, ss, o);
    __shared__ float warp_s[8];
    __shared__ float s_inv;
    if ((threadIdx.x & 31) == 0) warp_s[threadIdx.x >> 5] = ss;
    __syncthreads();
    if (threadIdx.x == 0) {
        float t = 0.f;
#pragma unroll
        for (int i = 0; i < 8; i++) t += warp_s[i];
        s_inv = rsqrtf(t / (float)width + 1e-6f);
    }
    __syncthreads();
    const float inv = s_inv;
    for (int i = threadIdx.x; i < width; i += 256) {
        const float v = x[i] * inv * gamma[i];
        __half h, l;
        split_f16(v, h, l);
        ohi[(size_t)row * width + i] = h;
        olo[(size_t)row * width + i] = l;
    }
}

// ---------------- RoPE on fp16 hi/lo Q planes + kpe from fp32 ----------------
__global__ __launch_bounds__(256) void rope_hl_kernel(
    uint32_t* __restrict__ qhi, uint32_t* __restrict__ qlo,
    const float* __restrict__ qkv_a, float* __restrict__ kpe,
    const int* __restrict__ positions)
{
    const int t = blockIdx.x;
    const float pos = (float)positions[t];
    for (int i = threadIdx.x; i < NH * 32 + 32; i += 256) {
        if (i < NH * 32) {
            const int h = i >> 5, p = i & 31;
            const float inv = powf(10000.0f, -(float)p / 32.0f);
            float s, c;
            sincosf(pos * inv, &s, &c);
            const size_t idx = ((size_t)t * (NH * D_QK) + h * D_QK + D_NOPE + 2 * p) >> 1;
            const uint32_t wh = qhi[idx], wl = qlo[idx];
            const float x1 = __half2float(__ushort_as_half((unsigned short)(wh & 0xffff)))
                           + __half2float(__ushort_as_half((unsigned short)(wl & 0xffff)));
            const float x2 = __half2float(__ushort_as_half((unsigned short)(wh >> 16)))
                           + __half2float(__ushort_as_half((unsigned short)(wl >> 16)));
            const float o1 = x1 * c - x2 * s;
            const float o2 = x1 * s + x2 * c;
            __half h0, l0, h1, l1;
            split_f16(o1, h0, l0);
            split_f16(o2, h1, l1);
            qhi[idx] = pack2h(h0, h1);
            qlo[idx] = pack2h(l0, l1);
        } else {
            const int p = i - NH * 32;
            const float inv = powf(10000.0f, -(float)p / 32.0f);
            float s, c;
            sincosf(pos * inv, &s, &c);
            const float* src = qkv_a + (size_t)t * QKV_A_N + (Q_LORA + KV_LORA);
            const float x1 = src[2 * p], x2 = src[2 * p + 1];
            kpe[(size_t)t * D_ROPE + 2 * p]     = x1 * c - x2 * s;
            kpe[(size_t)t * D_ROPE + 2 * p + 1] = x1 * s + x2 * c;
        }
    }
}

// ---------------- fp16 causal flash attention (occ 2) ----------------
// Q hi/lo, K single, V single, P single.
#define SQH 0
#define SQL 25600
#define SK  51200
#define SV  76800
#define SPH 95232
#define SSTAT 104448
#define ATT_SMEM (SSTAT + 1792)   // 106240 B -> 2 CTAs/SM

__global__ __launch_bounds__(256, 2) void attn_f16_kernel(
    const __half* __restrict__ qh, const __half* __restrict__ ql,
    const __half* __restrict__ k16, const __half* __restrict__ vt16,
    uint32_t* __restrict__ ohi, uint32_t* __restrict__ olo)
{
    extern __shared__ __align__(128) char sma[];
    const uint32_t sb = smem_u32(sma);
    float* sWmax  = (float*)(sma + SSTAT);
    float* sWsum  = sWmax + 128;
    float* sM     = sWsum + 128;
    float* sL     = sM + 64;
    float* sScale = sL + 64;

    const int h    = blockIdx.y;
    const int qt   = (int)gridDim.x - 1 - (int)blockIdx.x;   // longest-first
    const int t0   = qt * 64;
    const int tid  = threadIdx.x;
    const int w    = tid >> 5;
    const int lane = tid & 31;
    const int g    = lane >> 2;
    const int t    = lane & 3;
    const int mrow = (w & 3) * 16;
    const int nhalf = w >> 2;
    const int r0 = mrow + g, r1 = r0 + 8;

    // Q tile (once)
    for (int i = tid; i < 1536; i += 256) {
        const int r = i / 24, c = i - r * 24;
        const size_t src = (size_t)(t0 + r) * (NH * D_QK) + h * D_QK + c * 8;
        cp16(sma + SQH + r * 400 + c * 16, qh + src);
        cp16(sma + SQL + r * 400 + c * 16, ql + src);
    }
    CP_COMMIT();
    if (tid < 64) { sM[tid] = -1e30f; sL[tid] = 0.f; }

    float o[8][4];
#pragma unroll
    for (int i = 0; i < 8; i++)
#pragma unroll
        for (int j = 0; j < 4; j++) o[i][j] = 0.f;

    const int rowL = (lane & 7) + (lane & 8);
    const int kbL  = (lane >> 4) * 16;

    for (int kt = 0; kt <= qt; kt++) {
        const int k0 = kt * 64;
        __syncthreads();
        for (int i = tid; i < 1536; i += 256) {
            const int r = i / 24, c = i - r * 24;
            const size_t src = (size_t)(k0 + r) * (NH * D_QK) + h * D_QK + c * 8;
            cp16(sma + SK + r * 400 + c * 16, k16 + src);
        }
        for (int i = tid; i < 1024; i += 256) {
            const int r = i >> 3, c = i & 7;
            const size_t src = ((size_t)h * D_V + r) * T_TOK + k0 + c * 8;
            cp16(sma + SV + r * 144 + c * 16, vt16 + src);
        }
        CP_COMMIT();
        CP_WAIT0();
        __syncthreads();

        // ---- S = (Qh+Ql) @ K^T ----
        float s[4][4];
#pragma unroll
        for (int nt = 0; nt < 4; nt++)
#pragma unroll
            for (int j = 0; j < 4; j++) s[nt][j] = 0.f;

#pragma unroll 3
        for (int ks = 0; ks < 12; ks++) {
            const int kb = ks * 32 + kbL;
            uint32_t ah0, ah1, ah2, ah3, al0, al1, al2, al3;
            const int rA = (mrow + rowL) * 400 + kb;
            LDSM4(ah0, ah1, ah2, ah3, sb + SQH + rA);
            LDSM4(al0, al1, al2, al3, sb + SQL + rA);
            uint32_t bh[2][4];
#pragma unroll
            for (int j = 0; j < 2; j++) {
                const int rB = (nhalf * 32 + j * 16 + rowL) * 400 + kb;
                LDSM4(bh[j][0], bh[j][1], bh[j][2], bh[j][3], sb + SK + rB);
            }
#pragma unroll
            for (int nt = 0; nt < 4; nt++) {
                const int j = nt >> 1, hh = nt & 1;
                mma_f16(s[nt], ah0, ah1, ah2, ah3, bh[j][hh], bh[j][hh + 2]);
                mma_f16(s[nt], al0, al1, al2, al3, bh[j][hh], bh[j][hh + 2]);
            }
        }

        const int rg0 = t0 + r0, rg1 = t0 + r1;
#pragma unroll
        for (int nt = 0; nt < 4; nt++) {
            const int cg = k0 + nhalf * 32 + nt * 8 + 2 * t;
            s[nt][0] = (rg0 >= cg)     ? s[nt][0] * SCALING : -1e30f;
            s[nt][1] = (rg0 >= cg + 1) ? s[nt][1] * SCALING : -1e30f;
            s[nt][2] = (rg1 >= cg)     ? s[nt][2] * SCALING : -1e30f;
            s[nt][3] = (rg1 >= cg + 1) ? s[nt][3] * SCALING : -1e30f;
        }

        float mx0 = -1e30f, mx1 = -1e30f;
#pragma unroll
        for (int nt = 0; nt < 4; nt++) {
            mx0 = fmaxf(mx0, fmaxf(s[nt][0], s[nt][1]));
            mx1 = fmaxf(mx1, fmaxf(s[nt][2], s[nt][3]));
        }
        mx0 = fmaxf(mx0, __shfl_xor_sync(0xffffffffu, mx0, 1));
        mx0 = fmaxf(mx0, __shfl_xor_sync(0xffffffffu, mx0, 2));
        mx1 = fmaxf(mx1, __shfl_xor_sync(0xffffffffu, mx1, 1));
        mx1 = fmaxf(mx1, __shfl_xor_sync(0xffffffffu, mx1, 2));
        if (t == 0) { sWmax[nhalf * 64 + r0] = mx0; sWmax[nhalf * 64 + r1] = mx1; }
        __syncthreads();

        const float mn0 = fmaxf(sM[r0], fmaxf(sWmax[r0], sWmax[64 + r0]));
        const float mn1 = fmaxf(sM[r1], fmaxf(sWmax[r1], sWmax[64 + r1]));

        float sum0 = 0.f, sum1 = 0.f;
#pragma unroll
        for (int nt = 0; nt < 4; nt++) {
            s[nt][0] = __expf(s[nt][0] - mn0);
            s[nt][1] = __expf(s[nt][1] - mn0);
            s[nt][2] = __expf(s[nt][2] - mn1);
            s[nt][3] = __expf(s[nt][3] - mn1);
            sum0 += s[nt][0] + s[nt][1];
            sum1 += s[nt][2] + s[nt][3];
            const int coll = nhalf * 32 + nt * 8 + 2 * t;
            *(uint32_t*)(sma + SPH + r0 * 144 + coll * 2) =
                pack2h(__float2half_rn(s[nt][0]), __float2half_rn(s[nt][1]));
            *(uint32_t*)(sma + SPH + r1 * 144 + coll * 2) =
                pack2h(__float2half_rn(s[nt][2]), __float2half_rn(s[nt][3]));
        }
        sum0 += __shfl_xor_sync(0xffffffffu, sum0, 1);
        sum0 += __shfl_xor_sync(0xffffffffu, sum0, 2);
        sum1 += __shfl_xor_sync(0xffffffffu, sum1, 1);
        sum1 += __shfl_xor_sync(0xffffffffu, sum1, 2);
        if (t == 0) { sWsum[nhalf * 64 + r0] = sum0; sWsum[nhalf * 64 + r1] = sum1; }
        __syncthreads();

        if (tid < 64) {
            const float mo = sM[tid];
            const float mn = fmaxf(mo, fmaxf(sWmax[tid], sWmax[64 + tid]));
            const float sc = __expf(mo - mn);
            sM[tid] = mn;
            sL[tid] = sL[tid] * sc + sWsum[tid] + sWsum[64 + tid];
            sScale[tid] = sc;
        }
        __syncthreads();

        const float sc0 = sScale[r0], sc1 = sScale[r1];
#pragma unroll
        for (int nt = 0; nt < 8; nt++) {
            o[nt][0] *= sc0; o[nt][1] *= sc0;
            o[nt][2] *= sc1; o[nt][3] *= sc1;
        }

        // ---- O += P @ V ----
#pragma unroll
        for (int ks = 0; ks < 4; ks++) {
            const int kb = ks * 32 + kbL;
            uint32_t ph0, ph1, ph2, ph3;
            const int rP = (mrow + rowL) * 144 + kb;
            LDSM4(ph0, ph1, ph2, ph3, sb + SPH + rP);
#pragma unroll
            for (int j2 = 0; j2 < 4; j2++) {
                const int rV = (nhalf * 64 + j2 * 16 + rowL) * 144 + kb;
                uint32_t vh[4];
                LDSM4(vh[0], vh[1], vh[2], vh[3], sb + SV + rV);
#pragma unroll
                for (int hh = 0; hh < 2; hh++)
                    mma_f16(o[j2 * 2 + hh], ph0, ph1, ph2, ph3, vh[hh], vh[hh + 2]);
            }
        }
    }

    // epilogue -> fp16 hi/lo planes
    const float il0 = 1.f / sL[r0];
    const float il1 = 1.f / sL[r1];
#pragma unroll
    for (int nt = 0; nt < 8; nt++) {
        const int col = h * D_V + nhalf * 64 + nt * 8 + 2 * t;
        const float v00 = o[nt][0] * il0, v01 = o[nt][1] * il0;
        const float v10 = o[nt][2] * il1, v11 = o[nt][3] * il1;
        __half h0, l0, h1, l1;
        split_f16(v00, h0, l0); split_f16(v01, h1, l1);
        ohi[((size_t)(t0 + r0) * (NH * D_V) + col) >> 1] = pack2h(h0, h1);
        olo[((size_t)(t0 + r0) * (NH * D_V) + col) >> 1] = pack2h(l0, l1);
        split_f16(v10, h0, l0); split_f16(v11, h1, l1);
        ohi[((size_t)(t0 + r1) * (NH * D_V) + col) >> 1] = pack2h(h0, h1);
        olo[((size_t)(t0 + r1) * (NH * D_V) + col) >> 1] = pack2h(l0, l1);
    }
}

// ---------------- launch ----------------
extern "C" void kernel_launch(void* const* d_in, const int* in_sizes, int n_in,
                              void* d_out, int out_size)
{
    const float* hidden    = (const float*)d_in[0];
    const int*   positions = (const int*)  d_in[1];
    const float* w_qkv_a   = (const float*)d_in[2];
    const float* gamma_q   = (const float*)d_in[3];
    const float* w_q_b     = (const float*)d_in[4];
    const float* gamma_kv  = (const float*)d_in[5];
    const float* w_kv_b    = (const float*)d_in[6];
    const float* w_o       = (const float*)d_in[7];
    float* out = (float*)d_out;

    float *qkv_a, *kvbuf, *kpe;
    __half *hid_h, *hid_l, *qn_h, *qn_l, *kvn_h, *kvn_l, *at_h, *at_l;
    __half *wa, *wqb, *wkvb, *wo;
    __half *q_h, *q_l, *k16, *vt16;
    cudaGetSymbolAddress((void**)&qkv_a, g_qkv_a);
    cudaGetSymbolAddress((void**)&kvbuf, g_kvbuf);
    cudaGetSymbolAddress((void**)&kpe,   g_kpe);
    cudaGetSymbolAddress((void**)&hid_h, g_hid_hi);  cudaGetSymbolAddress((void**)&hid_l, g_hid_lo);
    cudaGetSymbolAddress((void**)&qn_h,  g_qn_hi);   cudaGetSymbolAddress((void**)&qn_l,  g_qn_lo);
    cudaGetSymbolAddress((void**)&kvn_h, g_kvn_hi);  cudaGetSymbolAddress((void**)&kvn_l, g_kvn_lo);
    cudaGetSymbolAddress((void**)&at_h,  g_attn_hi); cudaGetSymbolAddress((void**)&at_l,  g_attn_lo);
    cudaGetSymbolAddress((void**)&wa,    g_wa_f16);
    cudaGetSymbolAddress((void**)&wqb,   g_wqb_f16);
    cudaGetSymbolAddress((void**)&wkvb,  g_wkvb_f16);
    cudaGetSymbolAddress((void**)&wo,    g_wo_f16);
    cudaGetSymbolAddress((void**)&q_h,   g_q_hi);    cudaGetSymbolAddress((void**)&q_l,   g_q_lo);
    cudaGetSymbolAddress((void**)&k16,   g_k_f16);
    cudaGetSymbolAddress((void**)&vt16,  g_vt_f16);

    cudaFuncSetAttribute(gemm_f16, cudaFuncAttributeMaxDynamicSharedMemorySize, F_SMEM);
    cudaFuncSetAttribute(attn_f16_kernel, cudaFuncAttributeMaxDynamicSharedMemorySize, ATT_SMEM);

    // 0) one-time conversions
    convert_hl_f16_kernel<<<1184, 256>>>((const float2*)hidden,
        (uint32_t*)hid_h, (uint32_t*)hid_l, T_TOK * HID / 2);
    transpose_cvt_f16_kernel<<<dim3(QKV_A_N / 32, HID / 32),      dim3(32, 8)>>>(w_qkv_a, wa,   HID,      QKV_A_N);
    transpose_cvt_f16_kernel<<<dim3((NH*D_QK) / 32, Q_LORA / 32), dim3(32, 8)>>>(w_q_b,   wqb,  Q_LORA,   NH * D_QK);
    transpose_cvt_f16_kernel<<<dim3((NH*256) / 32, KV_LORA / 32), dim3(32, 8)>>>(w_kv_b,  wkvb, KV_LORA,  NH * 256);
    transpose_cvt_f16_kernel<<<dim3(HID / 32, (NH*D_V) / 32),     dim3(32, 8)>>>(w_o,     wo,   NH * D_V, HID);

    // 1) qkv_a = hidden @ w_qkv_a   (fp32 out)
    gemm_f16<<<dim3(QKV_A_N / 64, T_TOK / 256), 256, F_SMEM>>>(
        hid_h, hid_l, wa, qkv_a, 0, 0, 0, T_TOK, QKV_A_N, HID);

    // 2) RMSNorm -> fp16 hi/lo
    rmsnorm_kernel<<<T_TOK, 256>>>(qkv_a, QKV_A_N, 0,      Q_LORA,  gamma_q,  qn_h,  qn_l);
    rmsnorm_kernel<<<T_TOK, 256>>>(qkv_a, QKV_A_N, Q_LORA, KV_LORA, gamma_kv, kvn_h, kvn_l);

    // 3) q = qn @ w_q_b  -> directly into fp16 hi/lo Q planes
    gemm_f16<<<dim3((NH * D_QK) / 64, T_TOK / 256), 256, F_SMEM>>>(
        qn_h, qn_l, wqb, 0, (uint32_t*)q_h, (uint32_t*)q_l, 1, T_TOK, NH * D_QK, Q_LORA);

    // 4) kv = kvn @ w_kv_b  (fp32 out)
    gemm_f16<<<dim3((NH * 256) / 64, T_TOK / 256), 256, F_SMEM>>>(
        kvn_h, kvn_l, wkvb, kvbuf, 0, 0, 0, T_TOK, NH * 256, KV_LORA);

    // 5) RoPE in-place on Q hi/lo planes; kpe from qkv_a
    rope_hl_kernel<<<T_TOK, 256>>>((uint32_t*)q_h, (uint32_t*)q_l, qkv_a, kpe, positions);

    // 6) K / VT planes
    build_k_kernel<<<T_TOK, 256>>>(kvbuf, kpe, k16);
    build_vt_kernel<<<dim3(T_TOK / 32, D_V / 32, NH), dim3(32, 8)>>>(kvbuf, vt16);

    // 7) attention -> fp16 hi/lo planes
    attn_f16_kernel<<<dim3(T_TOK / 64, NH), 256, ATT_SMEM>>>(
        q_h, q_l, k16, vt16, (uint32_t*)at_h, (uint32_t*)at_l);

    // 8) out = attn @ w_o  (fp32 out)
    gemm_f16<<<dim3(HID / 64, T_TOK / 256), 256, F_SMEM>>>(
        at_h, at_l, wo, out, 0, 0, 0, T_TOK, HID, NH * D_V);
}

// round 14
// speedup vs baseline: 1.5422x; 1.0742x over previous
#include <cuda_runtime.h>
#include <cuda_fp16.h>
#include <math.h>
#include <stdint.h>

// ---------------- problem constants ----------------
#define T_TOK   2048
#define HID     2048
#define NH      16
#define D_NOPE  128
#define D_ROPE  64
#define D_QK    192
#define D_V     128
#define Q_LORA  1536
#define KV_LORA 512
#define QKV_A_N 2112
#define SCALING 0.07216878364870322f   // 192^-0.5

// ---------------- scratch ----------------
__device__ __align__(128) float g_qkv_a [T_TOK * QKV_A_N];
__device__ __align__(128) float g_kvbuf [T_TOK * NH * 256];
__device__ __align__(128) float g_kpe   [T_TOK * D_ROPE];
// fp16 planes
__device__ __align__(128) __half g_hid_hi [T_TOK * HID];
__device__ __align__(128) __half g_hid_lo [T_TOK * HID];
__device__ __align__(128) __half g_qn_hi  [T_TOK * Q_LORA];
__device__ __align__(128) __half g_qn_lo  [T_TOK * Q_LORA];
__device__ __align__(128) __half g_kvn_hi [T_TOK * KV_LORA];
__device__ __align__(128) __half g_kvn_lo [T_TOK * KV_LORA];
__device__ __align__(128) __half g_attn_hi[T_TOK * NH * D_V];
__device__ __align__(128) __half g_attn_lo[T_TOK * NH * D_V];
__device__ __align__(128) __half g_wa_f16  [QKV_A_N * HID];
__device__ __align__(128) __half g_wqb_f16 [NH * D_QK * Q_LORA];
__device__ __align__(128) __half g_wkvb_f16[NH * 256 * KV_LORA];
__device__ __align__(128) __half g_wo_f16  [HID * NH * D_V];
// attention operand planes (all single fp16 except attention output)
__device__ __align__(128) __half g_q_f16 [T_TOK * NH * D_QK];
__device__ __align__(128) __half g_k_f16 [T_TOK * NH * D_QK];
__device__ __align__(128) __half g_vt_f16[NH * D_V * T_TOK];

// ---------------- helpers ----------------
__device__ __forceinline__ void cp16(void* s, const void* g) {
    unsigned int sa = (unsigned int)__cvta_generic_to_shared(s);
    asm volatile("cp.async.cg.shared.global [%0], [%1], 16;" :: "r"(sa), "l"(g));
}
#define CP_COMMIT() asm volatile("cp.async.commit_group;")
#define CP_WAIT1()  asm volatile("cp.async.wait_group 1;")
#define CP_WAIT0()  asm volatile("cp.async.wait_group 0;")

__device__ __forceinline__ uint32_t smem_u32(const void* p) {
    return (uint32_t)__cvta_generic_to_shared(p);
}
#define LDSM4(r0, r1, r2, r3, a) \
    asm volatile("ldmatrix.sync.aligned.m8n8.x4.shared.b16 {%0,%1,%2,%3}, [%4];" \
        : "=r"(r0), "=r"(r1), "=r"(r2), "=r"(r3) : "r"(a))

__device__ __forceinline__ void mma_f16(float* c,
    uint32_t a0, uint32_t a1, uint32_t a2, uint32_t a3, uint32_t b0, uint32_t b1)
{
    asm volatile(
        "mma.sync.aligned.m16n8k16.row.col.f32.f16.f16.f32 "
        "{%0,%1,%2,%3},{%4,%5,%6,%7},{%8,%9},{%0,%1,%2,%3};"
        : "+f"(c[0]), "+f"(c[1]), "+f"(c[2]), "+f"(c[3])
        : "r"(a0), "r"(a1), "r"(a2), "r"(a3), "r"(b0), "r"(b1));
}

__device__ __forceinline__ void split_f16(float v, __half& h, __half& l) {
    h = __float2half_rn(v);
    l = __float2half_rn(v - __half2float(h));
}
__device__ __forceinline__ uint32_t pack2h(__half a, __half b) {
    return (uint32_t)__half_as_ushort(a) | ((uint32_t)__half_as_ushort(b) << 16);
}

// ---------------- converters ----------------
__global__ __launch_bounds__(256) void convert_hl_f16_kernel(
    const float2* __restrict__ src, uint32_t* __restrict__ hi,
    uint32_t* __restrict__ lo, int n2)
{
    int i = blockIdx.x * 256 + threadIdx.x;
    const int stride = gridDim.x * 256;
    for (; i < n2; i += stride) {
        const float2 v = src[i];
        __half h0, l0, h1, l1;
        split_f16(v.x, h0, l0);
        split_f16(v.y, h1, l1);
        hi[i] = pack2h(h0, h1);
        lo[i] = pack2h(l0, l1);
    }
}

// in fp32 [R][C] -> out single fp16 [C][R] (weights)
__global__ __launch_bounds__(256) void transpose_cvt_f16_kernel(
    const float* __restrict__ in, __half* __restrict__ outp, int R, int C)
{
    __shared__ float t[32][33];
    const int c0 = blockIdx.x * 32, r0 = blockIdx.y * 32;
    const int x = threadIdx.x, y = threadIdx.y;
#pragma unroll
    for (int j = 0; j < 32; j += 8)
        t[y + j][x] = in[(size_t)(r0 + y + j) * C + c0 + x];
    __syncthreads();
#pragma unroll
    for (int j = 0; j < 32; j += 8)
        outp[(size_t)(c0 + y + j) * R + r0 + x] = __float2half_rn(t[x][y + j]);
}

// build K plane (single fp16)
__global__ __launch_bounds__(256) void build_k_kernel(
    const float* __restrict__ kvbuf, const float* __restrict__ kpe,
    __half* __restrict__ k16)
{
    const int t = blockIdx.x;
    for (int i = threadIdx.x; i < NH * D_QK; i += 256) {
        const int h = i / D_QK, d = i - h * D_QK;
        const float v = (d < 128)
            ? kvbuf[(size_t)t * (NH * 256) + h * 256 + d]
            : kpe[(size_t)t * D_ROPE + (d - 128)];
        k16[(size_t)t * (NH * D_QK) + i] = __float2half_rn(v);
    }
}

// build VT plane (single fp16): vt[h][d][t]
__global__ __launch_bounds__(256) void build_vt_kernel(
    const float* __restrict__ kvbuf, __half* __restrict__ vt16)
{
    __shared__ float tile[32][33];
    const int h = blockIdx.z;
    const int d0 = blockIdx.y * 32;
    const int t0 = blockIdx.x * 32;
    const int x = threadIdx.x, y = threadIdx.y;
#pragma unroll
    for (int j = 0; j < 32; j += 8)
        tile[y + j][x] = kvbuf[(size_t)(t0 + y + j) * (NH * 256) + h * 256 + 128 + d0 + x];
    __syncthreads();
#pragma unroll
    for (int j = 0; j < 32; j += 8)
        vt16[((size_t)h * D_V + d0 + y + j) * T_TOK + t0 + x] = __float2half_rn(tile[x][y + j]);
}

// ---------------- fp16 2-product GEMM, fp32 out (BN=64, proven) ----------------
#define PITCH_B 80
#define F_AHI 0
#define F_ALO 20480
#define F_BHI 40960
#define F_STAGE 46080
#define F_SMEM  (2 * F_STAGE)

__global__ __launch_bounds__(256, 2) void gemm_f16(
    const __half* __restrict__ Ah, const __half* __restrict__ Al,
    const __half* __restrict__ Bh,
    float* __restrict__ C, int M, int N, int K)
{
    extern __shared__ __align__(128) char smx[];
    const uint32_t sbase = smem_u32(smx);
    const int tid  = threadIdx.x;
    const int warp = tid >> 5;
    const int lane = tid & 31;
    const int wm   = warp >> 1;
    const int wn   = warp & 1;
    const int row0 = blockIdx.y * 256;
    const int col0 = blockIdx.x * 64;

    float c[16][4];
#pragma unroll
    for (int i = 0; i < 16; i++)
#pragma unroll
        for (int j = 0; j < 4; j++) c[i][j] = 0.f;

    auto fill = [&](int stage, int k0) {
        char* st = smx + stage * F_STAGE;
#pragma unroll
        for (int rep = 0; rep < 4; rep++) {
            const int cch = tid + rep * 256;
            const int r = cch >> 2, q = cch & 3;
            const size_t src = (size_t)(row0 + r) * K + k0 + q * 8;
            cp16(st + F_AHI + r * PITCH_B + q * 16, Ah + src);
            cp16(st + F_ALO + r * PITCH_B + q * 16, Al + src);
        }
        {
            const int r = tid >> 2, q = tid & 3;
            const size_t src = (size_t)(col0 + r) * K + k0 + q * 8;
            cp16(st + F_BHI + r * PITCH_B + q * 16, Bh + src);
        }
    };

    fill(0, 0);
    CP_COMMIT();

    const int nch = K >> 5;
    const int rowL = (lane & 7) + (lane & 8);
    const int kbL  = (lane >> 4) * 16;

    for (int ch = 0; ch < nch; ch++) {
        const int buf = ch & 1;
        if (ch + 1 < nch) {
            fill(buf ^ 1, (ch + 1) * 32);
            CP_COMMIT();
            CP_WAIT1();
        } else {
            CP_WAIT0();
        }
        __syncthreads();

        const uint32_t sAh = sbase + buf * F_STAGE + F_AHI;
        const uint32_t sAl = sbase + buf * F_STAGE + F_ALO;
        const uint32_t sBh = sbase + buf * F_STAGE + F_BHI;

#pragma unroll
        for (int kk = 0; kk < 2; kk++) {
            const int kb = kk * 32 + kbL;
            uint32_t bh[2][4];
#pragma unroll
            for (int j = 0; j < 2; j++) {
                const int rB = (wn * 32 + j * 16 + rowL) * PITCH_B + kb;
                LDSM4(bh[j][0], bh[j][1], bh[j][2], bh[j][3], sBh + rB);
            }
#pragma unroll
            for (int i = 0; i < 4; i++) {
                const int rA = (wm * 64 + i * 16 + rowL) * PITCH_B + kb;
                uint32_t ah0, ah1, ah2, ah3, al0, al1, al2, al3;
                LDSM4(ah0, ah1, ah2, ah3, sAh + rA);
                LDSM4(al0, al1, al2, al3, sAl + rA);
#pragma unroll
                for (int f = 0; f < 4; f++) {
                    const int j = f >> 1, h = f & 1;
                    float* acc = c[i * 4 + f];
                    mma_f16(acc, ah0, ah1, ah2, ah3, bh[j][h], bh[j][h + 2]);
                    mma_f16(acc, al0, al1, al2, al3, bh[j][h], bh[j][h + 2]);
                }
            }
        }
        __syncthreads();
    }

    const int qr = lane >> 2, qc = 2 * (lane & 3);
#pragma unroll
    for (int i = 0; i < 4; i++) {
#pragma unroll
        for (int f = 0; f < 4; f++) {
            const int r   = row0 + wm * 64 + i * 16 + qr;
            const int col = col0 + wn * 32 + f * 8 + qc;
            *(float2*)(C + (size_t)r * N + col)       = make_float2(c[i * 4 + f][0], c[i * 4 + f][1]);
            *(float2*)(C + (size_t)(r + 8) * N + col) = make_float2(c[i * 4 + f][2], c[i * 4 + f][3]);
        }
    }
}

// ---------------- fp16 2-product GEMM, BN=96, 512 threads, single-f16 out ----------------
#define G96_AHI 0
#define G96_ALO 20480
#define G96_BHI 40960
#define G96_STAGE 48640       // 2*20480 + 96*80
#define G96_SMEM (2 * G96_STAGE)

__global__ __launch_bounds__(512, 1) void gemm96_f16(
    const __half* __restrict__ Ah, const __half* __restrict__ Al,
    const __half* __restrict__ Bh,
    uint32_t* __restrict__ Cq, int M, int N, int K)
{
    extern __shared__ __align__(128) char smx[];
    const uint32_t sbase = smem_u32(smx);
    const int tid  = threadIdx.x;
    const int warp = tid >> 5;       // 0..15
    const int lane = tid & 31;
    const int wm   = warp >> 1;      // 0..7 -> rows wm*32
    const int wn   = warp & 1;       // 0..1 -> cols wn*48
    const int row0 = blockIdx.y * 256;
    const int col0 = blockIdx.x * 96;

    float c[12][4];
#pragma unroll
    for (int i = 0; i < 12; i++)
#pragma unroll
        for (int j = 0; j < 4; j++) c[i][j] = 0.f;

    auto fill = [&](int stage, int k0) {
        char* st = smx + stage * G96_STAGE;
#pragma unroll
        for (int rep = 0; rep < 2; rep++) {
            const int cch = tid + rep * 512;   // 0..1023
            const int r = cch >> 2, q = cch & 3;
            const size_t src = (size_t)(row0 + r) * K + k0 + q * 8;
            cp16(st + G96_AHI + r * PITCH_B + q * 16, Ah + src);
            cp16(st + G96_ALO + r * PITCH_B + q * 16, Al + src);
        }
        if (tid < 384) {
            const int r = tid >> 2, q = tid & 3;   // 96 rows x 4 chunks
            const size_t src = (size_t)(col0 + r) * K + k0 + q * 8;
            cp16(st + G96_BHI + r * PITCH_B + q * 16, Bh + src);
        }
    };

    fill(0, 0);
    CP_COMMIT();

    const int nch = K >> 5;
    const int rowL = (lane & 7) + (lane & 8);
    const int kbL  = (lane >> 4) * 16;

    for (int ch = 0; ch < nch; ch++) {
        const int buf = ch & 1;
        if (ch + 1 < nch) {
            fill(buf ^ 1, (ch + 1) * 32);
            CP_COMMIT();
            CP_WAIT1();
        } else {
            CP_WAIT0();
        }
        __syncthreads();

        const uint32_t sAh = sbase + buf * G96_STAGE + G96_AHI;
        const uint32_t sAl = sbase + buf * G96_STAGE + G96_ALO;
        const uint32_t sBh = sbase + buf * G96_STAGE + G96_BHI;

#pragma unroll
        for (int kk = 0; kk < 2; kk++) {
            const int kb = kk * 32 + kbL;
            uint32_t bh[3][4];
#pragma unroll
            for (int j = 0; j < 3; j++) {
                const int rB = (wn * 48 + j * 16 + rowL) * PITCH_B + kb;
                LDSM4(bh[j][0], bh[j][1], bh[j][2], bh[j][3], sBh + rB);
            }
#pragma unroll
            for (int i = 0; i < 2; i++) {
                const int rA = (wm * 32 + i * 16 + rowL) * PITCH_B + kb;
                uint32_t ah0, ah1, ah2, ah3, al0, al1, al2, al3;
                LDSM4(ah0, ah1, ah2, ah3, sAh + rA);
                LDSM4(al0, al1, al2, al3, sAl + rA);
#pragma unroll
                for (int f = 0; f < 6; f++) {
                    const int j = f >> 1, h = f & 1;
                    float* acc = c[i * 6 + f];
                    mma_f16(acc, ah0, ah1, ah2, ah3, bh[j][h], bh[j][h + 2]);
                    mma_f16(acc, al0, al1, al2, al3, bh[j][h], bh[j][h + 2]);
                }
            }
        }
        __syncthreads();
    }

    const int qr = lane >> 2, qc = 2 * (lane & 3);
#pragma unroll
    for (int i = 0; i < 2; i++) {
#pragma unroll
        for (int f = 0; f < 6; f++) {
            const int j = f >> 1, h = f & 1;
            const int r   = row0 + wm * 32 + i * 16 + qr;
            const int col = col0 + wn * 48 + j * 16 + h * 8 + qc;
            const float* a = c[i * 6 + f];
            Cq[((size_t)r * N + col) >> 1] =
                pack2h(__float2half_rn(a[0]), __float2half_rn(a[1]));
            Cq[((size_t)(r + 8) * N + col) >> 1] =
                pack2h(__float2half_rn(a[2]), __float2half_rn(a[3]));
        }
    }
}

// ---------------- RMSNorm -> fp16 hi/lo ----------------
__global__ __launch_bounds__(256) void rmsnorm_kernel(
    const float* __restrict__ in, int ld, int off, int width,
    const float* __restrict__ gamma,
    __half* __restrict__ ohi, __half* __restrict__ olo)
{
    const int row = blockIdx.x;
    const float* x = in + (size_t)row * ld + off;
    float ss = 0.f;
    for (int i = threadIdx.x; i < width; i += 256) {
        float v = x[i];
        ss += v * v;
    }
#pragma unroll
    for (int o = 16; o; o >>= 1) ss += __shfl_xor_sync(0xffffffffu, ss, o);
    __shared__ float warp_s[8];
    __shared__ float s_inv;
    if ((threadIdx.x & 31) == 0) warp_s[threadIdx.x >> 5] = ss;
    __syncthreads();
    if (threadIdx.x == 0) {
        float t = 0.f;
#pragma unroll
        for (int i = 0; i < 8; i++) t += warp_s[i];
        s_inv = rsqrtf(t / (float)width + 1e-6f);
    }
    __syncthreads();
    const float inv = s_inv;
    for (int i = threadIdx.x; i < width; i += 256) {
        const float v = x[i] * inv * gamma[i];
        __half h, l;
        split_f16(v, h, l);
        ohi[(size_t)row * width + i] = h;
        olo[(size_t)row * width + i] = l;
    }
}

// ---------------- RoPE on single fp16 Q plane + kpe from fp32 ----------------
__global__ __launch_bounds__(256) void rope_q16_kernel(
    uint32_t* __restrict__ q16,
    const float* __restrict__ qkv_a, float* __restrict__ kpe,
    const int* __restrict__ positions)
{
    const int t = blockIdx.x;
    const float pos = (float)positions[t];
    for (int i = threadIdx.x; i < NH * 32 + 32; i += 256) {
        if (i < NH * 32) {
            const int h = i >> 5, p = i & 31;
            const float inv = powf(10000.0f, -(float)p / 32.0f);
            float s, c;
            sincosf(pos * inv, &s, &c);
            const size_t idx = ((size_t)t * (NH * D_QK) + h * D_QK + D_NOPE + 2 * p) >> 1;
            const uint32_t w = q16[idx];
            const float x1 = __half2float(__ushort_as_half((unsigned short)(w & 0xffff)));
            const float x2 = __half2float(__ushort_as_half((unsigned short)(w >> 16)));
            q16[idx] = pack2h(__float2half_rn(x1 * c - x2 * s),
                              __float2half_rn(x1 * s + x2 * c));
        } else {
            const int p = i - NH * 32;
            const float inv = powf(10000.0f, -(float)p / 32.0f);
            float s, c;
            sincosf(pos * inv, &s, &c);
            const float* src = qkv_a + (size_t)t * QKV_A_N + (Q_LORA + KV_LORA);
            const float x1 = src[2 * p], x2 = src[2 * p + 1];
            kpe[(size_t)t * D_ROPE + 2 * p]     = x1 * c - x2 * s;
            kpe[(size_t)t * D_ROPE + 2 * p + 1] = x1 * s + x2 * c;
        }
    }
}

// ---------------- fp16 causal flash attention (occ 2, all single fp16) ----------------
#define SQ  0
#define SK  25600
#define SV  51200
#define SPH 69632
#define SSTAT 78848
#define ATT_SMEM (SSTAT + 1792)   // 80640 B -> 2 CTAs/SM

__global__ __launch_bounds__(256, 2) void attn_f16_kernel(
    const __half* __restrict__ q16,
    const __half* __restrict__ k16, const __half* __restrict__ vt16,
    uint32_t* __restrict__ ohi, uint32_t* __restrict__ olo)
{
    extern __shared__ __align__(128) char sma[];
    const uint32_t sb = smem_u32(sma);
    float* sWmax  = (float*)(sma + SSTAT);
    float* sWsum  = sWmax + 128;
    float* sM     = sWsum + 128;
    float* sL     = sM + 64;
    float* sScale = sL + 64;

    const int h    = blockIdx.y;
    const int qt   = (int)gridDim.x - 1 - (int)blockIdx.x;   // longest-first
    const int t0   = qt * 64;
    const int tid  = threadIdx.x;
    const int w    = tid >> 5;
    const int lane = tid & 31;
    const int g    = lane >> 2;
    const int t    = lane & 3;
    const int mrow = (w & 3) * 16;
    const int nhalf = w >> 2;
    const int r0 = mrow + g, r1 = r0 + 8;

    // Q tile (once): 64 rows x 192 halves = 24 chunks of 16B per row
    for (int i = tid; i < 1536; i += 256) {
        const int r = i / 24, c = i - r * 24;
        const size_t src = (size_t)(t0 + r) * (NH * D_QK) + h * D_QK + c * 8;
        cp16(sma + SQ + r * 400 + c * 16, q16 + src);
    }
    CP_COMMIT();
    if (tid < 64) { sM[tid] = -1e30f; sL[tid] = 0.f; }

    float o[8][4];
#pragma unroll
    for (int i = 0; i < 8; i++)
#pragma unroll
        for (int j = 0; j < 4; j++) o[i][j] = 0.f;

    const int rowL = (lane & 7) + (lane & 8);
    const int kbL  = (lane >> 4) * 16;

    for (int kt = 0; kt <= qt; kt++) {
        const int k0 = kt * 64;
        __syncthreads();
        for (int i = tid; i < 1536; i += 256) {
            const int r = i / 24, c = i - r * 24;
            const size_t src = (size_t)(k0 + r) * (NH * D_QK) + h * D_QK + c * 8;
            cp16(sma + SK + r * 400 + c * 16, k16 + src);
        }
        for (int i = tid; i < 1024; i += 256) {
            const int r = i >> 3, c = i & 7;
            const size_t src = ((size_t)h * D_V + r) * T_TOK + k0 + c * 8;
            cp16(sma + SV + r * 144 + c * 16, vt16 + src);
        }
        CP_COMMIT();
        CP_WAIT0();
        __syncthreads();

        // ---- S = Q @ K^T (single product) ----
        float s[4][4];
#pragma unroll
        for (int nt = 0; nt < 4; nt++)
#pragma unroll
            for (int j = 0; j < 4; j++) s[nt][j] = 0.f;

#pragma unroll 3
        for (int ks = 0; ks < 12; ks++) {
            const int kb = ks * 32 + kbL;
            uint32_t a0, a1, a2, a3;
            const int rA = (mrow + rowL) * 400 + kb;
            LDSM4(a0, a1, a2, a3, sb + SQ + rA);
            uint32_t bh[2][4];
#pragma unroll
            for (int j = 0; j < 2; j++) {
                const int rB = (nhalf * 32 + j * 16 + rowL) * 400 + kb;
                LDSM4(bh[j][0], bh[j][1], bh[j][2], bh[j][3], sb + SK + rB);
            }
#pragma unroll
            for (int nt = 0; nt < 4; nt++) {
                const int j = nt >> 1, hh = nt & 1;
                mma_f16(s[nt], a0, a1, a2, a3, bh[j][hh], bh[j][hh + 2]);
            }
        }

        const int rg0 = t0 + r0, rg1 = t0 + r1;
#pragma unroll
        for (int nt = 0; nt < 4; nt++) {
            const int cg = k0 + nhalf * 32 + nt * 8 + 2 * t;
            s[nt][0] = (rg0 >= cg)     ? s[nt][0] * SCALING : -1e30f;
            s[nt][1] = (rg0 >= cg + 1) ? s[nt][1] * SCALING : -1e30f;
            s[nt][2] = (rg1 >= cg)     ? s[nt][2] * SCALING : -1e30f;
            s[nt][3] = (rg1 >= cg + 1) ? s[nt][3] * SCALING : -1e30f;
        }

        float mx0 = -1e30f, mx1 = -1e30f;
#pragma unroll
        for (int nt = 0; nt < 4; nt++) {
            mx0 = fmaxf(mx0, fmaxf(s[nt][0], s[nt][1]));
            mx1 = fmaxf(mx1, fmaxf(s[nt][2], s[nt][3]));
        }
        mx0 = fmaxf(mx0, __shfl_xor_sync(0xffffffffu, mx0, 1));
        mx0 = fmaxf(mx0, __shfl_xor_sync(0xffffffffu, mx0, 2));
        mx1 = fmaxf(mx1, __shfl_xor_sync(0xffffffffu, mx1, 1));
        mx1 = fmaxf(mx1, __shfl_xor_sync(0xffffffffu, mx1, 2));
        if (t == 0) { sWmax[nhalf * 64 + r0] = mx0; sWmax[nhalf * 64 + r1] = mx1; }
        __syncthreads();

        const float mn0 = fmaxf(sM[r0], fmaxf(sWmax[r0], sWmax[64 + r0]));
        const float mn1 = fmaxf(sM[r1], fmaxf(sWmax[r1], sWmax[64 + r1]));

        float sum0 = 0.f, sum1 = 0.f;
#pragma unroll
        for (int nt = 0; nt < 4; nt++) {
            s[nt][0] = __expf(s[nt][0] - mn0);
            s[nt][1] = __expf(s[nt][1] - mn0);
            s[nt][2] = __expf(s[nt][2] - mn1);
            s[nt][3] = __expf(s[nt][3] - mn1);
            sum0 += s[nt][0] + s[nt][1];
            sum1 += s[nt][2] + s[nt][3];
            const int coll = nhalf * 32 + nt * 8 + 2 * t;
            *(uint32_t*)(sma + SPH + r0 * 144 + coll * 2) =
                pack2h(__float2half_rn(s[nt][0]), __float2half_rn(s[nt][1]));
            *(uint32_t*)(sma + SPH + r1 * 144 + coll * 2) =
                pack2h(__float2half_rn(s[nt][2]), __float2half_rn(s[nt][3]));
        }
        sum0 += __shfl_xor_sync(0xffffffffu, sum0, 1);
        sum0 += __shfl_xor_sync(0xffffffffu, sum0, 2);
        sum1 += __shfl_xor_sync(0xffffffffu, sum1, 1);
        sum1 += __shfl_xor_sync(0xffffffffu, sum1, 2);
        if (t == 0) { sWsum[nhalf * 64 + r0] = sum0; sWsum[nhalf * 64 + r1] = sum1; }
        __syncthreads();

        if (tid < 64) {
            const float mo = sM[tid];
            const float mn = fmaxf(mo, fmaxf(sWmax[tid], sWmax[64 + tid]));
            const float sc = __expf(mo - mn);
            sM[tid] = mn;
            sL[tid] = sL[tid] * sc + sWsum[tid] + sWsum[64 + tid];
            sScale[tid] = sc;
        }
        __syncthreads();

        const float sc0 = sScale[r0], sc1 = sScale[r1];
#pragma unroll
        for (int nt = 0; nt < 8; nt++) {
            o[nt][0] *= sc0; o[nt][1] *= sc0;
            o[nt][2] *= sc1; o[nt][3] *= sc1;
        }

        // ---- O += P @ V ----
#pragma unroll
        for (int ks = 0; ks < 4; ks++) {
            const int kb = ks * 32 + kbL;
            uint32_t ph0, ph1, ph2, ph3;
            const int rP = (mrow + rowL) * 144 + kb;
            LDSM4(ph0, ph1, ph2, ph3, sb + SPH + rP);
#pragma unroll
            for (int j2 = 0; j2 < 4; j2++) {
                const int rV = (nhalf * 64 + j2 * 16 + rowL) * 144 + kb;
                uint32_t vh[4];
                LDSM4(vh[0], vh[1], vh[2], vh[3], sb + SV + rV);
#pragma unroll
                for (int hh = 0; hh < 2; hh++)
                    mma_f16(o[j2 * 2 + hh], ph0, ph1, ph2, ph3, vh[hh], vh[hh + 2]);
            }
        }
    }

    // epilogue -> fp16 hi/lo planes
    const float il0 = 1.f / sL[r0];
    const float il1 = 1.f / sL[r1];
#pragma unroll
    for (int nt = 0; nt < 8; nt++) {
        const int col = h * D_V + nhalf * 64 + nt * 8 + 2 * t;
        const float v00 = o[nt][0] * il0, v01 = o[nt][1] * il0;
        const float v10 = o[nt][2] * il1, v11 = o[nt][3] * il1;
        __half h0, l0, h1, l1;
        split_f16(v00, h0, l0); split_f16(v01, h1, l1);
        ohi[((size_t)(t0 + r0) * (NH * D_V) + col) >> 1] = pack2h(h0, h1);
        olo[((size_t)(t0 + r0) * (NH * D_V) + col) >> 1] = pack2h(l0, l1);
        split_f16(v10, h0, l0); split_f16(v11, h1, l1);
        ohi[((size_t)(t0 + r1) * (NH * D_V) + col) >> 1] = pack2h(h0, h1);
        olo[((size_t)(t0 + r1) * (NH * D_V) + col) >> 1] = pack2h(l0, l1);
    }
}

// ---------------- launch ----------------
extern "C" void kernel_launch(void* const* d_in, const int* in_sizes, int n_in,
                              void* d_out, int out_size)
{
    const float* hidden    = (const float*)d_in[0];
    const int*   positions = (const int*)  d_in[1];
    const float* w_qkv_a   = (const float*)d_in[2];
    const float* gamma_q   = (const float*)d_in[3];
    const float* w_q_b     = (const float*)d_in[4];
    const float* gamma_kv  = (const float*)d_in[5];
    const float* w_kv_b    = (const float*)d_in[6];
    const float* w_o       = (const float*)d_in[7];
    float* out = (float*)d_out;

    float *qkv_a, *kvbuf, *kpe;
    __half *hid_h, *hid_l, *qn_h, *qn_l, *kvn_h, *kvn_l, *at_h, *at_l;
    __half *wa, *wqb, *wkvb, *wo;
    __half *q16, *k16, *vt16;
    cudaGetSymbolAddress((void**)&qkv_a, g_qkv_a);
    cudaGetSymbolAddress((void**)&kvbuf, g_kvbuf);
    cudaGetSymbolAddress((void**)&kpe,   g_kpe);
    cudaGetSymbolAddress((void**)&hid_h, g_hid_hi);  cudaGetSymbolAddress((void**)&hid_l, g_hid_lo);
    cudaGetSymbolAddress((void**)&qn_h,  g_qn_hi);   cudaGetSymbolAddress((void**)&qn_l,  g_qn_lo);
    cudaGetSymbolAddress((void**)&kvn_h, g_kvn_hi);  cudaGetSymbolAddress((void**)&kvn_l, g_kvn_lo);
    cudaGetSymbolAddress((void**)&at_h,  g_attn_hi); cudaGetSymbolAddress((void**)&at_l,  g_attn_lo);
    cudaGetSymbolAddress((void**)&wa,    g_wa_f16);
    cudaGetSymbolAddress((void**)&wqb,   g_wqb_f16);
    cudaGetSymbolAddress((void**)&wkvb,  g_wkvb_f16);
    cudaGetSymbolAddress((void**)&wo,    g_wo_f16);
    cudaGetSymbolAddress((void**)&q16,   g_q_f16);
    cudaGetSymbolAddress((void**)&k16,   g_k_f16);
    cudaGetSymbolAddress((void**)&vt16,  g_vt_f16);

    cudaFuncSetAttribute(gemm_f16,   cudaFuncAttributeMaxDynamicSharedMemorySize, F_SMEM);
    cudaFuncSetAttribute(gemm96_f16, cudaFuncAttributeMaxDynamicSharedMemorySize, G96_SMEM);
    cudaFuncSetAttribute(attn_f16_kernel, cudaFuncAttributeMaxDynamicSharedMemorySize, ATT_SMEM);

    // 0) one-time conversions
    convert_hl_f16_kernel<<<1184, 256>>>((const float2*)hidden,
        (uint32_t*)hid_h, (uint32_t*)hid_l, T_TOK * HID / 2);
    transpose_cvt_f16_kernel<<<dim3(QKV_A_N / 32, HID / 32),      dim3(32, 8)>>>(w_qkv_a, wa,   HID,      QKV_A_N);
    transpose_cvt_f16_kernel<<<dim3((NH*D_QK) / 32, Q_LORA / 32), dim3(32, 8)>>>(w_q_b,   wqb,  Q_LORA,   NH * D_QK);
    transpose_cvt_f16_kernel<<<dim3((NH*256) / 32, KV_LORA / 32), dim3(32, 8)>>>(w_kv_b,  wkvb, KV_LORA,  NH * 256);
    transpose_cvt_f16_kernel<<<dim3(HID / 32, (NH*D_V) / 32),     dim3(32, 8)>>>(w_o,     wo,   NH * D_V, HID);

    // 1) qkv_a = hidden @ w_qkv_a   (fp32 out)
    gemm_f16<<<dim3(QKV_A_N / 64, T_TOK / 256), 256, F_SMEM>>>(
        hid_h, hid_l, wa, qkv_a, T_TOK, QKV_A_N, HID);

    // 2) RMSNorm -> fp16 hi/lo
    rmsnorm_kernel<<<T_TOK, 256>>>(qkv_a, QKV_A_N, 0,      Q_LORA,  gamma_q,  qn_h,  qn_l);
    rmsnorm_kernel<<<T_TOK, 256>>>(qkv_a, QKV_A_N, Q_LORA, KV_LORA, gamma_kv, kvn_h, kvn_l);

    // 3) q = qn @ w_q_b -> single fp16 Q plane (BN=96 wave-balanced)
    gemm96_f16<<<dim3((NH * D_QK) / 96, T_TOK / 256), 512, G96_SMEM>>>(
        qn_h, qn_l, wqb, (uint32_t*)q16, T_TOK, NH * D_QK, Q_LORA);

    // 4) kv = kvn @ w_kv_b  (fp32 out)
    gemm_f16<<<dim3((NH * 256) / 64, T_TOK / 256), 256, F_SMEM>>>(
        kvn_h, kvn_l, wkvb, kvbuf, T_TOK, NH * 256, KV_LORA);

    // 5) RoPE in-place on Q plane; kpe from qkv_a
    rope_q16_kernel<<<T_TOK, 256>>>((uint32_t*)q16, qkv_a, kpe, positions);

    // 6) K / VT planes
    build_k_kernel<<<T_TOK, 256>>>(kvbuf, kpe, k16);
    build_vt_kernel<<<dim3(T_TOK / 32, D_V / 32, NH), dim3(32, 8)>>>(kvbuf, vt16);

    // 7) attention -> fp16 hi/lo planes
    attn_f16_kernel<<<dim3(T_TOK / 64, NH), 256, ATT_SMEM>>>(
        q16, k16, vt16, (uint32_t*)at_h, (uint32_t*)at_l);

    // 8) out = attn @ w_o  (fp32 out)
    gemm_f16<<<dim3(HID / 64, T_TOK / 256), 256, F_SMEM>>>(
        at_h, at_l, wo, out, T_TOK, HID, NH * D_V);
}

// round 15
// speedup vs baseline: 2.1908x; 1.4205x over previous
#include <cuda_runtime.h>
#include <cuda_fp16.h>
#include <math.h>
#include <stdint.h>

// ---------------- problem constants ----------------
#define T_TOK   2048
#define HID     2048
#define NH      16
#define D_NOPE  128
#define D_ROPE  64
#define D_QK    192
#define D_V     128
#define Q_LORA  1536
#define KV_LORA 512
#define QKV_A_N 2112
#define SCALING 0.07216878364870322f   // 192^-0.5

// ---------------- scratch ----------------
__device__ __align__(128) float g_qkv_a [T_TOK * QKV_A_N];
__device__ __align__(128) float g_kvbuf [T_TOK * NH * 256];
__device__ __align__(128) float g_kpe   [T_TOK * D_ROPE];
// fp16 planes (all single-rounded)
__device__ __align__(128) __half g_hid_f16 [T_TOK * HID];
__device__ __align__(128) __half g_qn_f16  [T_TOK * Q_LORA];
__device__ __align__(128) __half g_kvn_f16 [T_TOK * KV_LORA];
__device__ __align__(128) __half g_at_f16  [T_TOK * NH * D_V];
__device__ __align__(128) __half g_wa_f16  [QKV_A_N * HID];
__device__ __align__(128) __half g_wqb_f16 [NH * D_QK * Q_LORA];
__device__ __align__(128) __half g_wkvb_f16[NH * 256 * KV_LORA];
__device__ __align__(128) __half g_wo_f16  [HID * NH * D_V];
// attention operand planes
__device__ __align__(128) __half g_q_f16 [T_TOK * NH * D_QK];
__device__ __align__(128) __half g_k_f16 [T_TOK * NH * D_QK];
__device__ __align__(128) __half g_vt_f16[NH * D_V * T_TOK];

// ---------------- helpers ----------------
__device__ __forceinline__ void cp16(void* s, const void* g) {
    unsigned int sa = (unsigned int)__cvta_generic_to_shared(s);
    asm volatile("cp.async.cg.shared.global [%0], [%1], 16;" :: "r"(sa), "l"(g));
}
#define CP_COMMIT() asm volatile("cp.async.commit_group;")
#define CP_WAIT1()  asm volatile("cp.async.wait_group 1;")
#define CP_WAIT0()  asm volatile("cp.async.wait_group 0;")

__device__ __forceinline__ uint32_t smem_u32(const void* p) {
    return (uint32_t)__cvta_generic_to_shared(p);
}
#define LDSM4(r0, r1, r2, r3, a) \
    asm volatile("ldmatrix.sync.aligned.m8n8.x4.shared.b16 {%0,%1,%2,%3}, [%4];" \
        : "=r"(r0), "=r"(r1), "=r"(r2), "=r"(r3) : "r"(a))

__device__ __forceinline__ void mma_f16(float* c,
    uint32_t a0, uint32_t a1, uint32_t a2, uint32_t a3, uint32_t b0, uint32_t b1)
{
    asm volatile(
        "mma.sync.aligned.m16n8k16.row.col.f32.f16.f16.f32 "
        "{%0,%1,%2,%3},{%4,%5,%6,%7},{%8,%9},{%0,%1,%2,%3};"
        : "+f"(c[0]), "+f"(c[1]), "+f"(c[2]), "+f"(c[3])
        : "r"(a0), "r"(a1), "r"(a2), "r"(a3), "r"(b0), "r"(b1));
}

__device__ __forceinline__ uint32_t pack2h(__half a, __half b) {
    return (uint32_t)__half_as_ushort(a) | ((uint32_t)__half_as_ushort(b) << 16);
}

// ---------------- converters ----------------
__global__ __launch_bounds__(256) void convert_f16_kernel(
    const float2* __restrict__ src, uint32_t* __restrict__ dst, int n2)
{
    int i = blockIdx.x * 256 + threadIdx.x;
    const int stride = gridDim.x * 256;
    for (; i < n2; i += stride) {
        const float2 v = src[i];
        dst[i] = pack2h(__float2half_rn(v.x), __float2half_rn(v.y));
    }
}

// in fp32 [R][C] -> out single fp16 [C][R] (weights)
__global__ __launch_bounds__(256) void transpose_cvt_f16_kernel(
    const float* __restrict__ in, __half* __restrict__ outp, int R, int C)
{
    __shared__ float t[32][33];
    const int c0 = blockIdx.x * 32, r0 = blockIdx.y * 32;
    const int x = threadIdx.x, y = threadIdx.y;
#pragma unroll
    for (int j = 0; j < 32; j += 8)
        t[y + j][x] = in[(size_t)(r0 + y + j) * C + c0 + x];
    __syncthreads();
#pragma unroll
    for (int j = 0; j < 32; j += 8)
        outp[(size_t)(c0 + y + j) * R + r0 + x] = __float2half_rn(t[x][y + j]);
}

// build K plane (single fp16)
__global__ __launch_bounds__(256) void build_k_kernel(
    const float* __restrict__ kvbuf, const float* __restrict__ kpe,
    __half* __restrict__ k16)
{
    const int t = blockIdx.x;
    for (int i = threadIdx.x; i < NH * D_QK; i += 256) {
        const int h = i / D_QK, d = i - h * D_QK;
        const float v = (d < 128)
            ? kvbuf[(size_t)t * (NH * 256) + h * 256 + d]
            : kpe[(size_t)t * D_ROPE + (d - 128)];
        k16[(size_t)t * (NH * D_QK) + i] = __float2half_rn(v);
    }
}

// build VT plane (single fp16): vt[h][d][t]
__global__ __launch_bounds__(256) void build_vt_kernel(
    const float* __restrict__ kvbuf, __half* __restrict__ vt16)
{
    __shared__ float tile[32][33];
    const int h = blockIdx.z;
    const int d0 = blockIdx.y * 32;
    const int t0 = blockIdx.x * 32;
    const int x = threadIdx.x, y = threadIdx.y;
#pragma unroll
    for (int j = 0; j < 32; j += 8)
        tile[y + j][x] = kvbuf[(size_t)(t0 + y + j) * (NH * 256) + h * 256 + 128 + d0 + x];
    __syncthreads();
#pragma unroll
    for (int j = 0; j < 32; j += 8)
        vt16[((size_t)h * D_V + d0 + y + j) * T_TOK + t0 + x] = __float2half_rn(tile[x][y + j]);
}

// ---------------- fp16 1-product GEMM, fp32 out (BN=64) ----------------
#define PITCH_B 80
#define F_A   0
#define F_B   20480
#define F_STAGE 25600
#define F_SMEM  (2 * F_STAGE)

__global__ __launch_bounds__(256, 2) void gemm_f16(
    const __half* __restrict__ Ah, const __half* __restrict__ Bh,
    float* __restrict__ C, int M, int N, int K)
{
    extern __shared__ __align__(128) char smx[];
    const uint32_t sbase = smem_u32(smx);
    const int tid  = threadIdx.x;
    const int warp = tid >> 5;
    const int lane = tid & 31;
    const int wm   = warp >> 1;
    const int wn   = warp & 1;
    const int row0 = blockIdx.y * 256;
    const int col0 = blockIdx.x * 64;

    float c[16][4];
#pragma unroll
    for (int i = 0; i < 16; i++)
#pragma unroll
        for (int j = 0; j < 4; j++) c[i][j] = 0.f;

    auto fill = [&](int stage, int k0) {
        char* st = smx + stage * F_STAGE;
#pragma unroll
        for (int rep = 0; rep < 4; rep++) {
            const int cch = tid + rep * 256;
            const int r = cch >> 2, q = cch & 3;
            const size_t src = (size_t)(row0 + r) * K + k0 + q * 8;
            cp16(st + F_A + r * PITCH_B + q * 16, Ah + src);
        }
        {
            const int r = tid >> 2, q = tid & 3;
            const size_t src = (size_t)(col0 + r) * K + k0 + q * 8;
            cp16(st + F_B + r * PITCH_B + q * 16, Bh + src);
        }
    };

    fill(0, 0);
    CP_COMMIT();

    const int nch = K >> 5;
    const int rowL = (lane & 7) + (lane & 8);
    const int kbL  = (lane >> 4) * 16;

    for (int ch = 0; ch < nch; ch++) {
        const int buf = ch & 1;
        if (ch + 1 < nch) {
            fill(buf ^ 1, (ch + 1) * 32);
            CP_COMMIT();
            CP_WAIT1();
        } else {
            CP_WAIT0();
        }
        __syncthreads();

        const uint32_t sA = sbase + buf * F_STAGE + F_A;
        const uint32_t sB = sbase + buf * F_STAGE + F_B;

#pragma unroll
        for (int kk = 0; kk < 2; kk++) {
            const int kb = kk * 32 + kbL;
            uint32_t bh[2][4];
#pragma unroll
            for (int j = 0; j < 2; j++) {
                const int rB = (wn * 32 + j * 16 + rowL) * PITCH_B + kb;
                LDSM4(bh[j][0], bh[j][1], bh[j][2], bh[j][3], sB + rB);
            }
#pragma unroll
            for (int i = 0; i < 4; i++) {
                const int rA = (wm * 64 + i * 16 + rowL) * PITCH_B + kb;
                uint32_t a0, a1, a2, a3;
                LDSM4(a0, a1, a2, a3, sA + rA);
#pragma unroll
                for (int f = 0; f < 4; f++) {
                    const int j = f >> 1, h = f & 1;
                    mma_f16(c[i * 4 + f], a0, a1, a2, a3, bh[j][h], bh[j][h + 2]);
                }
            }
        }
        __syncthreads();
    }

    const int qr = lane >> 2, qc = 2 * (lane & 3);
#pragma unroll
    for (int i = 0; i < 4; i++) {
#pragma unroll
        for (int f = 0; f < 4; f++) {
            const int r   = row0 + wm * 64 + i * 16 + qr;
            const int col = col0 + wn * 32 + f * 8 + qc;
            *(float2*)(C + (size_t)r * N + col)       = make_float2(c[i * 4 + f][0], c[i * 4 + f][1]);
            *(float2*)(C + (size_t)(r + 8) * N + col) = make_float2(c[i * 4 + f][2], c[i * 4 + f][3]);
        }
    }
}

// ---------------- fp16 1-product GEMM, BN=96, 512 threads, single-f16 out ----------------
#define G96_A   0
#define G96_B   20480
#define G96_STAGE 28160       // 20480 + 96*80
#define G96_SMEM (2 * G96_STAGE)

__global__ __launch_bounds__(512, 2) void gemm96_f16(
    const __half* __restrict__ Ah, const __half* __restrict__ Bh,
    uint32_t* __restrict__ Cq, int M, int N, int K)
{
    extern __shared__ __align__(128) char smx[];
    const uint32_t sbase = smem_u32(smx);
    const int tid  = threadIdx.x;
    const int warp = tid >> 5;       // 0..15
    const int lane = tid & 31;
    const int wm   = warp >> 1;      // 0..7 -> rows wm*32
    const int wn   = warp & 1;       // 0..1 -> cols wn*48
    const int row0 = blockIdx.y * 256;
    const int col0 = blockIdx.x * 96;

    float c[12][4];
#pragma unroll
    for (int i = 0; i < 12; i++)
#pragma unroll
        for (int j = 0; j < 4; j++) c[i][j] = 0.f;

    auto fill = [&](int stage, int k0) {
        char* st = smx + stage * G96_STAGE;
#pragma unroll
        for (int rep = 0; rep < 2; rep++) {
            const int cch = tid + rep * 512;   // 0..1023
            const int r = cch >> 2, q = cch & 3;
            const size_t src = (size_t)(row0 + r) * K + k0 + q * 8;
            cp16(st + G96_A + r * PITCH_B + q * 16, Ah + src);
        }
        if (tid < 384) {
            const int r = tid >> 2, q = tid & 3;   // 96 rows x 4 chunks
            const size_t src = (size_t)(col0 + r) * K + k0 + q * 8;
            cp16(st + G96_B + r * PITCH_B + q * 16, Bh + src);
        }
    };

    fill(0, 0);
    CP_COMMIT();

    const int nch = K >> 5;
    const int rowL = (lane & 7) + (lane & 8);
    const int kbL  = (lane >> 4) * 16;

    for (int ch = 0; ch < nch; ch++) {
        const int buf = ch & 1;
        if (ch + 1 < nch) {
            fill(buf ^ 1, (ch + 1) * 32);
            CP_COMMIT();
            CP_WAIT1();
        } else {
            CP_WAIT0();
        }
        __syncthreads();

        const uint32_t sA = sbase + buf * G96_STAGE + G96_A;
        const uint32_t sB = sbase + buf * G96_STAGE + G96_B;

#pragma unroll
        for (int kk = 0; kk < 2; kk++) {
            const int kb = kk * 32 + kbL;
            uint32_t bh[3][4];
#pragma unroll
            for (int j = 0; j < 3; j++) {
                const int rB = (wn * 48 + j * 16 + rowL) * PITCH_B + kb;
                LDSM4(bh[j][0], bh[j][1], bh[j][2], bh[j][3], sB + rB);
            }
#pragma unroll
            for (int i = 0; i < 2; i++) {
                const int rA = (wm * 32 + i * 16 + rowL) * PITCH_B + kb;
                uint32_t a0, a1, a2, a3;
                LDSM4(a0, a1, a2, a3, sA + rA);
#pragma unroll
                for (int f = 0; f < 6; f++) {
                    const int j = f >> 1, h = f & 1;
                    mma_f16(c[i * 6 + f], a0, a1, a2, a3, bh[j][h], bh[j][h + 2]);
                }
            }
        }
        __syncthreads();
    }

    const int qr = lane >> 2, qc = 2 * (lane & 3);
#pragma unroll
    for (int i = 0; i < 2; i++) {
#pragma unroll
        for (int f = 0; f < 6; f++) {
            const int j = f >> 1, h = f & 1;
            const int r   = row0 + wm * 32 + i * 16 + qr;
            const int col = col0 + wn * 48 + j * 16 + h * 8 + qc;
            const float* a = c[i * 6 + f];
            Cq[((size_t)r * N + col) >> 1] =
                pack2h(__float2half_rn(a[0]), __float2half_rn(a[1]));
            Cq[((size_t)(r + 8) * N + col) >> 1] =
                pack2h(__float2half_rn(a[2]), __float2half_rn(a[3]));
        }
    }
}

// ---------------- RMSNorm -> single fp16 ----------------
__global__ __launch_bounds__(256) void rmsnorm_kernel(
    const float* __restrict__ in, int ld, int off, int width,
    const float* __restrict__ gamma, __half* __restrict__ o16)
{
    const int row = blockIdx.x;
    const float* x = in + (size_t)row * ld + off;
    float ss = 0.f;
    for (int i = threadIdx.x; i < width; i += 256) {
        float v = x[i];
        ss += v * v;
    }
#pragma unroll
    for (int o = 16; o; o >>= 1) ss += __shfl_xor_sync(0xffffffffu, ss, o);
    __shared__ float warp_s[8];
    __shared__ float s_inv;
    if ((threadIdx.x & 31) == 0) warp_s[threadIdx.x >> 5] = ss;
    __syncthreads();
    if (threadIdx.x == 0) {
        float t = 0.f;
#pragma unroll
        for (int i = 0; i < 8; i++) t += warp_s[i];
        s_inv = rsqrtf(t / (float)width + 1e-6f);
    }
    __syncthreads();
    const float inv = s_inv;
    for (int i = threadIdx.x; i < width; i += 256)
        o16[(size_t)row * width + i] = __float2half_rn(x[i] * inv * gamma[i]);
}

// ---------------- RoPE on single fp16 Q plane + kpe from fp32 ----------------
__global__ __launch_bounds__(256) void rope_q16_kernel(
    uint32_t* __restrict__ q16,
    const float* __restrict__ qkv_a, float* __restrict__ kpe,
    const int* __restrict__ positions)
{
    const int t = blockIdx.x;
    const float pos = (float)positions[t];
    for (int i = threadIdx.x; i < NH * 32 + 32; i += 256) {
        if (i < NH * 32) {
            const int h = i >> 5, p = i & 31;
            const float inv = powf(10000.0f, -(float)p / 32.0f);
            float s, c;
            sincosf(pos * inv, &s, &c);
            const size_t idx = ((size_t)t * (NH * D_QK) + h * D_QK + D_NOPE + 2 * p) >> 1;
            const uint32_t w = q16[idx];
            const float x1 = __half2float(__ushort_as_half((unsigned short)(w & 0xffff)));
            const float x2 = __half2float(__ushort_as_half((unsigned short)(w >> 16)));
            q16[idx] = pack2h(__float2half_rn(x1 * c - x2 * s),
                              __float2half_rn(x1 * s + x2 * c));
        } else {
            const int p = i - NH * 32;
            const float inv = powf(10000.0f, -(float)p / 32.0f);
            float s, c;
            sincosf(pos * inv, &s, &c);
            const float* src = qkv_a + (size_t)t * QKV_A_N + (Q_LORA + KV_LORA);
            const float x1 = src[2 * p], x2 = src[2 * p + 1];
            kpe[(size_t)t * D_ROPE + 2 * p]     = x1 * c - x2 * s;
            kpe[(size_t)t * D_ROPE + 2 * p + 1] = x1 * s + x2 * c;
        }
    }
}

// ---------------- fp16 causal flash attention (occ 2, R14 proven) ----------------
#define SQ  0
#define SK  25600
#define SV  51200
#define SPH 69632
#define SSTAT 78848
#define ATT_SMEM (SSTAT + 1792)   // 80640 B -> 2 CTAs/SM

__global__ __launch_bounds__(256, 2) void attn_f16_kernel(
    const __half* __restrict__ q16,
    const __half* __restrict__ k16, const __half* __restrict__ vt16,
    uint32_t* __restrict__ o16)
{
    extern __shared__ __align__(128) char sma[];
    const uint32_t sb = smem_u32(sma);
    float* sWmax  = (float*)(sma + SSTAT);
    float* sWsum  = sWmax + 128;
    float* sM     = sWsum + 128;
    float* sL     = sM + 64;
    float* sScale = sL + 64;

    const int h    = blockIdx.y;
    const int qt   = (int)gridDim.x - 1 - (int)blockIdx.x;   // longest-first
    const int t0   = qt * 64;
    const int tid  = threadIdx.x;
    const int w    = tid >> 5;
    const int lane = tid & 31;
    const int g    = lane >> 2;
    const int t    = lane & 3;
    const int mrow = (w & 3) * 16;
    const int nhalf = w >> 2;
    const int r0 = mrow + g, r1 = r0 + 8;

    // Q tile (once): 64 rows x 24 chunks of 16B
    for (int i = tid; i < 1536; i += 256) {
        const int r = i / 24, c = i - r * 24;
        const size_t src = (size_t)(t0 + r) * (NH * D_QK) + h * D_QK + c * 8;
        cp16(sma + SQ + r * 400 + c * 16, q16 + src);
    }
    CP_COMMIT();
    if (tid < 64) { sM[tid] = -1e30f; sL[tid] = 0.f; }

    float o[8][4];
#pragma unroll
    for (int i = 0; i < 8; i++)
#pragma unroll
        for (int j = 0; j < 4; j++) o[i][j] = 0.f;

    const int rowL = (lane & 7) + (lane & 8);
    const int kbL  = (lane >> 4) * 16;

    for (int kt = 0; kt <= qt; kt++) {
        const int k0 = kt * 64;
        __syncthreads();
        for (int i = tid; i < 1536; i += 256) {
            const int r = i / 24, c = i - r * 24;
            const size_t src = (size_t)(k0 + r) * (NH * D_QK) + h * D_QK + c * 8;
            cp16(sma + SK + r * 400 + c * 16, k16 + src);
        }
        for (int i = tid; i < 1024; i += 256) {
            const int r = i >> 3, c = i & 7;
            const size_t src = ((size_t)h * D_V + r) * T_TOK + k0 + c * 8;
            cp16(sma + SV + r * 144 + c * 16, vt16 + src);
        }
        CP_COMMIT();
        CP_WAIT0();
        __syncthreads();

        // ---- S = Q @ K^T ----
        float s[4][4];
#pragma unroll
        for (int nt = 0; nt < 4; nt++)
#pragma unroll
            for (int j = 0; j < 4; j++) s[nt][j] = 0.f;

#pragma unroll 3
        for (int ks = 0; ks < 12; ks++) {
            const int kb = ks * 32 + kbL;
            uint32_t a0, a1, a2, a3;
            const int rA = (mrow + rowL) * 400 + kb;
            LDSM4(a0, a1, a2, a3, sb + SQ + rA);
            uint32_t bh[2][4];
#pragma unroll
            for (int j = 0; j < 2; j++) {
                const int rB = (nhalf * 32 + j * 16 + rowL) * 400 + kb;
                LDSM4(bh[j][0], bh[j][1], bh[j][2], bh[j][3], sb + SK + rB);
            }
#pragma unroll
            for (int nt = 0; nt < 4; nt++) {
                const int j = nt >> 1, hh = nt & 1;
                mma_f16(s[nt], a0, a1, a2, a3, bh[j][hh], bh[j][hh + 2]);
            }
        }

        const int rg0 = t0 + r0, rg1 = t0 + r1;
#pragma unroll
        for (int nt = 0; nt < 4; nt++) {
            const int cg = k0 + nhalf * 32 + nt * 8 + 2 * t;
            s[nt][0] = (rg0 >= cg)     ? s[nt][0] * SCALING : -1e30f;
            s[nt][1] = (rg0 >= cg + 1) ? s[nt][1] * SCALING : -1e30f;
            s[nt][2] = (rg1 >= cg)     ? s[nt][2] * SCALING : -1e30f;
            s[nt][3] = (rg1 >= cg + 1) ? s[nt][3] * SCALING : -1e30f;
        }

        float mx0 = -1e30f, mx1 = -1e30f;
#pragma unroll
        for (int nt = 0; nt < 4; nt++) {
            mx0 = fmaxf(mx0, fmaxf(s[nt][0], s[nt][1]));
            mx1 = fmaxf(mx1, fmaxf(s[nt][2], s[nt][3]));
        }
        mx0 = fmaxf(mx0, __shfl_xor_sync(0xffffffffu, mx0, 1));
        mx0 = fmaxf(mx0, __shfl_xor_sync(0xffffffffu, mx0, 2));
        mx1 = fmaxf(mx1, __shfl_xor_sync(0xffffffffu, mx1, 1));
        mx1 = fmaxf(mx1, __shfl_xor_sync(0xffffffffu, mx1, 2));
        if (t == 0) { sWmax[nhalf * 64 + r0] = mx0; sWmax[nhalf * 64 + r1] = mx1; }
        __syncthreads();

        const float mn0 = fmaxf(sM[r0], fmaxf(sWmax[r0], sWmax[64 + r0]));
        const float mn1 = fmaxf(sM[r1], fmaxf(sWmax[r1], sWmax[64 + r1]));

        float sum0 = 0.f, sum1 = 0.f;
#pragma unroll
        for (int nt = 0; nt < 4; nt++) {
            s[nt][0] = __expf(s[nt][0] - mn0);
            s[nt][1] = __expf(s[nt][1] - mn0);
            s[nt][2] = __expf(s[nt][2] - mn1);
            s[nt][3] = __expf(s[nt][3] - mn1);
            sum0 += s[nt][0] + s[nt][1];
            sum1 += s[nt][2] + s[nt][3];
            const int coll = nhalf * 32 + nt * 8 + 2 * t;
            *(uint32_t*)(sma + SPH + r0 * 144 + coll * 2) =
                pack2h(__float2half_rn(s[nt][0]), __float2half_rn(s[nt][1]));
            *(uint32_t*)(sma + SPH + r1 * 144 + coll * 2) =
                pack2h(__float2half_rn(s[nt][2]), __float2half_rn(s[nt][3]));
        }
        sum0 += __shfl_xor_sync(0xffffffffu, sum0, 1);
        sum0 += __shfl_xor_sync(0xffffffffu, sum0, 2);
        sum1 += __shfl_xor_sync(0xffffffffu, sum1, 1);
        sum1 += __shfl_xor_sync(0xffffffffu, sum1, 2);
        if (t == 0) { sWsum[nhalf * 64 + r0] = sum0; sWsum[nhalf * 64 + r1] = sum1; }
        __syncthreads();

        if (tid < 64) {
            const float mo = sM[tid];
            const float mn = fmaxf(mo, fmaxf(sWmax[tid], sWmax[64 + tid]));
            const float sc = __expf(mo - mn);
            sM[tid] = mn;
            sL[tid] = sL[tid] * sc + sWsum[tid] + sWsum[64 + tid];
            sScale[tid] = sc;
        }
        __syncthreads();

        const float sc0 = sScale[r0], sc1 = sScale[r1];
#pragma unroll
        for (int nt = 0; nt < 8; nt++) {
            o[nt][0] *= sc0; o[nt][1] *= sc0;
            o[nt][2] *= sc1; o[nt][3] *= sc1;
        }

        // ---- O += P @ V ----
#pragma unroll
        for (int ks = 0; ks < 4; ks++) {
            const int kb = ks * 32 + kbL;
            uint32_t ph0, ph1, ph2, ph3;
            const int rP = (mrow + rowL) * 144 + kb;
            LDSM4(ph0, ph1, ph2, ph3, sb + SPH + rP);
#pragma unroll
            for (int j2 = 0; j2 < 4; j2++) {
                const int rV = (nhalf * 64 + j2 * 16 + rowL) * 144 + kb;
                uint32_t vh[4];
                LDSM4(vh[0], vh[1], vh[2], vh[3], sb + SV + rV);
#pragma unroll
                for (int hh = 0; hh < 2; hh++)
                    mma_f16(o[j2 * 2 + hh], ph0, ph1, ph2, ph3, vh[hh], vh[hh + 2]);
            }
        }
    }

    // epilogue -> single fp16 plane
    const float il0 = 1.f / sL[r0];
    const float il1 = 1.f / sL[r1];
#pragma unroll
    for (int nt = 0; nt < 8; nt++) {
        const int col = h * D_V + nhalf * 64 + nt * 8 + 2 * t;
        o16[((size_t)(t0 + r0) * (NH * D_V) + col) >> 1] =
            pack2h(__float2half_rn(o[nt][0] * il0), __float2half_rn(o[nt][1] * il0));
        o16[((size_t)(t0 + r1) * (NH * D_V) + col) >> 1] =
            pack2h(__float2half_rn(o[nt][2] * il1), __float2half_rn(o[nt][3] * il1));
    }
}

// ---------------- launch ----------------
extern "C" void kernel_launch(void* const* d_in, const int* in_sizes, int n_in,
                              void* d_out, int out_size)
{
    const float* hidden    = (const float*)d_in[0];
    const int*   positions = (const int*)  d_in[1];
    const float* w_qkv_a   = (const float*)d_in[2];
    const float* gamma_q   = (const float*)d_in[3];
    const float* w_q_b     = (const float*)d_in[4];
    const float* gamma_kv  = (const float*)d_in[5];
    const float* w_kv_b    = (const float*)d_in[6];
    const float* w_o       = (const float*)d_in[7];
    float* out = (float*)d_out;

    float *qkv_a, *kvbuf, *kpe;
    __half *hid16, *qn16, *kvn16, *at16;
    __half *wa, *wqb, *wkvb, *wo;
    __half *q16, *k16, *vt16;
    cudaGetSymbolAddress((void**)&qkv_a, g_qkv_a);
    cudaGetSymbolAddress((void**)&kvbuf, g_kvbuf);
    cudaGetSymbolAddress((void**)&kpe,   g_kpe);
    cudaGetSymbolAddress((void**)&hid16, g_hid_f16);
    cudaGetSymbolAddress((void**)&qn16,  g_qn_f16);
    cudaGetSymbolAddress((void**)&kvn16, g_kvn_f16);
    cudaGetSymbolAddress((void**)&at16,  g_at_f16);
    cudaGetSymbolAddress((void**)&wa,    g_wa_f16);
    cudaGetSymbolAddress((void**)&wqb,   g_wqb_f16);
    cudaGetSymbolAddress((void**)&wkvb,  g_wkvb_f16);
    cudaGetSymbolAddress((void**)&wo,    g_wo_f16);
    cudaGetSymbolAddress((void**)&q16,   g_q_f16);
    cudaGetSymbolAddress((void**)&k16,   g_k_f16);
    cudaGetSymbolAddress((void**)&vt16,  g_vt_f16);

    cudaFuncSetAttribute(gemm_f16,   cudaFuncAttributeMaxDynamicSharedMemorySize, F_SMEM);
    cudaFuncSetAttribute(gemm96_f16, cudaFuncAttributeMaxDynamicSharedMemorySize, G96_SMEM);
    cudaFuncSetAttribute(attn_f16_kernel, cudaFuncAttributeMaxDynamicSharedMemorySize, ATT_SMEM);

    // 0) one-time conversions
    convert_f16_kernel<<<1184, 256>>>((const float2*)hidden,
        (uint32_t*)hid16, T_TOK * HID / 2);
    transpose_cvt_f16_kernel<<<dim3(QKV_A_N / 32, HID / 32),      dim3(32, 8)>>>(w_qkv_a, wa,   HID,      QKV_A_N);
    transpose_cvt_f16_kernel<<<dim3((NH*D_QK) / 32, Q_LORA / 32), dim3(32, 8)>>>(w_q_b,   wqb,  Q_LORA,   NH * D_QK);
    transpose_cvt_f16_kernel<<<dim3((NH*256) / 32, KV_LORA / 32), dim3(32, 8)>>>(w_kv_b,  wkvb, KV_LORA,  NH * 256);
    transpose_cvt_f16_kernel<<<dim3(HID / 32, (NH*D_V) / 32),     dim3(32, 8)>>>(w_o,     wo,   NH * D_V, HID);

    // 1) qkv_a = hidden @ w_qkv_a   (fp32 out)
    gemm_f16<<<dim3(QKV_A_N / 64, T_TOK / 256), 256, F_SMEM>>>(
        hid16, wa, qkv_a, T_TOK, QKV_A_N, HID);

    // 2) RMSNorm -> single fp16
    rmsnorm_kernel<<<T_TOK, 256>>>(qkv_a, QKV_A_N, 0,      Q_LORA,  gamma_q,  qn16);
    rmsnorm_kernel<<<T_TOK, 256>>>(qkv_a, QKV_A_N, Q_LORA, KV_LORA, gamma_kv, kvn16);

    // 3) q = qn @ w_q_b -> single fp16 Q plane
    gemm96_f16<<<dim3((NH * D_QK) / 96, T_TOK / 256), 512, G96_SMEM>>>(
        qn16, wqb, (uint32_t*)q16, T_TOK, NH * D_QK, Q_LORA);

    // 4) kv = kvn @ w_kv_b  (fp32 out)
    gemm_f16<<<dim3((NH * 256) / 64, T_TOK / 256), 256, F_SMEM>>>(
        kvn16, wkvb, kvbuf, T_TOK, NH * 256, KV_LORA);

    // 5) RoPE in-place on Q plane; kpe from qkv_a
    rope_q16_kernel<<<T_TOK, 256>>>((uint32_t*)q16, qkv_a, kpe, positions);

    // 6) K / VT planes
    build_k_kernel<<<T_TOK, 256>>>(kvbuf, kpe, k16);
    build_vt_kernel<<<dim3(T_TOK / 32, D_V / 32, NH), dim3(32, 8)>>>(kvbuf, vt16);

    // 7) attention -> single fp16 plane
    attn_f16_kernel<<<dim3(T_TOK / 64, NH), 256, ATT_SMEM>>>(
        q16, k16, vt16, (uint32_t*)at16);

    // 8) out = attn @ w_o  (fp32 out)
    gemm_f16<<<dim3(HID / 64, T_TOK / 256), 256, F_SMEM>>>(
        at16, wo, out, T_TOK, HID, NH * D_V);
}

// round 16
// speedup vs baseline: 2.2138x; 1.0105x over previous
#include <cuda_runtime.h>
#include <cuda_fp16.h>
#include <math.h>
#include <stdint.h>

// ---------------- problem constants ----------------
#define T_TOK   2048
#define HID     2048
#define NH      16
#define D_NOPE  128
#define D_ROPE  64
#define D_QK    192
#define D_V     128
#define Q_LORA  1536
#define KV_LORA 512
#define QKV_A_N 2112
#define SCALING 0.07216878364870322f   // 192^-0.5

// ---------------- scratch (all fp16 now) ----------------
__device__ __align__(128) __half g_qkv16  [T_TOK * QKV_A_N];
__device__ __align__(128) __half g_kv16   [T_TOK * NH * 256];
__device__ __align__(128) __half g_kpe16  [T_TOK * D_ROPE];
__device__ __align__(128) __half g_hid_f16 [T_TOK * HID];
__device__ __align__(128) __half g_qn_f16  [T_TOK * Q_LORA];
__device__ __align__(128) __half g_kvn_f16 [T_TOK * KV_LORA];
__device__ __align__(128) __half g_at_f16  [T_TOK * NH * D_V];
__device__ __align__(128) __half g_wa_f16  [QKV_A_N * HID];
__device__ __align__(128) __half g_wqb_f16 [NH * D_QK * Q_LORA];
__device__ __align__(128) __half g_wkvb_f16[NH * 256 * KV_LORA];
__device__ __align__(128) __half g_wo_f16  [HID * NH * D_V];
__device__ __align__(128) __half g_q_f16 [T_TOK * NH * D_QK];
__device__ __align__(128) __half g_k_f16 [T_TOK * NH * D_QK];
__device__ __align__(128) __half g_vt_f16[NH * D_V * T_TOK];

// ---------------- helpers ----------------
__device__ __forceinline__ void cp16(void* s, const void* g) {
    unsigned int sa = (unsigned int)__cvta_generic_to_shared(s);
    asm volatile("cp.async.cg.shared.global [%0], [%1], 16;" :: "r"(sa), "l"(g));
}
#define CP_COMMIT() asm volatile("cp.async.commit_group;")
#define CP_WAIT1()  asm volatile("cp.async.wait_group 1;")
#define CP_WAIT0()  asm volatile("cp.async.wait_group 0;")

__device__ __forceinline__ uint32_t smem_u32(const void* p) {
    return (uint32_t)__cvta_generic_to_shared(p);
}
#define LDSM4(r0, r1, r2, r3, a) \
    asm volatile("ldmatrix.sync.aligned.m8n8.x4.shared.b16 {%0,%1,%2,%3}, [%4];" \
        : "=r"(r0), "=r"(r1), "=r"(r2), "=r"(r3) : "r"(a))

__device__ __forceinline__ void mma_f16(float* c,
    uint32_t a0, uint32_t a1, uint32_t a2, uint32_t a3, uint32_t b0, uint32_t b1)
{
    asm volatile(
        "mma.sync.aligned.m16n8k16.row.col.f32.f16.f16.f32 "
        "{%0,%1,%2,%3},{%4,%5,%6,%7},{%8,%9},{%0,%1,%2,%3};"
        : "+f"(c[0]), "+f"(c[1]), "+f"(c[2]), "+f"(c[3])
        : "r"(a0), "r"(a1), "r"(a2), "r"(a3), "r"(b0), "r"(b1));
}

__device__ __forceinline__ uint32_t pack2h(__half a, __half b) {
    return (uint32_t)__half_as_ushort(a) | ((uint32_t)__half_as_ushort(b) << 16);
}

// ---------------- converters ----------------
__global__ __launch_bounds__(256) void convert_f16_kernel(
    const float2* __restrict__ src, uint32_t* __restrict__ dst, int n2)
{
    int i = blockIdx.x * 256 + threadIdx.x;
    const int stride = gridDim.x * 256;
    for (; i < n2; i += stride) {
        const float2 v = src[i];
        dst[i] = pack2h(__float2half_rn(v.x), __float2half_rn(v.y));
    }
}

// in fp32 [R][C] -> out single fp16 [C][R] (weights)
__global__ __launch_bounds__(256) void transpose_cvt_f16_kernel(
    const float* __restrict__ in, __half* __restrict__ outp, int R, int C)
{
    __shared__ float t[32][33];
    const int c0 = blockIdx.x * 32, r0 = blockIdx.y * 32;
    const int x = threadIdx.x, y = threadIdx.y;
#pragma unroll
    for (int j = 0; j < 32; j += 8)
        t[y + j][x] = in[(size_t)(r0 + y + j) * C + c0 + x];
    __syncthreads();
#pragma unroll
    for (int j = 0; j < 32; j += 8)
        outp[(size_t)(c0 + y + j) * R + r0 + x] = __float2half_rn(t[x][y + j]);
}

// build K plane (fp16 copy): k[t][h*192+d]
__global__ __launch_bounds__(256) void build_k_kernel(
    const __half* __restrict__ kv16, const __half* __restrict__ kpe16,
    __half* __restrict__ k16)
{
    const int t = blockIdx.x;
    for (int i = threadIdx.x; i < NH * D_QK; i += 256) {
        const int h = i / D_QK, d = i - h * D_QK;
        k16[(size_t)t * (NH * D_QK) + i] = (d < 128)
            ? kv16[(size_t)t * (NH * 256) + h * 256 + d]
            : kpe16[(size_t)t * D_ROPE + (d - 128)];
    }
}

// build VT plane (fp16 transpose): vt[h][d][t]
__global__ __launch_bounds__(256) void build_vt_kernel(
    const __half* __restrict__ kv16, __half* __restrict__ vt16)
{
    __shared__ __half tile[32][34];
    const int h = blockIdx.z;
    const int d0 = blockIdx.y * 32;
    const int t0 = blockIdx.x * 32;
    const int x = threadIdx.x, y = threadIdx.y;
#pragma unroll
    for (int j = 0; j < 32; j += 8)
        tile[y + j][x] = kv16[(size_t)(t0 + y + j) * (NH * 256) + h * 256 + 128 + d0 + x];
    __syncthreads();
#pragma unroll
    for (int j = 0; j < 32; j += 8)
        vt16[((size_t)h * D_V + d0 + y + j) * T_TOK + t0 + x] = tile[x][y + j];
}

// ---------------- fp16 1-product GEMM (BN=64), fp32 or fp16 out ----------------
#define PITCH_B 80
#define F_A   0
#define F_B   20480
#define F_STAGE 25600
#define F_SMEM  (2 * F_STAGE)

__global__ __launch_bounds__(256, 2) void gemm_f16(
    const __half* __restrict__ Ah, const __half* __restrict__ Bh,
    float* __restrict__ C, uint32_t* __restrict__ C16, int out16,
    int M, int N, int K)
{
    extern __shared__ __align__(128) char smx[];
    const uint32_t sbase = smem_u32(smx);
    const int tid  = threadIdx.x;
    const int warp = tid >> 5;
    const int lane = tid & 31;
    const int wm   = warp >> 1;
    const int wn   = warp & 1;
    const int row0 = blockIdx.y * 256;
    const int col0 = blockIdx.x * 64;

    float c[16][4];
#pragma unroll
    for (int i = 0; i < 16; i++)
#pragma unroll
        for (int j = 0; j < 4; j++) c[i][j] = 0.f;

    auto fill = [&](int stage, int k0) {
        char* st = smx + stage * F_STAGE;
#pragma unroll
        for (int rep = 0; rep < 4; rep++) {
            const int cch = tid + rep * 256;
            const int r = cch >> 2, q = cch & 3;
            const size_t src = (size_t)(row0 + r) * K + k0 + q * 8;
            cp16(st + F_A + r * PITCH_B + q * 16, Ah + src);
        }
        {
            const int r = tid >> 2, q = tid & 3;
            const size_t src = (size_t)(col0 + r) * K + k0 + q * 8;
            cp16(st + F_B + r * PITCH_B + q * 16, Bh + src);
        }
    };

    fill(0, 0);
    CP_COMMIT();

    const int nch = K >> 5;
    const int rowL = (lane & 7) + (lane & 8);
    const int kbL  = (lane >> 4) * 16;

    for (int ch = 0; ch < nch; ch++) {
        const int buf = ch & 1;
        if (ch + 1 < nch) {
            fill(buf ^ 1, (ch + 1) * 32);
            CP_COMMIT();
            CP_WAIT1();
        } else {
            CP_WAIT0();
        }
        __syncthreads();

        const uint32_t sA = sbase + buf * F_STAGE + F_A;
        const uint32_t sB = sbase + buf * F_STAGE + F_B;

#pragma unroll
        for (int kk = 0; kk < 2; kk++) {
            const int kb = kk * 32 + kbL;
            uint32_t bh[2][4];
#pragma unroll
            for (int j = 0; j < 2; j++) {
                const int rB = (wn * 32 + j * 16 + rowL) * PITCH_B + kb;
                LDSM4(bh[j][0], bh[j][1], bh[j][2], bh[j][3], sB + rB);
            }
#pragma unroll
            for (int i = 0; i < 4; i++) {
                const int rA = (wm * 64 + i * 16 + rowL) * PITCH_B + kb;
                uint32_t a0, a1, a2, a3;
                LDSM4(a0, a1, a2, a3, sA + rA);
#pragma unroll
                for (int f = 0; f < 4; f++) {
                    const int j = f >> 1, h = f & 1;
                    mma_f16(c[i * 4 + f], a0, a1, a2, a3, bh[j][h], bh[j][h + 2]);
                }
            }
        }
        __syncthreads();
    }

    const int qr = lane >> 2, qc = 2 * (lane & 3);
    if (out16) {
#pragma unroll
        for (int i = 0; i < 4; i++) {
#pragma unroll
            for (int f = 0; f < 4; f++) {
                const int r   = row0 + wm * 64 + i * 16 + qr;
                const int col = col0 + wn * 32 + f * 8 + qc;
                const float* a = c[i * 4 + f];
                C16[((size_t)r * N + col) >> 1] =
                    pack2h(__float2half_rn(a[0]), __float2half_rn(a[1]));
                C16[((size_t)(r + 8) * N + col) >> 1] =
                    pack2h(__float2half_rn(a[2]), __float2half_rn(a[3]));
            }
        }
    } else {
#pragma unroll
        for (int i = 0; i < 4; i++) {
#pragma unroll
            for (int f = 0; f < 4; f++) {
                const int r   = row0 + wm * 64 + i * 16 + qr;
                const int col = col0 + wn * 32 + f * 8 + qc;
                *(float2*)(C + (size_t)r * N + col)       = make_float2(c[i * 4 + f][0], c[i * 4 + f][1]);
                *(float2*)(C + (size_t)(r + 8) * N + col) = make_float2(c[i * 4 + f][2], c[i * 4 + f][3]);
            }
        }
    }
}

// ---------------- fp16 1-product GEMM, BN=96, 512 threads, fp16 out ----------------
#define G96_A   0
#define G96_B   20480
#define G96_STAGE 28160
#define G96_SMEM (2 * G96_STAGE)

__global__ __launch_bounds__(512, 2) void gemm96_f16(
    const __half* __restrict__ Ah, const __half* __restrict__ Bh,
    uint32_t* __restrict__ Cq, int M, int N, int K)
{
    extern __shared__ __align__(128) char smx[];
    const uint32_t sbase = smem_u32(smx);
    const int tid  = threadIdx.x;
    const int warp = tid >> 5;
    const int lane = tid & 31;
    const int wm   = warp >> 1;
    const int wn   = warp & 1;
    const int row0 = blockIdx.y * 256;
    const int col0 = blockIdx.x * 96;

    float c[12][4];
#pragma unroll
    for (int i = 0; i < 12; i++)
#pragma unroll
        for (int j = 0; j < 4; j++) c[i][j] = 0.f;

    auto fill = [&](int stage, int k0) {
        char* st = smx + stage * G96_STAGE;
#pragma unroll
        for (int rep = 0; rep < 2; rep++) {
            const int cch = tid + rep * 512;
            const int r = cch >> 2, q = cch & 3;
            const size_t src = (size_t)(row0 + r) * K + k0 + q * 8;
            cp16(st + G96_A + r * PITCH_B + q * 16, Ah + src);
        }
        if (tid < 384) {
            const int r = tid >> 2, q = tid & 3;
            const size_t src = (size_t)(col0 + r) * K + k0 + q * 8;
            cp16(st + G96_B + r * PITCH_B + q * 16, Bh + src);
        }
    };

    fill(0, 0);
    CP_COMMIT();

    const int nch = K >> 5;
    const int rowL = (lane & 7) + (lane & 8);
    const int kbL  = (lane >> 4) * 16;

    for (int ch = 0; ch < nch; ch++) {
        const int buf = ch & 1;
        if (ch + 1 < nch) {
            fill(buf ^ 1, (ch + 1) * 32);
            CP_COMMIT();
            CP_WAIT1();
        } else {
            CP_WAIT0();
        }
        __syncthreads();

        const uint32_t sA = sbase + buf * G96_STAGE + G96_A;
        const uint32_t sB = sbase + buf * G96_STAGE + G96_B;

#pragma unroll
        for (int kk = 0; kk < 2; kk++) {
            const int kb = kk * 32 + kbL;
            uint32_t bh[3][4];
#pragma unroll
            for (int j = 0; j < 3; j++) {
                const int rB = (wn * 48 + j * 16 + rowL) * PITCH_B + kb;
                LDSM4(bh[j][0], bh[j][1], bh[j][2], bh[j][3], sB + rB);
            }
#pragma unroll
            for (int i = 0; i < 2; i++) {
                const int rA = (wm * 32 + i * 16 + rowL) * PITCH_B + kb;
                uint32_t a0, a1, a2, a3;
                LDSM4(a0, a1, a2, a3, sA + rA);
#pragma unroll
                for (int f = 0; f < 6; f++) {
                    const int j = f >> 1, h = f & 1;
                    mma_f16(c[i * 6 + f], a0, a1, a2, a3, bh[j][h], bh[j][h + 2]);
                }
            }
        }
        __syncthreads();
    }

    const int qr = lane >> 2, qc = 2 * (lane & 3);
#pragma unroll
    for (int i = 0; i < 2; i++) {
#pragma unroll
        for (int f = 0; f < 6; f++) {
            const int j = f >> 1, h = f & 1;
            const int r   = row0 + wm * 32 + i * 16 + qr;
            const int col = col0 + wn * 48 + j * 16 + h * 8 + qc;
            const float* a = c[i * 6 + f];
            Cq[((size_t)r * N + col) >> 1] =
                pack2h(__float2half_rn(a[0]), __float2half_rn(a[1]));
            Cq[((size_t)(r + 8) * N + col) >> 1] =
                pack2h(__float2half_rn(a[2]), __float2half_rn(a[3]));
        }
    }
}

// ---------------- fused RMSNorm (fp16 in, fp16 out), grid.y selects segment ----------------
__global__ __launch_bounds__(256) void rmsnorm2_kernel(
    const __half* __restrict__ in,
    const float* __restrict__ gq, const float* __restrict__ gkv,
    __half* __restrict__ oq, __half* __restrict__ okv)
{
    const int row = blockIdx.x;
    const int seg = blockIdx.y;
    const int off   = seg ? Q_LORA : 0;
    const int width = seg ? KV_LORA : Q_LORA;
    const float* gamma = seg ? gkv : gq;
    __half* o = seg ? okv : oq;

    const __half* x = in + (size_t)row * QKV_A_N + off;
    float ss = 0.f;
    for (int i = threadIdx.x; i < width; i += 256) {
        const float v = __half2float(x[i]);
        ss += v * v;
    }
#pragma unroll
    for (int oo = 16; oo; oo >>= 1) ss += __shfl_xor_sync(0xffffffffu, ss, oo);
    __shared__ float warp_s[8];
    __shared__ float s_inv;
    if ((threadIdx.x & 31) == 0) warp_s[threadIdx.x >> 5] = ss;
    __syncthreads();
    if (threadIdx.x == 0) {
        float t = 0.f;
#pragma unroll
        for (int i = 0; i < 8; i++) t += warp_s[i];
        s_inv = rsqrtf(t / (float)width + 1e-6f);
    }
    __syncthreads();
    const float inv = s_inv;
    for (int i = threadIdx.x; i < width; i += 256)
        o[(size_t)row * width + i] = __float2half_rn(__half2float(x[i]) * inv * gamma[i]);
}

// ---------------- RoPE on fp16 Q plane + kpe(fp16) from fp16 qkv ----------------
__global__ __launch_bounds__(256) void rope_q16_kernel(
    uint32_t* __restrict__ q16,
    const __half* __restrict__ qkv16, __half* __restrict__ kpe16,
    const int* __restrict__ positions)
{
    const int t = blockIdx.x;
    const float pos = (float)positions[t];
    for (int i = threadIdx.x; i < NH * 32 + 32; i += 256) {
        if (i < NH * 32) {
            const int h = i >> 5, p = i & 31;
            const float inv = powf(10000.0f, -(float)p / 32.0f);
            float s, c;
            sincosf(pos * inv, &s, &c);
            const size_t idx = ((size_t)t * (NH * D_QK) + h * D_QK + D_NOPE + 2 * p) >> 1;
            const uint32_t w = q16[idx];
            const float x1 = __half2float(__ushort_as_half((unsigned short)(w & 0xffff)));
            const float x2 = __half2float(__ushort_as_half((unsigned short)(w >> 16)));
            q16[idx] = pack2h(__float2half_rn(x1 * c - x2 * s),
                              __float2half_rn(x1 * s + x2 * c));
        } else {
            const int p = i - NH * 32;
            const float inv = powf(10000.0f, -(float)p / 32.0f);
            float s, c;
            sincosf(pos * inv, &s, &c);
            const __half* src = qkv16 + (size_t)t * QKV_A_N + (Q_LORA + KV_LORA);
            const float x1 = __half2float(src[2 * p]);
            const float x2 = __half2float(src[2 * p + 1]);
            kpe16[(size_t)t * D_ROPE + 2 * p]     = __float2half_rn(x1 * c - x2 * s);
            kpe16[(size_t)t * D_ROPE + 2 * p + 1] = __float2half_rn(x1 * s + x2 * c);
        }
    }
}

// ---------------- fp16 causal flash attention (occ 2, R15 proven) ----------------
#define SQ  0
#define SK  25600
#define SV  51200
#define SPH 69632
#define SSTAT 78848
#define ATT_SMEM (SSTAT + 1792)   // 80640 B -> 2 CTAs/SM

__global__ __launch_bounds__(256, 2) void attn_f16_kernel(
    const __half* __restrict__ q16,
    const __half* __restrict__ k16, const __half* __restrict__ vt16,
    uint32_t* __restrict__ o16)
{
    extern __shared__ __align__(128) char sma[];
    const uint32_t sb = smem_u32(sma);
    float* sWmax  = (float*)(sma + SSTAT);
    float* sWsum  = sWmax + 128;
    float* sM     = sWsum + 128;
    float* sL     = sM + 64;
    float* sScale = sL + 64;

    const int h    = blockIdx.y;
    const int qt   = (int)gridDim.x - 1 - (int)blockIdx.x;   // longest-first
    const int t0   = qt * 64;
    const int tid  = threadIdx.x;
    const int w    = tid >> 5;
    const int lane = tid & 31;
    const int g    = lane >> 2;
    const int t    = lane & 3;
    const int mrow = (w & 3) * 16;
    const int nhalf = w >> 2;
    const int r0 = mrow + g, r1 = r0 + 8;

    for (int i = tid; i < 1536; i += 256) {
        const int r = i / 24, c = i - r * 24;
        const size_t src = (size_t)(t0 + r) * (NH * D_QK) + h * D_QK + c * 8;
        cp16(sma + SQ + r * 400 + c * 16, q16 + src);
    }
    CP_COMMIT();
    if (tid < 64) { sM[tid] = -1e30f; sL[tid] = 0.f; }

    float o[8][4];
#pragma unroll
    for (int i = 0; i < 8; i++)
#pragma unroll
        for (int j = 0; j < 4; j++) o[i][j] = 0.f;

    const int rowL = (lane & 7) + (lane & 8);
    const int kbL  = (lane >> 4) * 16;

    for (int kt = 0; kt <= qt; kt++) {
        const int k0 = kt * 64;
        __syncthreads();
        for (int i = tid; i < 1536; i += 256) {
            const int r = i / 24, c = i - r * 24;
            const size_t src = (size_t)(k0 + r) * (NH * D_QK) + h * D_QK + c * 8;
            cp16(sma + SK + r * 400 + c * 16, k16 + src);
        }
        for (int i = tid; i < 1024; i += 256) {
            const int r = i >> 3, c = i & 7;
            const size_t src = ((size_t)h * D_V + r) * T_TOK + k0 + c * 8;
            cp16(sma + SV + r * 144 + c * 16, vt16 + src);
        }
        CP_COMMIT();
        CP_WAIT0();
        __syncthreads();

        float s[4][4];
#pragma unroll
        for (int nt = 0; nt < 4; nt++)
#pragma unroll
            for (int j = 0; j < 4; j++) s[nt][j] = 0.f;

#pragma unroll 3
        for (int ks = 0; ks < 12; ks++) {
            const int kb = ks * 32 + kbL;
            uint32_t a0, a1, a2, a3;
            const int rA = (mrow + rowL) * 400 + kb;
            LDSM4(a0, a1, a2, a3, sb + SQ + rA);
            uint32_t bh[2][4];
#pragma unroll
            for (int j = 0; j < 2; j++) {
                const int rB = (nhalf * 32 + j * 16 + rowL) * 400 + kb;
                LDSM4(bh[j][0], bh[j][1], bh[j][2], bh[j][3], sb + SK + rB);
            }
#pragma unroll
            for (int nt = 0; nt < 4; nt++) {
                const int j = nt >> 1, hh = nt & 1;
                mma_f16(s[nt], a0, a1, a2, a3, bh[j][hh], bh[j][hh + 2]);
            }
        }

        const int rg0 = t0 + r0, rg1 = t0 + r1;
#pragma unroll
        for (int nt = 0; nt < 4; nt++) {
            const int cg = k0 + nhalf * 32 + nt * 8 + 2 * t;
            s[nt][0] = (rg0 >= cg)     ? s[nt][0] * SCALING : -1e30f;
            s[nt][1] = (rg0 >= cg + 1) ? s[nt][1] * SCALING : -1e30f;
            s[nt][2] = (rg1 >= cg)     ? s[nt][2] * SCALING : -1e30f;
            s[nt][3] = (rg1 >= cg + 1) ? s[nt][3] * SCALING : -1e30f;
        }

        float mx0 = -1e30f, mx1 = -1e30f;
#pragma unroll
        for (int nt = 0; nt < 4; nt++) {
            mx0 = fmaxf(mx0, fmaxf(s[nt][0], s[nt][1]));
            mx1 = fmaxf(mx1, fmaxf(s[nt][2], s[nt][3]));
        }
        mx0 = fmaxf(mx0, __shfl_xor_sync(0xffffffffu, mx0, 1));
        mx0 = fmaxf(mx0, __shfl_xor_sync(0xffffffffu, mx0, 2));
        mx1 = fmaxf(mx1, __shfl_xor_sync(0xffffffffu, mx1, 1));
        mx1 = fmaxf(mx1, __shfl_xor_sync(0xffffffffu, mx1, 2));
        if (t == 0) { sWmax[nhalf * 64 + r0] = mx0; sWmax[nhalf * 64 + r1] = mx1; }
        __syncthreads();

        const float mn0 = fmaxf(sM[r0], fmaxf(sWmax[r0], sWmax[64 + r0]));
        const float mn1 = fmaxf(sM[r1], fmaxf(sWmax[r1], sWmax[64 + r1]));

        float sum0 = 0.f, sum1 = 0.f;
#pragma unroll
        for (int nt = 0; nt < 4; nt++) {
            s[nt][0] = __expf(s[nt][0] - mn0);
            s[nt][1] = __expf(s[nt][1] - mn0);
            s[nt][2] = __expf(s[nt][2] - mn1);
            s[nt][3] = __expf(s[nt][3] - mn1);
            sum0 += s[nt][0] + s[nt][1];
            sum1 += s[nt][2] + s[nt][3];
            const int coll = nhalf * 32 + nt * 8 + 2 * t;
            *(uint32_t*)(sma + SPH + r0 * 144 + coll * 2) =
                pack2h(__float2half_rn(s[nt][0]), __float2half_rn(s[nt][1]));
            *(uint32_t*)(sma + SPH + r1 * 144 + coll * 2) =
                pack2h(__float2half_rn(s[nt][2]), __float2half_rn(s[nt][3]));
        }
        sum0 += __shfl_xor_sync(0xffffffffu, sum0, 1);
        sum0 += __shfl_xor_sync(0xffffffffu, sum0, 2);
        sum1 += __shfl_xor_sync(0xffffffffu, sum1, 1);
        sum1 += __shfl_xor_sync(0xffffffffu, sum1, 2);
        if (t == 0) { sWsum[nhalf * 64 + r0] = sum0; sWsum[nhalf * 64 + r1] = sum1; }
        __syncthreads();

        if (tid < 64) {
            const float mo = sM[tid];
            const float mn = fmaxf(mo, fmaxf(sWmax[tid], sWmax[64 + tid]));
            const float sc = __expf(mo - mn);
            sM[tid] = mn;
            sL[tid] = sL[tid] * sc + sWsum[tid] + sWsum[64 + tid];
            sScale[tid] = sc;
        }
        __syncthreads();

        const float sc0 = sScale[r0], sc1 = sScale[r1];
#pragma unroll
        for (int nt = 0; nt < 8; nt++) {
            o[nt][0] *= sc0; o[nt][1] *= sc0;
            o[nt][2] *= sc1; o[nt][3] *= sc1;
        }

#pragma unroll
        for (int ks = 0; ks < 4; ks++) {
            const int kb = ks * 32 + kbL;
            uint32_t ph0, ph1, ph2, ph3;
            const int rP = (mrow + rowL) * 144 + kb;
            LDSM4(ph0, ph1, ph2, ph3, sb + SPH + rP);
#pragma unroll
            for (int j2 = 0; j2 < 4; j2++) {
                const int rV = (nhalf * 64 + j2 * 16 + rowL) * 144 + kb;
                uint32_t vh[4];
                LDSM4(vh[0], vh[1], vh[2], vh[3], sb + SV + rV);
#pragma unroll
                for (int hh = 0; hh < 2; hh++)
                    mma_f16(o[j2 * 2 + hh], ph0, ph1, ph2, ph3, vh[hh], vh[hh + 2]);
            }
        }
    }

    const float il0 = 1.f / sL[r0];
    const float il1 = 1.f / sL[r1];
#pragma unroll
    for (int nt = 0; nt < 8; nt++) {
        const int col = h * D_V + nhalf * 64 + nt * 8 + 2 * t;
        o16[((size_t)(t0 + r0) * (NH * D_V) + col) >> 1] =
            pack2h(__float2half_rn(o[nt][0] * il0), __float2half_rn(o[nt][1] * il0));
        o16[((size_t)(t0 + r1) * (NH * D_V) + col) >> 1] =
            pack2h(__float2half_rn(o[nt][2] * il1), __float2half_rn(o[nt][3] * il1));
    }
}

// ---------------- launch ----------------
extern "C" void kernel_launch(void* const* d_in, const int* in_sizes, int n_in,
                              void* d_out, int out_size)
{
    const float* hidden    = (const float*)d_in[0];
    const int*   positions = (const int*)  d_in[1];
    const float* w_qkv_a   = (const float*)d_in[2];
    const float* gamma_q   = (const float*)d_in[3];
    const float* w_q_b     = (const float*)d_in[4];
    const float* gamma_kv  = (const float*)d_in[5];
    const float* w_kv_b    = (const float*)d_in[6];
    const float* w_o       = (const float*)d_in[7];
    float* out = (float*)d_out;

    __half *qkv16, *kv16, *kpe16;
    __half *hid16, *qn16, *kvn16, *at16;
    __half *wa, *wqb, *wkvb, *wo;
    __half *q16, *k16, *vt16;
    cudaGetSymbolAddress((void**)&qkv16, g_qkv16);
    cudaGetSymbolAddress((void**)&kv16,  g_kv16);
    cudaGetSymbolAddress((void**)&kpe16, g_kpe16);
    cudaGetSymbolAddress((void**)&hid16, g_hid_f16);
    cudaGetSymbolAddress((void**)&qn16,  g_qn_f16);
    cudaGetSymbolAddress((void**)&kvn16, g_kvn_f16);
    cudaGetSymbolAddress((void**)&at16,  g_at_f16);
    cudaGetSymbolAddress((void**)&wa,    g_wa_f16);
    cudaGetSymbolAddress((void**)&wqb,   g_wqb_f16);
    cudaGetSymbolAddress((void**)&wkvb,  g_wkvb_f16);
    cudaGetSymbolAddress((void**)&wo,    g_wo_f16);
    cudaGetSymbolAddress((void**)&q16,   g_q_f16);
    cudaGetSymbolAddress((void**)&k16,   g_k_f16);
    cudaGetSymbolAddress((void**)&vt16,  g_vt_f16);

    cudaFuncSetAttribute(gemm_f16,   cudaFuncAttributeMaxDynamicSharedMemorySize, F_SMEM);
    cudaFuncSetAttribute(gemm96_f16, cudaFuncAttributeMaxDynamicSharedMemorySize, G96_SMEM);
    cudaFuncSetAttribute(attn_f16_kernel, cudaFuncAttributeMaxDynamicSharedMemorySize, ATT_SMEM);

    // 0) one-time conversions
    convert_f16_kernel<<<1184, 256>>>((const float2*)hidden,
        (uint32_t*)hid16, T_TOK * HID / 2);
    transpose_cvt_f16_kernel<<<dim3(QKV_A_N / 32, HID / 32),      dim3(32, 8)>>>(w_qkv_a, wa,   HID,      QKV_A_N);
    transpose_cvt_f16_kernel<<<dim3((NH*D_QK) / 32, Q_LORA / 32), dim3(32, 8)>>>(w_q_b,   wqb,  Q_LORA,   NH * D_QK);
    transpose_cvt_f16_kernel<<<dim3((NH*256) / 32, KV_LORA / 32), dim3(32, 8)>>>(w_kv_b,  wkvb, KV_LORA,  NH * 256);
    transpose_cvt_f16_kernel<<<dim3(HID / 32, (NH*D_V) / 32),     dim3(32, 8)>>>(w_o,     wo,   NH * D_V, HID);

    // 1) qkv = hidden @ w_qkv_a   (fp16 out)
    gemm_f16<<<dim3(QKV_A_N / 64, T_TOK / 256), 256, F_SMEM>>>(
        hid16, wa, 0, (uint32_t*)qkv16, 1, T_TOK, QKV_A_N, HID);

    // 2) fused RMSNorm (both segments, fp16 in/out)
    rmsnorm2_kernel<<<dim3(T_TOK, 2), 256>>>(qkv16, gamma_q, gamma_kv, qn16, kvn16);

    // 3) q = qn @ w_q_b -> fp16 Q plane (BN=96)
    gemm96_f16<<<dim3((NH * D_QK) / 96, T_TOK / 256), 512, G96_SMEM>>>(
        qn16, wqb, (uint32_t*)q16, T_TOK, NH * D_QK, Q_LORA);

    // 4) kv = kvn @ w_kv_b  (fp16 out)
    gemm_f16<<<dim3((NH * 256) / 64, T_TOK / 256), 256, F_SMEM>>>(
        kvn16, wkvb, 0, (uint32_t*)kv16, 1, T_TOK, NH * 256, KV_LORA);

    // 5) RoPE in-place on Q plane; kpe(fp16) from qkv16
    rope_q16_kernel<<<T_TOK, 256>>>((uint32_t*)q16, qkv16, kpe16, positions);

    // 6) K / VT planes (fp16 copies)
    build_k_kernel<<<T_TOK, 256>>>(kv16, kpe16, k16);
    build_vt_kernel<<<dim3(T_TOK / 32, D_V / 32, NH), dim3(32, 8)>>>(kv16, vt16);

    // 7) attention -> fp16 plane
    attn_f16_kernel<<<dim3(T_TOK / 64, NH), 256, ATT_SMEM>>>(
        q16, k16, vt16, (uint32_t*)at16);

    // 8) out = attn @ w_o  (fp32 out)
    gemm_f16<<<dim3(HID / 64, T_TOK / 256), 256, F_SMEM>>>(
        at16, wo, out, 0, 0, T_TOK, HID, NH * D_V);
}

// round 17
// speedup vs baseline: 2.2905x; 1.0347x over previous
#include <cuda_runtime.h>
#include <cuda_fp16.h>
#include <math.h>
#include <stdint.h>

// ---------------- problem constants ----------------
#define T_TOK   2048
#define HID     2048
#define NH      16
#define D_NOPE  128
#define D_ROPE  64
#define D_QK    192
#define D_V     128
#define Q_LORA  1536
#define KV_LORA 512
#define QKV_A_N 2112
#define SCALING 0.07216878364870322f   // 192^-0.5

// ---------------- scratch ----------------
__device__ __align__(128) __half g_qkv16  [T_TOK * QKV_A_N];
__device__ __align__(128) __half g_hid_f16 [T_TOK * HID];
__device__ __align__(128) __half g_qn_f16  [T_TOK * Q_LORA];
__device__ __align__(128) __half g_kvn_f16 [T_TOK * KV_LORA];
__device__ __align__(128) __half g_at_f16  [T_TOK * NH * D_V];
__device__ __align__(128) __half g_wa_f16  [QKV_A_N * HID];
__device__ __align__(128) __half g_wqb_f16 [NH * D_QK * Q_LORA];
__device__ __align__(128) __half g_wkvb_f16[NH * 256 * KV_LORA];
__device__ __align__(128) __half g_wo_f16  [HID * NH * D_V];
__device__ __align__(128) __half g_q_f16 [T_TOK * NH * D_QK];
__device__ __align__(128) __half g_k_f16 [T_TOK * NH * D_QK];
__device__ __align__(128) __half g_vt_f16[NH * D_V * T_TOK];

// ---------------- helpers ----------------
__device__ __forceinline__ void cp16(void* s, const void* g) {
    unsigned int sa = (unsigned int)__cvta_generic_to_shared(s);
    asm volatile("cp.async.cg.shared.global [%0], [%1], 16;" :: "r"(sa), "l"(g));
}
#define CP_COMMIT() asm volatile("cp.async.commit_group;")
#define CP_WAIT1()  asm volatile("cp.async.wait_group 1;")
#define CP_WAIT0()  asm volatile("cp.async.wait_group 0;")

__device__ __forceinline__ uint32_t smem_u32(const void* p) {
    return (uint32_t)__cvta_generic_to_shared(p);
}
#define LDSM4(r0, r1, r2, r3, a) \
    asm volatile("ldmatrix.sync.aligned.m8n8.x4.shared.b16 {%0,%1,%2,%3}, [%4];" \
        : "=r"(r0), "=r"(r1), "=r"(r2), "=r"(r3) : "r"(a))

__device__ __forceinline__ void mma_f16(float* c,
    uint32_t a0, uint32_t a1, uint32_t a2, uint32_t a3, uint32_t b0, uint32_t b1)
{
    asm volatile(
        "mma.sync.aligned.m16n8k16.row.col.f32.f16.f16.f32 "
        "{%0,%1,%2,%3},{%4,%5,%6,%7},{%8,%9},{%0,%1,%2,%3};"
        : "+f"(c[0]), "+f"(c[1]), "+f"(c[2]), "+f"(c[3])
        : "r"(a0), "r"(a1), "r"(a2), "r"(a3), "r"(b0), "r"(b1));
}

__device__ __forceinline__ uint32_t pack2h(__half a, __half b) {
    return (uint32_t)__half_as_ushort(a) | ((uint32_t)__half_as_ushort(b) << 16);
}

// ---------------- converters ----------------
__global__ __launch_bounds__(256) void convert_f16_kernel(
    const float2* __restrict__ src, uint32_t* __restrict__ dst, int n2)
{
    int i = blockIdx.x * 256 + threadIdx.x;
    const int stride = gridDim.x * 256;
    for (; i < n2; i += stride) {
        const float2 v = src[i];
        dst[i] = pack2h(__float2half_rn(v.x), __float2half_rn(v.y));
    }
}

__global__ __launch_bounds__(256) void transpose_cvt_f16_kernel(
    const float* __restrict__ in, __half* __restrict__ outp, int R, int C)
{
    __shared__ float t[32][33];
    const int c0 = blockIdx.x * 32, r0 = blockIdx.y * 32;
    const int x = threadIdx.x, y = threadIdx.y;
#pragma unroll
    for (int j = 0; j < 32; j += 8)
        t[y + j][x] = in[(size_t)(r0 + y + j) * C + c0 + x];
    __syncthreads();
#pragma unroll
    for (int j = 0; j < 32; j += 8)
        outp[(size_t)(c0 + y + j) * R + r0 + x] = __float2half_rn(t[x][y + j]);
}

// fill rope columns of K plane (all heads broadcast) from qkv16
__global__ __launch_bounds__(256) void fill_k_rope_kernel(
    const __half* __restrict__ qkv16, __half* __restrict__ k16,
    const int* __restrict__ positions)
{
    const int t = blockIdx.x;
    const float pos = (float)positions[t];
    for (int item = threadIdx.x; item < NH * 32; item += 256) {
        const int h = item >> 5, p = item & 31;
        const float inv = powf(10000.0f, -(float)p / 32.0f);
        float s, c;
        sincosf(pos * inv, &s, &c);
        const __half* src = qkv16 + (size_t)t * QKV_A_N + (Q_LORA + KV_LORA);
        const float x1 = __half2float(src[2 * p]);
        const float x2 = __half2float(src[2 * p + 1]);
        *(uint32_t*)(k16 + (size_t)t * (NH * D_QK) + h * D_QK + D_NOPE + 2 * p) =
            pack2h(__float2half_rn(x1 * c - x2 * s), __float2half_rn(x1 * s + x2 * c));
    }
}

// ---------------- fp16 1-product GEMM (BN=64) ----------------
// mode 0: fp32 out C; mode 1: fp16 out C16; mode 2: scatter K/VT (gemm4).
#define PITCH_B 80
#define F_A   0
#define F_B   20480
#define F_STAGE 25600
#define F_SMEM  (2 * F_STAGE)

__global__ __launch_bounds__(256, 2) void gemm_f16(
    const __half* __restrict__ Ah, const __half* __restrict__ Bh,
    float* __restrict__ C, uint32_t* __restrict__ C16,
    __half* __restrict__ Kp, __half* __restrict__ Vt,
    int mode, int M, int N, int K)
{
    extern __shared__ __align__(128) char smx[];
    const uint32_t sbase = smem_u32(smx);
    const int tid  = threadIdx.x;
    const int warp = tid >> 5;
    const int lane = tid & 31;
    const int wm   = warp >> 1;
    const int wn   = warp & 1;
    const int row0 = blockIdx.y * 256;
    const int col0 = blockIdx.x * 64;

    float c[16][4];
#pragma unroll
    for (int i = 0; i < 16; i++)
#pragma unroll
        for (int j = 0; j < 4; j++) c[i][j] = 0.f;

    auto fill = [&](int stage, int k0) {
        char* st = smx + stage * F_STAGE;
#pragma unroll
        for (int rep = 0; rep < 4; rep++) {
            const int cch = tid + rep * 256;
            const int r = cch >> 2, q = cch & 3;
            const size_t src = (size_t)(row0 + r) * K + k0 + q * 8;
            cp16(st + F_A + r * PITCH_B + q * 16, Ah + src);
        }
        {
            const int r = tid >> 2, q = tid & 3;
            const size_t src = (size_t)(col0 + r) * K + k0 + q * 8;
            cp16(st + F_B + r * PITCH_B + q * 16, Bh + src);
        }
    };

    fill(0, 0);
    CP_COMMIT();

    const int nch = K >> 5;
    const int rowL = (lane & 7) + (lane & 8);
    const int kbL  = (lane >> 4) * 16;

    for (int ch = 0; ch < nch; ch++) {
        const int buf = ch & 1;
        if (ch + 1 < nch) {
            fill(buf ^ 1, (ch + 1) * 32);
            CP_COMMIT();
            CP_WAIT1();
        } else {
            CP_WAIT0();
        }
        __syncthreads();

        const uint32_t sA = sbase + buf * F_STAGE + F_A;
        const uint32_t sB = sbase + buf * F_STAGE + F_B;

#pragma unroll
        for (int kk = 0; kk < 2; kk++) {
            const int kb = kk * 32 + kbL;
            uint32_t bh[2][4];
#pragma unroll
            for (int j = 0; j < 2; j++) {
                const int rB = (wn * 32 + j * 16 + rowL) * PITCH_B + kb;
                LDSM4(bh[j][0], bh[j][1], bh[j][2], bh[j][3], sB + rB);
            }
#pragma unroll
            for (int i = 0; i < 4; i++) {
                const int rA = (wm * 64 + i * 16 + rowL) * PITCH_B + kb;
                uint32_t a0, a1, a2, a3;
                LDSM4(a0, a1, a2, a3, sA + rA);
#pragma unroll
                for (int f = 0; f < 4; f++) {
                    const int j = f >> 1, h = f & 1;
                    mma_f16(c[i * 4 + f], a0, a1, a2, a3, bh[j][h], bh[j][h + 2]);
                }
            }
        }
        __syncthreads();
    }

    const int qr = lane >> 2, qc = 2 * (lane & 3);
    if (mode == 0) {
#pragma unroll
        for (int i = 0; i < 4; i++) {
#pragma unroll
            for (int f = 0; f < 4; f++) {
                const int r   = row0 + wm * 64 + i * 16 + qr;
                const int col = col0 + wn * 32 + f * 8 + qc;
                *(float2*)(C + (size_t)r * N + col)       = make_float2(c[i * 4 + f][0], c[i * 4 + f][1]);
                *(float2*)(C + (size_t)(r + 8) * N + col) = make_float2(c[i * 4 + f][2], c[i * 4 + f][3]);
            }
        }
    } else if (mode == 1) {
#pragma unroll
        for (int i = 0; i < 4; i++) {
#pragma unroll
            for (int f = 0; f < 4; f++) {
                const int r   = row0 + wm * 64 + i * 16 + qr;
                const int col = col0 + wn * 32 + f * 8 + qc;
                const float* a = c[i * 4 + f];
                C16[((size_t)r * N + col) >> 1] =
                    pack2h(__float2half_rn(a[0]), __float2half_rn(a[1]));
                C16[((size_t)(r + 8) * N + col) >> 1] =
                    pack2h(__float2half_rn(a[2]), __float2half_rn(a[3]));
            }
        }
    } else {
        // mode 2 (gemm4): col = h*256 + d. d<128 -> K plane; d>=128 -> VT plane.
#pragma unroll
        for (int i = 0; i < 4; i++) {
#pragma unroll
            for (int f = 0; f < 4; f++) {
                const int r   = row0 + wm * 64 + i * 16 + qr;
                const int col = col0 + wn * 32 + f * 8 + qc;
                const int h = col >> 8, d = col & 255;
                const float* a = c[i * 4 + f];
                if (d < 128) {
                    *(uint32_t*)(Kp + (size_t)r * (NH * D_QK) + h * D_QK + d) =
                        pack2h(__float2half_rn(a[0]), __float2half_rn(a[1]));
                    *(uint32_t*)(Kp + (size_t)(r + 8) * (NH * D_QK) + h * D_QK + d) =
                        pack2h(__float2half_rn(a[2]), __float2half_rn(a[3]));
                } else {
                    const int vd = d - 128;
                    __half* b0 = Vt + ((size_t)h * D_V + vd) * T_TOK;
                    __half* b1 = Vt + ((size_t)h * D_V + vd + 1) * T_TOK;
                    b0[r]     = __float2half_rn(a[0]);
                    b1[r]     = __float2half_rn(a[1]);
                    b0[r + 8] = __float2half_rn(a[2]);
                    b1[r + 8] = __float2half_rn(a[3]);
                }
            }
        }
    }
}

// ---------------- fp16 GEMM BN=96 + fused RoPE epilogue -> q16 ----------------
#define G96_A   0
#define G96_B   20480
#define G96_STAGE 28160
#define G96_SMEM (2 * G96_STAGE)

__global__ __launch_bounds__(512, 2) void gemm96_rope_f16(
    const __half* __restrict__ Ah, const __half* __restrict__ Bh,
    uint32_t* __restrict__ Cq, const int* __restrict__ positions,
    int M, int N, int K)
{
    extern __shared__ __align__(128) char smx[];
    const uint32_t sbase = smem_u32(smx);
    const int tid  = threadIdx.x;
    const int warp = tid >> 5;
    const int lane = tid & 31;
    const int wm   = warp >> 1;
    const int wn   = warp & 1;
    const int row0 = blockIdx.y * 256;
    const int col0 = blockIdx.x * 96;

    float c[12][4];
#pragma unroll
    for (int i = 0; i < 12; i++)
#pragma unroll
        for (int j = 0; j < 4; j++) c[i][j] = 0.f;

    auto fill = [&](int stage, int k0) {
        char* st = smx + stage * G96_STAGE;
#pragma unroll
        for (int rep = 0; rep < 2; rep++) {
            const int cch = tid + rep * 512;
            const int r = cch >> 2, q = cch & 3;
            const size_t src = (size_t)(row0 + r) * K + k0 + q * 8;
            cp16(st + G96_A + r * PITCH_B + q * 16, Ah + src);
        }
        if (tid < 384) {
            const int r = tid >> 2, q = tid & 3;
            const size_t src = (size_t)(col0 + r) * K + k0 + q * 8;
            cp16(st + G96_B + r * PITCH_B + q * 16, Bh + src);
        }
    };

    fill(0, 0);
    CP_COMMIT();

    const int nch = K >> 5;
    const int rowL = (lane & 7) + (lane & 8);
    const int kbL  = (lane >> 4) * 16;

    for (int ch = 0; ch < nch; ch++) {
        const int buf = ch & 1;
        if (ch + 1 < nch) {
            fill(buf ^ 1, (ch + 1) * 32);
            CP_COMMIT();
            CP_WAIT1();
        } else {
            CP_WAIT0();
        }
        __syncthreads();

        const uint32_t sA = sbase + buf * G96_STAGE + G96_A;
        const uint32_t sB = sbase + buf * G96_STAGE + G96_B;

#pragma unroll
        for (int kk = 0; kk < 2; kk++) {
            const int kb = kk * 32 + kbL;
            uint32_t bh[3][4];
#pragma unroll
            for (int j = 0; j < 3; j++) {
                const int rB = (wn * 48 + j * 16 + rowL) * PITCH_B + kb;
                LDSM4(bh[j][0], bh[j][1], bh[j][2], bh[j][3], sB + rB);
            }
#pragma unroll
            for (int i = 0; i < 2; i++) {
                const int rA = (wm * 32 + i * 16 + rowL) * PITCH_B + kb;
                uint32_t a0, a1, a2, a3;
                LDSM4(a0, a1, a2, a3, sA + rA);
#pragma unroll
                for (int f = 0; f < 6; f++) {
                    const int j = f >> 1, h = f & 1;
                    mma_f16(c[i * 6 + f], a0, a1, a2, a3, bh[j][h], bh[j][h + 2]);
                }
            }
        }
        __syncthreads();
    }

    const int qr = lane >> 2, qc = 2 * (lane & 3);
#pragma unroll
    for (int i = 0; i < 2; i++) {
#pragma unroll
        for (int f = 0; f < 6; f++) {
            const int j = f >> 1, h = f & 1;
            const int r   = row0 + wm * 32 + i * 16 + qr;
            const int col = col0 + wn * 48 + j * 16 + h * 8 + qc;
            const float* a = c[i * 6 + f];
            float v0 = a[0], v1 = a[1], v2 = a[2], v3 = a[3];
            const int d = col % D_QK;
            if (d >= D_NOPE) {
                const int p = (d - D_NOPE) >> 1;
                const float inv = powf(10000.0f, -(float)p / 32.0f);
                float s0, c0, s1, c1;
                sincosf((float)positions[r] * inv, &s0, &c0);
                sincosf((float)positions[r + 8] * inv, &s1, &c1);
                const float t0 = v0 * c0 - v1 * s0, t1 = v0 * s0 + v1 * c0;
                const float t2 = v2 * c1 - v3 * s1, t3 = v2 * s1 + v3 * c1;
                v0 = t0; v1 = t1; v2 = t2; v3 = t3;
            }
            Cq[((size_t)r * N + col) >> 1] =
                pack2h(__float2half_rn(v0), __float2half_rn(v1));
            Cq[((size_t)(r + 8) * N + col) >> 1] =
                pack2h(__float2half_rn(v2), __float2half_rn(v3));
        }
    }
}

// ---------------- fused RMSNorm (fp16 in, fp16 out) ----------------
__global__ __launch_bounds__(256) void rmsnorm2_kernel(
    const __half* __restrict__ in,
    const float* __restrict__ gq, const float* __restrict__ gkv,
    __half* __restrict__ oq, __half* __restrict__ okv)
{
    const int row = blockIdx.x;
    const int seg = blockIdx.y;
    const int off   = seg ? Q_LORA : 0;
    const int width = seg ? KV_LORA : Q_LORA;
    const float* gamma = seg ? gkv : gq;
    __half* o = seg ? okv : oq;

    const __half* x = in + (size_t)row * QKV_A_N + off;
    float ss = 0.f;
    for (int i = threadIdx.x; i < width; i += 256) {
        const float v = __half2float(x[i]);
        ss += v * v;
    }
#pragma unroll
    for (int oo = 16; oo; oo >>= 1) ss += __shfl_xor_sync(0xffffffffu, ss, oo);
    __shared__ float warp_s[8];
    __shared__ float s_inv;
    if ((threadIdx.x & 31) == 0) warp_s[threadIdx.x >> 5] = ss;
    __syncthreads();
    if (threadIdx.x == 0) {
        float t = 0.f;
#pragma unroll
        for (int i = 0; i < 8; i++) t += warp_s[i];
        s_inv = rsqrtf(t / (float)width + 1e-6f);
    }
    __syncthreads();
    const float inv = s_inv;
    for (int i = threadIdx.x; i < width; i += 256)
        o[(size_t)row * width + i] = __float2half_rn(__half2float(x[i]) * inv * gamma[i]);
}

// ---------------- fp16 causal flash attention (occ 2, proven) ----------------
#define SQ  0
#define SK  25600
#define SV  51200
#define SPH 69632
#define SSTAT 78848
#define ATT_SMEM (SSTAT + 1792)

__global__ __launch_bounds__(256, 2) void attn_f16_kernel(
    const __half* __restrict__ q16,
    const __half* __restrict__ k16, const __half* __restrict__ vt16,
    uint32_t* __restrict__ o16)
{
    extern __shared__ __align__(128) char sma[];
    const uint32_t sb = smem_u32(sma);
    float* sWmax  = (float*)(sma + SSTAT);
    float* sWsum  = sWmax + 128;
    float* sM     = sWsum + 128;
    float* sL     = sM + 64;
    float* sScale = sL + 64;

    const int h    = blockIdx.y;
    const int qt   = (int)gridDim.x - 1 - (int)blockIdx.x;
    const int t0   = qt * 64;
    const int tid  = threadIdx.x;
    const int w    = tid >> 5;
    const int lane = tid & 31;
    const int g    = lane >> 2;
    const int t    = lane & 3;
    const int mrow = (w & 3) * 16;
    const int nhalf = w >> 2;
    const int r0 = mrow + g, r1 = r0 + 8;

    for (int i = tid; i < 1536; i += 256) {
        const int r = i / 24, c = i - r * 24;
        const size_t src = (size_t)(t0 + r) * (NH * D_QK) + h * D_QK + c * 8;
        cp16(sma + SQ + r * 400 + c * 16, q16 + src);
    }
    CP_COMMIT();
    if (tid < 64) { sM[tid] = -1e30f; sL[tid] = 0.f; }

    float o[8][4];
#pragma unroll
    for (int i = 0; i < 8; i++)
#pragma unroll
        for (int j = 0; j < 4; j++) o[i][j] = 0.f;

    const int rowL = (lane & 7) + (lane & 8);
    const int kbL  = (lane >> 4) * 16;

    for (int kt = 0; kt <= qt; kt++) {
        const int k0 = kt * 64;
        __syncthreads();
        for (int i = tid; i < 1536; i += 256) {
            const int r = i / 24, c = i - r * 24;
            const size_t src = (size_t)(k0 + r) * (NH * D_QK) + h * D_QK + c * 8;
            cp16(sma + SK + r * 400 + c * 16, k16 + src);
        }
        for (int i = tid; i < 1024; i += 256) {
            const int r = i >> 3, c = i & 7;
            const size_t src = ((size_t)h * D_V + r) * T_TOK + k0 + c * 8;
            cp16(sma + SV + r * 144 + c * 16, vt16 + src);
        }
        CP_COMMIT();
        CP_WAIT0();
        __syncthreads();

        float s[4][4];
#pragma unroll
        for (int nt = 0; nt < 4; nt++)
#pragma unroll
            for (int j = 0; j < 4; j++) s[nt][j] = 0.f;

#pragma unroll 3
        for (int ks = 0; ks < 12; ks++) {
            const int kb = ks * 32 + kbL;
            uint32_t a0, a1, a2, a3;
            const int rA = (mrow + rowL) * 400 + kb;
            LDSM4(a0, a1, a2, a3, sb + SQ + rA);
            uint32_t bh[2][4];
#pragma unroll
            for (int j = 0; j < 2; j++) {
                const int rB = (nhalf * 32 + j * 16 + rowL) * 400 + kb;
                LDSM4(bh[j][0], bh[j][1], bh[j][2], bh[j][3], sb + SK + rB);
            }
#pragma unroll
            for (int nt = 0; nt < 4; nt++) {
                const int j = nt >> 1, hh = nt & 1;
                mma_f16(s[nt], a0, a1, a2, a3, bh[j][hh], bh[j][hh + 2]);
            }
        }

        const int rg0 = t0 + r0, rg1 = t0 + r1;
#pragma unroll
        for (int nt = 0; nt < 4; nt++) {
            const int cg = k0 + nhalf * 32 + nt * 8 + 2 * t;
            s[nt][0] = (rg0 >= cg)     ? s[nt][0] * SCALING : -1e30f;
            s[nt][1] = (rg0 >= cg + 1) ? s[nt][1] * SCALING : -1e30f;
            s[nt][2] = (rg1 >= cg)     ? s[nt][2] * SCALING : -1e30f;
            s[nt][3] = (rg1 >= cg + 1) ? s[nt][3] * SCALING : -1e30f;
        }

        float mx0 = -1e30f, mx1 = -1e30f;
#pragma unroll
        for (int nt = 0; nt < 4; nt++) {
            mx0 = fmaxf(mx0, fmaxf(s[nt][0], s[nt][1]));
            mx1 = fmaxf(mx1, fmaxf(s[nt][2], s[nt][3]));
        }
        mx0 = fmaxf(mx0, __shfl_xor_sync(0xffffffffu, mx0, 1));
        mx0 = fmaxf(mx0, __shfl_xor_sync(0xffffffffu, mx0, 2));
        mx1 = fmaxf(mx1, __shfl_xor_sync(0xffffffffu, mx1, 1));
        mx1 = fmaxf(mx1, __shfl_xor_sync(0xffffffffu, mx1, 2));
        if (t == 0) { sWmax[nhalf * 64 + r0] = mx0; sWmax[nhalf * 64 + r1] = mx1; }
        __syncthreads();

        const float mn0 = fmaxf(sM[r0], fmaxf(sWmax[r0], sWmax[64 + r0]));
        const float mn1 = fmaxf(sM[r1], fmaxf(sWmax[r1], sWmax[64 + r1]));

        float sum0 = 0.f, sum1 = 0.f;
#pragma unroll
        for (int nt = 0; nt < 4; nt++) {
            s[nt][0] = __expf(s[nt][0] - mn0);
            s[nt][1] = __expf(s[nt][1] - mn0);
            s[nt][2] = __expf(s[nt][2] - mn1);
            s[nt][3] = __expf(s[nt][3] - mn1);
            sum0 += s[nt][0] + s[nt][1];
            sum1 += s[nt][2] + s[nt][3];
            const int coll = nhalf * 32 + nt * 8 + 2 * t;
            *(uint32_t*)(sma + SPH + r0 * 144 + coll * 2) =
                pack2h(__float2half_rn(s[nt][0]), __float2half_rn(s[nt][1]));
            *(uint32_t*)(sma + SPH + r1 * 144 + coll * 2) =
                pack2h(__float2half_rn(s[nt][2]), __float2half_rn(s[nt][3]));
        }
        sum0 += __shfl_xor_sync(0xffffffffu, sum0, 1);
        sum0 += __shfl_xor_sync(0xffffffffu, sum0, 2);
        sum1 += __shfl_xor_sync(0xffffffffu, sum1, 1);
        sum1 += __shfl_xor_sync(0xffffffffu, sum1, 2);
        if (t == 0) { sWsum[nhalf * 64 + r0] = sum0; sWsum[nhalf * 64 + r1] = sum1; }
        __syncthreads();

        if (tid < 64) {
            const float mo = sM[tid];
            const float mn = fmaxf(mo, fmaxf(sWmax[tid], sWmax[64 + tid]));
            const float sc = __expf(mo - mn);
            sM[tid] = mn;
            sL[tid] = sL[tid] * sc + sWsum[tid] + sWsum[64 + tid];
            sScale[tid] = sc;
        }
        __syncthreads();

        const float sc0 = sScale[r0], sc1 = sScale[r1];
#pragma unroll
        for (int nt = 0; nt < 8; nt++) {
            o[nt][0] *= sc0; o[nt][1] *= sc0;
            o[nt][2] *= sc1; o[nt][3] *= sc1;
        }

#pragma unroll
        for (int ks = 0; ks < 4; ks++) {
            const int kb = ks * 32 + kbL;
            uint32_t ph0, ph1, ph2, ph3;
            const int rP = (mrow + rowL) * 144 + kb;
            LDSM4(ph0, ph1, ph2, ph3, sb + SPH + rP);
#pragma unroll
            for (int j2 = 0; j2 < 4; j2++) {
                const int rV = (nhalf * 64 + j2 * 16 + rowL) * 144 + kb;
                uint32_t vh[4];
                LDSM4(vh[0], vh[1], vh[2], vh[3], sb + SV + rV);
#pragma unroll
                for (int hh = 0; hh < 2; hh++)
                    mma_f16(o[j2 * 2 + hh], ph0, ph1, ph2, ph3, vh[hh], vh[hh + 2]);
            }
        }
    }

    const float il0 = 1.f / sL[r0];
    const float il1 = 1.f / sL[r1];
#pragma unroll
    for (int nt = 0; nt < 8; nt++) {
        const int col = h * D_V + nhalf * 64 + nt * 8 + 2 * t;
        o16[((size_t)(t0 + r0) * (NH * D_V) + col) >> 1] =
            pack2h(__float2half_rn(o[nt][0] * il0), __float2half_rn(o[nt][1] * il0));
        o16[((size_t)(t0 + r1) * (NH * D_V) + col) >> 1] =
            pack2h(__float2half_rn(o[nt][2] * il1), __float2half_rn(o[nt][3] * il1));
    }
}

// ---------------- launch ----------------
extern "C" void kernel_launch(void* const* d_in, const int* in_sizes, int n_in,
                              void* d_out, int out_size)
{
    const float* hidden    = (const float*)d_in[0];
    const int*   positions = (const int*)  d_in[1];
    const float* w_qkv_a   = (const float*)d_in[2];
    const float* gamma_q   = (const float*)d_in[3];
    const float* w_q_b     = (const float*)d_in[4];
    const float* gamma_kv  = (const float*)d_in[5];
    const float* w_kv_b    = (const float*)d_in[6];
    const float* w_o       = (const float*)d_in[7];
    float* out = (float*)d_out;

    __half *qkv16, *hid16, *qn16, *kvn16, *at16;
    __half *wa, *wqb, *wkvb, *wo;
    __half *q16, *k16, *vt16;
    cudaGetSymbolAddress((void**)&qkv16, g_qkv16);
    cudaGetSymbolAddress((void**)&hid16, g_hid_f16);
    cudaGetSymbolAddress((void**)&qn16,  g_qn_f16);
    cudaGetSymbolAddress((void**)&kvn16, g_kvn_f16);
    cudaGetSymbolAddress((void**)&at16,  g_at_f16);
    cudaGetSymbolAddress((void**)&wa,    g_wa_f16);
    cudaGetSymbolAddress((void**)&wqb,   g_wqb_f16);
    cudaGetSymbolAddress((void**)&wkvb,  g_wkvb_f16);
    cudaGetSymbolAddress((void**)&wo,    g_wo_f16);
    cudaGetSymbolAddress((void**)&q16,   g_q_f16);
    cudaGetSymbolAddress((void**)&k16,   g_k_f16);
    cudaGetSymbolAddress((void**)&vt16,  g_vt_f16);

    cudaFuncSetAttribute(gemm_f16,        cudaFuncAttributeMaxDynamicSharedMemorySize, F_SMEM);
    cudaFuncSetAttribute(gemm96_rope_f16, cudaFuncAttributeMaxDynamicSharedMemorySize, G96_SMEM);
    cudaFuncSetAttribute(attn_f16_kernel, cudaFuncAttributeMaxDynamicSharedMemorySize, ATT_SMEM);

    // 0) one-time conversions
    convert_f16_kernel<<<1184, 256>>>((const float2*)hidden,
        (uint32_t*)hid16, T_TOK * HID / 2);
    transpose_cvt_f16_kernel<<<dim3(QKV_A_N / 32, HID / 32),      dim3(32, 8)>>>(w_qkv_a, wa,   HID,      QKV_A_N);
    transpose_cvt_f16_kernel<<<dim3((NH*D_QK) / 32, Q_LORA / 32), dim3(32, 8)>>>(w_q_b,   wqb,  Q_LORA,   NH * D_QK);
    transpose_cvt_f16_kernel<<<dim3((NH*256) / 32, KV_LORA / 32), dim3(32, 8)>>>(w_kv_b,  wkvb, KV_LORA,  NH * 256);
    transpose_cvt_f16_kernel<<<dim3(HID / 32, (NH*D_V) / 32),     dim3(32, 8)>>>(w_o,     wo,   NH * D_V, HID);

    // 1) qkv = hidden @ w_qkv_a   (fp16 out)
    gemm_f16<<<dim3(QKV_A_N / 64, T_TOK / 256), 256, F_SMEM>>>(
        hid16, wa, 0, (uint32_t*)qkv16, 0, 0, 1, T_TOK, QKV_A_N, HID);

    // 2) fused RMSNorm
    rmsnorm2_kernel<<<dim3(T_TOK, 2), 256>>>(qkv16, gamma_q, gamma_kv, qn16, kvn16);

    // 2b) rope columns of K plane (only needs qkv16)
    fill_k_rope_kernel<<<T_TOK, 256>>>(qkv16, k16, positions);

    // 3) q = qn @ w_q_b -> q16 with fused RoPE
    gemm96_rope_f16<<<dim3((NH * D_QK) / 96, T_TOK / 256), 512, G96_SMEM>>>(
        qn16, wqb, (uint32_t*)q16, positions, T_TOK, NH * D_QK, Q_LORA);

    // 4) kv = kvn @ w_kv_b -> scatter directly to K nope cols + VT plane
    gemm_f16<<<dim3((NH * 256) / 64, T_TOK / 256), 256, F_SMEM>>>(
        kvn16, wkvb, 0, 0, k16, vt16, 2, T_TOK, NH * 256, KV_LORA);

    // 5) attention -> fp16 plane
    attn_f16_kernel<<<dim3(T_TOK / 64, NH), 256, ATT_SMEM>>>(
        q16, k16, vt16, (uint32_t*)at16);

    // 6) out = attn @ w_o  (fp32 out)
    gemm_f16<<<dim3(HID / 64, T_TOK / 256), 256, F_SMEM>>>(
        at16, wo, out, 0, 0, 0, 0, T_TOK, HID, NH * D_V);
}